// round 2
// baseline (speedup 1.0000x reference)
#include <cuda_runtime.h>
#include <cuda_bf16.h>
#include <mma.h>

using namespace nvcuda;

#define N_EMBD 768
#define NHEAD  12
#define HS     64
#define TSEQ   1024
#define BATCH  8
#define MROWS  (BATCH*TSEQ)     /* 8192 */
#define FFDIM  (4*N_EMBD)       /* 3072 */
#define WINDOW 64

/* -------- scratch (no allocation allowed -> device globals) -------- */
__device__ float g_h1 [MROWS*N_EMBD];
__device__ float g_q  [MROWS*N_EMBD];
__device__ float g_k  [MROWS*N_EMBD];
__device__ float g_v  [MROWS*N_EMBD];
__device__ float g_att[MROWS*N_EMBD];
__device__ float g_x1 [MROWS*N_EMBD];
__device__ float g_h2 [MROWS*N_EMBD];
__device__ float g_ffh[MROWS*FFDIM];

/* ----------------------------- RMSNorm ----------------------------- */
__global__ void rmsnorm_kernel(const float* __restrict__ x,
                               const float* __restrict__ g,
                               float* __restrict__ out)
{
    int row = blockIdx.x;
    const float4* xr = (const float4*)(x + (size_t)row * N_EMBD);
    const float4* gr = (const float4*)g;
    float4* o4 = (float4*)(out + (size_t)row * N_EMBD);

    float ss = 0.f;
    for (int i = threadIdx.x; i < N_EMBD/4; i += 256) {
        float4 v = xr[i];
        ss += v.x*v.x + v.y*v.y + v.z*v.z + v.w*v.w;
    }
    __shared__ float red[8];
    for (int o = 16; o; o >>= 1) ss += __shfl_xor_sync(0xffffffffu, ss, o);
    int warp = threadIdx.x >> 5, lane = threadIdx.x & 31;
    if (lane == 0) red[warp] = ss;
    __syncthreads();
    if (threadIdx.x == 0) {
        float t = 0.f;
        for (int i = 0; i < 8; i++) t += red[i];
        red[0] = t;
    }
    __syncthreads();
    float r = rsqrtf(red[0] * (1.0f / N_EMBD) + 1e-6f);

    for (int i = threadIdx.x; i < N_EMBD/4; i += 256) {
        float4 v = xr[i], gv = gr[i], w;
        w.x = v.x * r * gv.x; w.y = v.y * r * gv.y;
        w.z = v.z * r * gv.z; w.w = v.w * r * gv.w;
        o4[i] = w;
    }
}

/* ------------------------- TF32 WMMA GEMM -------------------------- */
/* C[M,N] = A[M,K] @ B[K,N]  (+bias) (+residual) (gelu)                */
/* MODE: 0 = plain, 1 = +bias +residual, 2 = +bias +gelu               */
#define BM 128
#define BN 128
#define BK 32

__device__ __forceinline__ float gelu_tanh(float v)
{
    const float c = 0.7978845608028654f;
    return 0.5f * v * (1.f + tanhf(c * (v + 0.044715f * v * v * v)));
}

template<int MODE>
__global__ __launch_bounds__(256)
void gemm_tf32(const float* __restrict__ A, const float* __restrict__ B,
               const float* __restrict__ bias, const float* __restrict__ resid,
               float* __restrict__ out, int M, int N, int K)
{
    __shared__ float As[BM][BK + 8];   /* stride 40 floats */
    __shared__ float Bs[BK][BN + 8];   /* stride 136 floats */

    const int tid  = threadIdx.x;
    const int m0   = blockIdx.y * BM;
    const int n0   = blockIdx.x * BN;
    const int warp = tid >> 5, lane = tid & 31;
    const int wm   = (warp >> 2) * 64;   /* 0 / 64   */
    const int wn   = (warp & 3) * 32;    /* 0..96    */

    wmma::fragment<wmma::accumulator, 16, 16, 8, float> acc[4][2];
    #pragma unroll
    for (int mi = 0; mi < 4; mi++)
        #pragma unroll
        for (int ni = 0; ni < 2; ni++)
            wmma::fill_fragment(acc[mi][ni], 0.f);

    for (int k0 = 0; k0 < K; k0 += BK) {
        /* load A tile: 128x32 floats as float4 */
        #pragma unroll
        for (int c = tid; c < (BM*BK)/4; c += 256) {
            int r = c >> 3, col = (c & 7) * 4;
            float4 v = *(const float4*)&A[(size_t)(m0 + r) * K + k0 + col];
            As[r][col] = v.x; As[r][col+1] = v.y; As[r][col+2] = v.z; As[r][col+3] = v.w;
        }
        /* load B tile: 32x128 floats */
        #pragma unroll
        for (int c = tid; c < (BK*BN)/4; c += 256) {
            int r = c >> 5, col = (c & 31) * 4;
            float4 v = *(const float4*)&B[(size_t)(k0 + r) * N + n0 + col];
            Bs[r][col] = v.x; Bs[r][col+1] = v.y; Bs[r][col+2] = v.z; Bs[r][col+3] = v.w;
        }
        __syncthreads();

        #pragma unroll
        for (int kk = 0; kk < BK; kk += 8) {
            wmma::fragment<wmma::matrix_a, 16, 16, 8, wmma::precision::tf32, wmma::row_major> af[4];
            wmma::fragment<wmma::matrix_b, 16, 16, 8, wmma::precision::tf32, wmma::row_major> bf[2];
            #pragma unroll
            for (int mi = 0; mi < 4; mi++) {
                wmma::load_matrix_sync(af[mi], &As[wm + mi*16][kk], BK + 8);
                #pragma unroll
                for (int t = 0; t < af[mi].num_elements; t++)
                    af[mi].x[t] = wmma::__float_to_tf32(af[mi].x[t]);
            }
            #pragma unroll
            for (int ni = 0; ni < 2; ni++) {
                wmma::load_matrix_sync(bf[ni], &Bs[kk][wn + ni*16], BN + 8);
                #pragma unroll
                for (int t = 0; t < bf[ni].num_elements; t++)
                    bf[ni].x[t] = wmma::__float_to_tf32(bf[ni].x[t]);
            }
            #pragma unroll
            for (int mi = 0; mi < 4; mi++)
                #pragma unroll
                for (int ni = 0; ni < 2; ni++)
                    wmma::mma_sync(acc[mi][ni], af[mi], bf[ni], acc[mi][ni]);
        }
        __syncthreads();
    }

    /* epilogue: stage each 16x16 fragment through smem (reuse As) */
    float* stage = &As[0][0] + warp * 272;
    #pragma unroll
    for (int mi = 0; mi < 4; mi++) {
        #pragma unroll
        for (int ni = 0; ni < 2; ni++) {
            wmma::store_matrix_sync(stage, acc[mi][ni], 16, wmma::mem_row_major);
            __syncwarp();
            #pragma unroll
            for (int l = 0; l < 8; l++) {
                int e = lane + l * 32;
                int r = e >> 4, cc = e & 15;
                int gr = m0 + wm + mi*16 + r;
                int gc = n0 + wn + ni*16 + cc;
                float v = stage[r * 16 + cc];
                if (MODE >= 1) v += bias[gc];
                if (MODE == 1) v += resid[(size_t)gr * N + gc];
                if (MODE == 2) v = gelu_tanh(v);
                out[(size_t)gr * N + gc] = v;
            }
            __syncwarp();
        }
    }
}

/* ------------------ sliding-window (64) attention ------------------ */
/* grid (T/64, H, B), 256 threads, dynamic smem:
   Ks[128][65] | Vs[128][65] (Q overlays Vs) | Sc[64][64]              */
#define ATT_SMEM ((2*128*65 + 64*64) * (int)sizeof(float))

__global__ __launch_bounds__(256)
void attn_kernel(const float* __restrict__ Q, const float* __restrict__ K,
                 const float* __restrict__ V, float* __restrict__ O)
{
    extern __shared__ float sm[];
    float* Ks = sm;                 /* 128 x 65 */
    float* Vs = sm + 128 * 65;      /* 128 x 65 */
    float* Sc = sm + 2 * 128 * 65;  /* 64 x 64  */
    float* Qs = Vs;                 /* 64 x 65 overlay, used before V */

    const int tid = threadIdx.x;
    const int b = blockIdx.z, h = blockIdx.y;
    const int t0 = blockIdx.x * 64;
    const int hc = h * HS;

    /* load K rows j=0..127 -> s = t0-63+j ; zero-fill outside [0,TSEQ) */
    for (int idx = tid; idx < 128 * 64; idx += 256) {
        int j = idx >> 6, d = idx & 63;
        int s = t0 - 63 + j;
        Ks[j * 65 + d] = (s >= 0 && s < TSEQ)
                       ? K[((size_t)(b * TSEQ + s)) * N_EMBD + hc + d] : 0.f;
    }
    /* load Q rows i=0..63 */
    for (int idx = tid; idx < 64 * 64; idx += 256) {
        int i = idx >> 6, d = idx & 63;
        Qs[i * 65 + d] = Q[((size_t)(b * TSEQ + t0 + i)) * N_EMBD + hc + d];
    }
    __syncthreads();

    /* scores: query i attends key j=i+cc (s = t0+i-63+cc) */
    for (int e = tid; e < 64 * 64; e += 256) {
        int i = e >> 6, cc = e & 63;
        int s = t0 + i - 63 + cc;
        float acc;
        if (s < 0) acc = -1e30f;
        else {
            acc = 0.f;
            int j = i + cc;
            #pragma unroll 8
            for (int d = 0; d < 64; d++)
                acc += Qs[i * 65 + d] * Ks[j * 65 + d];
            acc *= 0.125f;   /* 1/sqrt(64) */
        }
        Sc[i * 64 + cc] = acc;
    }
    __syncthreads();   /* Q region may now be overwritten by V */

    /* load V (same zero-fill guard as K) */
    for (int idx = tid; idx < 128 * 64; idx += 256) {
        int j = idx >> 6, d = idx & 63;
        int s = t0 - 63 + j;
        Vs[j * 65 + d] = (s >= 0 && s < TSEQ)
                       ? V[((size_t)(b * TSEQ + s)) * N_EMBD + hc + d] : 0.f;
    }

    /* softmax: warp w handles rows w*8 .. w*8+7 */
    {
        int warp = tid >> 5, lane = tid & 31;
        for (int r = warp * 8; r < warp * 8 + 8; r++) {
            float s0 = Sc[r * 64 + lane];
            float s1 = Sc[r * 64 + lane + 32];
            float mx = fmaxf(s0, s1);
            for (int o = 16; o; o >>= 1) mx = fmaxf(mx, __shfl_xor_sync(0xffffffffu, mx, o));
            float e0 = __expf(s0 - mx), e1 = __expf(s1 - mx);
            float sum = e0 + e1;
            for (int o = 16; o; o >>= 1) sum += __shfl_xor_sync(0xffffffffu, sum, o);
            float inv = 1.f / sum;
            Sc[r * 64 + lane]      = e0 * inv;
            Sc[r * 64 + lane + 32] = e1 * inv;
        }
    }
    __syncthreads();

    /* out[i][d] = sum_cc P[i][cc] * V[i+cc][d] */
    for (int e = tid; e < 64 * 64; e += 256) {
        int i = e >> 6, d = e & 63;
        float acc = 0.f;
        #pragma unroll 8
        for (int cc = 0; cc < 64; cc++)
            acc += Sc[i * 64 + cc] * Vs[(i + cc) * 65 + d];
        O[((size_t)(b * TSEQ + t0 + i)) * N_EMBD + hc + d] = acc;
    }
}

/* --------------------------- tail zero ----------------------------- */
__global__ void tail_kernel(float* out, int start, int total)
{
    int i = start + blockIdx.x * blockDim.x + threadIdx.x;
    if (i < total) out[i] = 0.f;
}

/* --------------------------- launcher ------------------------------ */
extern "C" void kernel_launch(void* const* d_in, const int* in_sizes, int n_in,
                              void* d_out, int out_size)
{
    const float* x      = (const float*)d_in[0];
    const float* w_q    = (const float*)d_in[1];
    const float* w_k    = (const float*)d_in[2];
    const float* w_v    = (const float*)d_in[3];
    const float* w_proj = (const float*)d_in[4];
    const float* b_proj = (const float*)d_in[5];
    const float* w_ff1  = (const float*)d_in[6];
    const float* b_ff1  = (const float*)d_in[7];
    const float* w_ff2  = (const float*)d_in[8];
    const float* b_ff2  = (const float*)d_in[9];
    const float* g1     = (const float*)d_in[10];
    const float* g2     = (const float*)d_in[11];
    float* out = (float*)d_out;

    float *h1, *q, *k, *v, *att, *x1, *h2, *ffh;
    { void* p;
      cudaGetSymbolAddress(&p, g_h1);  h1  = (float*)p;
      cudaGetSymbolAddress(&p, g_q);   q   = (float*)p;
      cudaGetSymbolAddress(&p, g_k);   k   = (float*)p;
      cudaGetSymbolAddress(&p, g_v);   v   = (float*)p;
      cudaGetSymbolAddress(&p, g_att); att = (float*)p;
      cudaGetSymbolAddress(&p, g_x1);  x1  = (float*)p;
      cudaGetSymbolAddress(&p, g_h2);  h2  = (float*)p;
      cudaGetSymbolAddress(&p, g_ffh); ffh = (float*)p;
    }

    cudaFuncSetAttribute(attn_kernel,
                         cudaFuncAttributeMaxDynamicSharedMemorySize, ATT_SMEM);

    /* 1. rmsnorm(x) * g1 */
    rmsnorm_kernel<<<MROWS, 256>>>(x, g1, h1);

    /* 2. Q/K/V GEMMs: [8192,768] @ [768,768] */
    dim3 gq(N_EMBD / BN, MROWS / BM);
    gemm_tf32<0><<<gq, 256>>>(h1, w_q, nullptr, nullptr, q, MROWS, N_EMBD, N_EMBD);
    gemm_tf32<0><<<gq, 256>>>(h1, w_k, nullptr, nullptr, k, MROWS, N_EMBD, N_EMBD);
    gemm_tf32<0><<<gq, 256>>>(h1, w_v, nullptr, nullptr, v, MROWS, N_EMBD, N_EMBD);

    /* 3. sliding-window attention */
    dim3 ga(TSEQ / 64, NHEAD, BATCH);
    attn_kernel<<<ga, 256, ATT_SMEM>>>(q, k, v, att);

    /* 4. proj: x1 = x + att @ w_proj + b_proj */
    gemm_tf32<1><<<gq, 256>>>(att, w_proj, b_proj, x, x1, MROWS, N_EMBD, N_EMBD);

    /* 5. rmsnorm(x1) * g2 */
    rmsnorm_kernel<<<MROWS, 256>>>(x1, g2, h2);

    /* 6. ff1: gelu(h2 @ w_ff1 + b_ff1) */
    dim3 gf1(FFDIM / BN, MROWS / BM);
    gemm_tf32<2><<<gf1, 256>>>(h2, w_ff1, b_ff1, nullptr, ffh, MROWS, FFDIM, N_EMBD);

    /* 7. ff2: out = x1 + ffh @ w_ff2 + b_ff2  (written straight to d_out) */
    gemm_tf32<1><<<gq, 256>>>(ffh, w_ff2, b_ff2, x1, out, MROWS, N_EMBD, FFDIM);

    /* 8. aux / tail: zero everything past the main tensor */
    const int TOT = MROWS * N_EMBD;
    if (out_size > TOT) {
        int rem = out_size - TOT;
        tail_kernel<<<(rem + 255) / 256, 256>>>(out, TOT, out_size);
    }
}

// round 4
// speedup vs baseline: 1.0516x; 1.0516x over previous
#include <cstdint>
#include <cuda_runtime.h>
#include <cuda_bf16.h>
#include <mma.h>

using namespace nvcuda;

#define N_EMBD 768
#define NHEAD  12
#define HS     64
#define TSEQ   1024
#define BATCH  8
#define MROWS  (BATCH*TSEQ)     /* 8192 */
#define FFDIM  (4*N_EMBD)       /* 3072 */
#define WINDOW 64

/* -------- scratch (no allocation allowed -> device globals) -------- */
__device__ float g_h1 [MROWS*N_EMBD];
__device__ float g_q  [MROWS*N_EMBD];
__device__ float g_k  [MROWS*N_EMBD];
__device__ float g_v  [MROWS*N_EMBD];
__device__ float g_att[MROWS*N_EMBD];
__device__ float g_x1 [MROWS*N_EMBD];
__device__ float g_h2 [MROWS*N_EMBD];
__device__ float g_ffh[MROWS*FFDIM];

/* ----------------------------- RMSNorm ----------------------------- */
__global__ void rmsnorm_kernel(const float* __restrict__ x,
                               const float* __restrict__ g,
                               float* __restrict__ out)
{
    int row = blockIdx.x;
    const float4* xr = (const float4*)(x + (size_t)row * N_EMBD);
    const float4* gr = (const float4*)g;
    float4* o4 = (float4*)(out + (size_t)row * N_EMBD);

    float ss = 0.f;
    for (int i = threadIdx.x; i < N_EMBD/4; i += 256) {
        float4 v = xr[i];
        ss += v.x*v.x + v.y*v.y + v.z*v.z + v.w*v.w;
    }
    __shared__ float red[8];
    for (int o = 16; o; o >>= 1) ss += __shfl_xor_sync(0xffffffffu, ss, o);
    int warp = threadIdx.x >> 5, lane = threadIdx.x & 31;
    if (lane == 0) red[warp] = ss;
    __syncthreads();
    if (threadIdx.x == 0) {
        float t = 0.f;
        for (int i = 0; i < 8; i++) t += red[i];
        red[0] = t;
    }
    __syncthreads();
    float r = rsqrtf(red[0] * (1.0f / N_EMBD) + 1e-6f);

    for (int i = threadIdx.x; i < N_EMBD/4; i += 256) {
        float4 v = xr[i], gv = gr[i], w;
        w.x = v.x * r * gv.x; w.y = v.y * r * gv.y;
        w.z = v.z * r * gv.z; w.w = v.w * r * gv.w;
        o4[i] = w;
    }
}

/* --------------------- cp.async helpers ---------------------------- */
__device__ __forceinline__ void cp_async16(uint32_t smem_addr, const void* gptr)
{
    asm volatile("cp.async.cg.shared.global [%0], [%1], 16;\n"
                 :: "r"(smem_addr), "l"(gptr));
}
__device__ __forceinline__ void cp_commit()
{
    asm volatile("cp.async.commit_group;\n");
}
__device__ __forceinline__ void cp_wait1()
{
    asm volatile("cp.async.wait_group 1;\n");
}

/* ------------------------- TF32 WMMA GEMM -------------------------- */
/* C[M,N] = A[M,K] @ B[K,N]  (+bias) (+residual) (gelu)                */
/* MODE: 0 = plain, 1 = +bias +residual, 2 = +bias +gelu               */
/* cp.async double-buffered: 2 stages, 75.8KB dyn smem, 2 CTA/SM       */
#define BM 128
#define BN 128
#define BK 32
#define APAD 8
#define BPAD 8
#define ASTR (BK + APAD)     /* 40  */
#define BSTR (BN + BPAD)     /* 136 */
#define A_TILE (BM * ASTR)   /* 5120 floats */
#define B_TILE (BK * BSTR)   /* 4352 floats */
#define SMEM_GEMM ((2 * (A_TILE + B_TILE)) * (int)sizeof(float))  /* 75776 B */

__device__ __forceinline__ float gelu_tanh(float v)
{
    const float c = 0.7978845608028654f;
    return 0.5f * v * (1.f + tanhf(c * (v + 0.044715f * v * v * v)));
}

template<int MODE>
__global__ __launch_bounds__(256, 2)
void gemm_tf32(const float* __restrict__ A, const float* __restrict__ B,
               const float* __restrict__ bias, const float* __restrict__ resid,
               float* __restrict__ out, int M, int N, int K)
{
    extern __shared__ float smem[];
    float* As = smem;                      /* [2][BM][ASTR] */
    float* Bs = smem + 2 * A_TILE;         /* [2][BK][BSTR] */
    const uint32_t as_u32 = (uint32_t)__cvta_generic_to_shared(As);
    const uint32_t bs_u32 = (uint32_t)__cvta_generic_to_shared(Bs);

    const int tid  = threadIdx.x;
    const int m0   = blockIdx.y * BM;
    const int n0   = blockIdx.x * BN;
    const int warp = tid >> 5, lane = tid & 31;
    const int wm   = (warp >> 2) * 64;   /* 0 / 64   */
    const int wn   = (warp & 3) * 32;    /* 0..96    */

    wmma::fragment<wmma::accumulator, 16, 16, 8, float> acc[4][2];
    #pragma unroll
    for (int mi = 0; mi < 4; mi++)
        #pragma unroll
        for (int ni = 0; ni < 2; ni++)
            wmma::fill_fragment(acc[mi][ni], 0.f);

    const int nk = K / BK;

    auto load_tile = [&](int k0, int s) {
        #pragma unroll
        for (int i = 0; i < 4; i++) {
            int c = tid + i * 256;
            int r = c >> 3, col = (c & 7) * 4;
            cp_async16(as_u32 + (uint32_t)(s * A_TILE + r * ASTR + col) * 4u,
                       &A[(size_t)(m0 + r) * K + k0 + col]);
        }
        #pragma unroll
        for (int i = 0; i < 4; i++) {
            int c = tid + i * 256;
            int r = c >> 5, col = (c & 31) * 4;
            cp_async16(bs_u32 + (uint32_t)(s * B_TILE + r * BSTR + col) * 4u,
                       &B[(size_t)(k0 + r) * N + n0 + col]);
        }
    };

    /* prologue: stage 0 */
    load_tile(0, 0);
    cp_commit();

    int s = 0;
    for (int it = 0; it < nk; it++) {
        /* issue next tile into the other buffer (safe: trailing sync of
           previous iteration guarantees everyone finished reading it) */
        if (it + 1 < nk) load_tile((it + 1) * BK, s ^ 1);
        cp_commit();
        cp_wait1();            /* tile `it` resident */
        __syncthreads();

        const float* Acur = As + s * A_TILE;
        const float* Bcur = Bs + s * B_TILE;

        #pragma unroll
        for (int kk = 0; kk < BK; kk += 8) {
            wmma::fragment<wmma::matrix_a, 16, 16, 8, wmma::precision::tf32, wmma::row_major> af[4];
            wmma::fragment<wmma::matrix_b, 16, 16, 8, wmma::precision::tf32, wmma::row_major> bf[2];
            #pragma unroll
            for (int mi = 0; mi < 4; mi++) {
                wmma::load_matrix_sync(af[mi], Acur + (wm + mi*16) * ASTR + kk, ASTR);
                #pragma unroll
                for (int t = 0; t < af[mi].num_elements; t++)
                    af[mi].x[t] = wmma::__float_to_tf32(af[mi].x[t]);
            }
            #pragma unroll
            for (int ni = 0; ni < 2; ni++) {
                wmma::load_matrix_sync(bf[ni], Bcur + kk * BSTR + wn + ni*16, BSTR);
                #pragma unroll
                for (int t = 0; t < bf[ni].num_elements; t++)
                    bf[ni].x[t] = wmma::__float_to_tf32(bf[ni].x[t]);
            }
            #pragma unroll
            for (int mi = 0; mi < 4; mi++)
                #pragma unroll
                for (int ni = 0; ni < 2; ni++)
                    wmma::mma_sync(acc[mi][ni], af[mi], bf[ni], acc[mi][ni]);
        }
        __syncthreads();   /* buffer s free for reuse by next iteration's load */
        s ^= 1;
    }

    /* epilogue: stage each 16x16 fragment through smem (reuse As area) */
    float* stage = smem + warp * 272;
    #pragma unroll
    for (int mi = 0; mi < 4; mi++) {
        #pragma unroll
        for (int ni = 0; ni < 2; ni++) {
            wmma::store_matrix_sync(stage, acc[mi][ni], 16, wmma::mem_row_major);
            __syncwarp();
            #pragma unroll
            for (int l = 0; l < 8; l++) {
                int e = lane + l * 32;
                int r = e >> 4, cc = e & 15;
                int gr = m0 + wm + mi*16 + r;
                int gc = n0 + wn + ni*16 + cc;
                float v = stage[r * 16 + cc];
                if (MODE >= 1) v += bias[gc];
                if (MODE == 1) v += resid[(size_t)gr * N + gc];
                if (MODE == 2) v = gelu_tanh(v);
                out[(size_t)gr * N + gc] = v;
            }
            __syncwarp();
        }
    }
}

/* ------------------ sliding-window (64) attention ------------------ */
#define ATT_SMEM ((2*128*65 + 64*64) * (int)sizeof(float))

__global__ __launch_bounds__(256)
void attn_kernel(const float* __restrict__ Q, const float* __restrict__ K,
                 const float* __restrict__ V, float* __restrict__ O)
{
    extern __shared__ float sm[];
    float* Ks = sm;                 /* 128 x 65 */
    float* Vs = sm + 128 * 65;      /* 128 x 65 */
    float* Sc = sm + 2 * 128 * 65;  /* 64 x 64  */
    float* Qs = Vs;                 /* 64 x 65 overlay, used before V */

    const int tid = threadIdx.x;
    const int b = blockIdx.z, h = blockIdx.y;
    const int t0 = blockIdx.x * 64;
    const int hc = h * HS;

    for (int idx = tid; idx < 128 * 64; idx += 256) {
        int j = idx >> 6, d = idx & 63;
        int s = t0 - 63 + j;
        Ks[j * 65 + d] = (s >= 0 && s < TSEQ)
                       ? K[((size_t)(b * TSEQ + s)) * N_EMBD + hc + d] : 0.f;
    }
    for (int idx = tid; idx < 64 * 64; idx += 256) {
        int i = idx >> 6, d = idx & 63;
        Qs[i * 65 + d] = Q[((size_t)(b * TSEQ + t0 + i)) * N_EMBD + hc + d];
    }
    __syncthreads();

    for (int e = tid; e < 64 * 64; e += 256) {
        int i = e >> 6, cc = e & 63;
        int s = t0 + i - 63 + cc;
        float acc;
        if (s < 0) acc = -1e30f;
        else {
            acc = 0.f;
            int j = i + cc;
            #pragma unroll 8
            for (int d = 0; d < 64; d++)
                acc += Qs[i * 65 + d] * Ks[j * 65 + d];
            acc *= 0.125f;
        }
        Sc[i * 64 + cc] = acc;
    }
    __syncthreads();

    for (int idx = tid; idx < 128 * 64; idx += 256) {
        int j = idx >> 6, d = idx & 63;
        int s = t0 - 63 + j;
        Vs[j * 65 + d] = (s >= 0 && s < TSEQ)
                       ? V[((size_t)(b * TSEQ + s)) * N_EMBD + hc + d] : 0.f;
    }

    {
        int warp = tid >> 5, lane = tid & 31;
        for (int r = warp * 8; r < warp * 8 + 8; r++) {
            float s0 = Sc[r * 64 + lane];
            float s1 = Sc[r * 64 + lane + 32];
            float mx = fmaxf(s0, s1);
            for (int o = 16; o; o >>= 1) mx = fmaxf(mx, __shfl_xor_sync(0xffffffffu, mx, o));
            float e0 = __expf(s0 - mx), e1 = __expf(s1 - mx);
            float sum = e0 + e1;
            for (int o = 16; o; o >>= 1) sum += __shfl_xor_sync(0xffffffffu, sum, o);
            float inv = 1.f / sum;
            Sc[r * 64 + lane]      = e0 * inv;
            Sc[r * 64 + lane + 32] = e1 * inv;
        }
    }
    __syncthreads();

    for (int e = tid; e < 64 * 64; e += 256) {
        int i = e >> 6, d = e & 63;
        float acc = 0.f;
        #pragma unroll 8
        for (int cc = 0; cc < 64; cc++)
            acc += Sc[i * 64 + cc] * Vs[(i + cc) * 65 + d];
        O[((size_t)(b * TSEQ + t0 + i)) * N_EMBD + hc + d] = acc;
    }
}

/* --------------------------- tail zero ----------------------------- */
__global__ void tail_kernel(float* out, int start, int total)
{
    int i = start + blockIdx.x * blockDim.x + threadIdx.x;
    if (i < total) out[i] = 0.f;
}

/* --------------------------- launcher ------------------------------ */
extern "C" void kernel_launch(void* const* d_in, const int* in_sizes, int n_in,
                              void* d_out, int out_size)
{
    const float* x      = (const float*)d_in[0];
    const float* w_q    = (const float*)d_in[1];
    const float* w_k    = (const float*)d_in[2];
    const float* w_v    = (const float*)d_in[3];
    const float* w_proj = (const float*)d_in[4];
    const float* b_proj = (const float*)d_in[5];
    const float* w_ff1  = (const float*)d_in[6];
    const float* b_ff1  = (const float*)d_in[7];
    const float* w_ff2  = (const float*)d_in[8];
    const float* b_ff2  = (const float*)d_in[9];
    const float* g1     = (const float*)d_in[10];
    const float* g2     = (const float*)d_in[11];
    float* out = (float*)d_out;

    float *h1, *q, *k, *v, *att, *x1, *h2, *ffh;
    { void* p;
      cudaGetSymbolAddress(&p, g_h1);  h1  = (float*)p;
      cudaGetSymbolAddress(&p, g_q);   q   = (float*)p;
      cudaGetSymbolAddress(&p, g_k);   k   = (float*)p;
      cudaGetSymbolAddress(&p, g_v);   v   = (float*)p;
      cudaGetSymbolAddress(&p, g_att); att = (float*)p;
      cudaGetSymbolAddress(&p, g_x1);  x1  = (float*)p;
      cudaGetSymbolAddress(&p, g_h2);  h2  = (float*)p;
      cudaGetSymbolAddress(&p, g_ffh); ffh = (float*)p;
    }

    static int attr_done = 0;
    if (!attr_done) {
        cudaFuncSetAttribute(attn_kernel,
                             cudaFuncAttributeMaxDynamicSharedMemorySize, ATT_SMEM);
        cudaFuncSetAttribute(gemm_tf32<0>,
                             cudaFuncAttributeMaxDynamicSharedMemorySize, SMEM_GEMM);
        cudaFuncSetAttribute(gemm_tf32<1>,
                             cudaFuncAttributeMaxDynamicSharedMemorySize, SMEM_GEMM);
        cudaFuncSetAttribute(gemm_tf32<2>,
                             cudaFuncAttributeMaxDynamicSharedMemorySize, SMEM_GEMM);
        attr_done = 1;
    }

    /* 1. rmsnorm(x) * g1 */
    rmsnorm_kernel<<<MROWS, 256>>>(x, g1, h1);

    /* 2. Q/K/V GEMMs: [8192,768] @ [768,768] */
    dim3 gq(N_EMBD / BN, MROWS / BM);
    gemm_tf32<0><<<gq, 256, SMEM_GEMM>>>(h1, w_q, nullptr, nullptr, q, MROWS, N_EMBD, N_EMBD);
    gemm_tf32<0><<<gq, 256, SMEM_GEMM>>>(h1, w_k, nullptr, nullptr, k, MROWS, N_EMBD, N_EMBD);
    gemm_tf32<0><<<gq, 256, SMEM_GEMM>>>(h1, w_v, nullptr, nullptr, v, MROWS, N_EMBD, N_EMBD);

    /* 3. sliding-window attention */
    dim3 ga(TSEQ / 64, NHEAD, BATCH);
    attn_kernel<<<ga, 256, ATT_SMEM>>>(q, k, v, att);

    /* 4. proj: x1 = x + att @ w_proj + b_proj */
    gemm_tf32<1><<<gq, 256, SMEM_GEMM>>>(att, w_proj, b_proj, x, x1, MROWS, N_EMBD, N_EMBD);

    /* 5. rmsnorm(x1) * g2 */
    rmsnorm_kernel<<<MROWS, 256>>>(x1, g2, h2);

    /* 6. ff1: gelu(h2 @ w_ff1 + b_ff1) */
    dim3 gf1(FFDIM / BN, MROWS / BM);
    gemm_tf32<2><<<gf1, 256, SMEM_GEMM>>>(h2, w_ff1, b_ff1, nullptr, ffh, MROWS, FFDIM, N_EMBD);

    /* 7. ff2: out = x1 + ffh @ w_ff2 + b_ff2  (written straight to d_out) */
    gemm_tf32<1><<<gq, 256, SMEM_GEMM>>>(ffh, w_ff2, b_ff2, x1, out, MROWS, N_EMBD, FFDIM);

    /* 8. aux / tail: zero everything past the main tensor */
    const int TOT = MROWS * N_EMBD;
    if (out_size > TOT) {
        int rem = out_size - TOT;
        tail_kernel<<<(rem + 255) / 256, 256>>>(out, TOT, out_size);
    }
}

// round 6
// speedup vs baseline: 2.9709x; 2.8251x over previous
#include <cstdint>
#include <cuda_runtime.h>
#include <cuda_fp16.h>
#include <mma.h>

using namespace nvcuda;

#define N_EMBD 768
#define NHEAD  12
#define HS     64
#define TSEQ   1024
#define BATCH  8
#define MROWS  (BATCH*TSEQ)     /* 8192 */
#define FFDIM  (4*N_EMBD)       /* 3072 */
#define QKVD   (3*N_EMBD)       /* 2304 */
#define WINDOW 64

/* -------- scratch (no allocation allowed -> device globals) -------- */
__device__ float  g_qkv [MROWS*QKVD];     /* fused q|k|v fp32 */
__device__ float  g_x1  [MROWS*N_EMBD];
__device__ __half g_h1h [MROWS*N_EMBD];
__device__ __half g_atth[MROWS*N_EMBD];
__device__ __half g_h2h [MROWS*N_EMBD];
__device__ __half g_ffhh[MROWS*FFDIM];
/* transposed half weights [N,K] K-major */
__device__ __half g_wqkv[QKVD*N_EMBD];
__device__ __half g_wtp [N_EMBD*N_EMBD];
__device__ __half g_wt1 [FFDIM*N_EMBD];
__device__ __half g_wt2 [N_EMBD*FFDIM];

/* --------------------- cp.async helpers ---------------------------- */
__device__ __forceinline__ void cp_async16(uint32_t dst, const void* src)
{
    asm volatile("cp.async.cg.shared.global [%0], [%1], 16;\n" :: "r"(dst), "l"(src));
}
__device__ __forceinline__ void cp_commit()
{
    asm volatile("cp.async.commit_group;\n");
}
__device__ __forceinline__ void cp_wait1()
{
    asm volatile("cp.async.wait_group 1;\n");
}
__device__ __forceinline__ void cp_wait0()
{
    asm volatile("cp.async.wait_group 0;\n");
}

/* ----------------------------- RMSNorm (half out) ------------------ */
__global__ void rmsnorm_h_kernel(const float* __restrict__ x,
                                 const float* __restrict__ g,
                                 __half* __restrict__ out)
{
    int row = blockIdx.x;
    const float4* xr = (const float4*)(x + (size_t)row * N_EMBD);
    const float4* gr = (const float4*)g;
    __half2* o2 = (__half2*)(out + (size_t)row * N_EMBD);

    float ss = 0.f;
    for (int i = threadIdx.x; i < N_EMBD/4; i += 256) {
        float4 v = xr[i];
        ss += v.x*v.x + v.y*v.y + v.z*v.z + v.w*v.w;
    }
    __shared__ float red[8];
    for (int o = 16; o; o >>= 1) ss += __shfl_xor_sync(0xffffffffu, ss, o);
    int warp = threadIdx.x >> 5, lane = threadIdx.x & 31;
    if (lane == 0) red[warp] = ss;
    __syncthreads();
    if (threadIdx.x == 0) {
        float t = 0.f;
        for (int i = 0; i < 8; i++) t += red[i];
        red[0] = t;
    }
    __syncthreads();
    float r = rsqrtf(red[0] * (1.0f / N_EMBD) + 1e-6f);

    for (int i = threadIdx.x; i < N_EMBD/4; i += 256) {
        float4 v = xr[i], gv = gr[i];
        o2[i*2]   = __floats2half2_rn(v.x * r * gv.x, v.y * r * gv.y);
        o2[i*2+1] = __floats2half2_rn(v.z * r * gv.z, v.w * r * gv.w);
    }
}

/* ------------------------ weight transpose (f32 -> half) ----------- */
/* out[n*K + k] = (half)in[k*N + n] ; grid (N/32, K/32), block (32,8)  */
__global__ void transpose_h_kernel(const float* __restrict__ in,
                                   __half* __restrict__ outp, int K, int N)
{
    __shared__ float t[32][33];
    int n0 = blockIdx.x * 32, k0 = blockIdx.y * 32;
    int tx = threadIdx.x, ty = threadIdx.y;
    #pragma unroll
    for (int dy = 0; dy < 32; dy += 8)
        t[ty + dy][tx] = in[(size_t)(k0 + ty + dy) * N + n0 + tx];
    __syncthreads();
    #pragma unroll
    for (int dy = 0; dy < 32; dy += 8)
        outp[(size_t)(n0 + ty + dy) * K + k0 + tx] = __float2half(t[tx][ty + dy]);
}

/* ------------------------- FP16 WMMA GEMM -------------------------- */
/* C[M,N] = A[M,K] @ BT[N,K]^T  ; A,BT half K-major, accum fp32       */
/* MODE: 0 plain, 1 +bias+resid, 2 +bias+gelu                          */
/* OUTH: 0 -> float out, 1 -> half out                                 */
#define BM 128
#define BN 128
#define BK 32
#define HSTR 40                       /* halfs per row (BK+8) */
#define TILE_H (128 * HSTR)           /* 5120 halfs */
#define TILE_B (TILE_H * 2)           /* 10240 bytes */
#define SMEM_GEMM (4 * TILE_B)        /* 2 stages x (A+B) = 40960 B */

__device__ __forceinline__ float gelu_tanh(float v)
{
    const float c = 0.7978845608028654f;
    return 0.5f * v * (1.f + tanhf(c * (v + 0.044715f * v * v * v)));
}

template<int MODE, int OUTH>
__global__ __launch_bounds__(256)
void gemm_fp16(const __half* __restrict__ A, const __half* __restrict__ BT,
               const float* __restrict__ bias, const float* __restrict__ resid,
               float* __restrict__ outf, __half* __restrict__ outh,
               int M, int N, int K)
{
    extern __shared__ __align__(16) unsigned char smem_raw[];
    __half* As = (__half*)smem_raw;                       /* [2][128][40] */
    __half* Bs = (__half*)(smem_raw + 2 * TILE_B);        /* [2][128][40] */
    const uint32_t asu = (uint32_t)__cvta_generic_to_shared(As);
    const uint32_t bsu = (uint32_t)__cvta_generic_to_shared(Bs);

    const int tid  = threadIdx.x;
    const int warp = tid >> 5, lane = tid & 31;
    const int m0 = blockIdx.y * BM, n0 = blockIdx.x * BN;
    const int wm = (warp >> 2) * 64;     /* 0 / 64  */
    const int wn = (warp & 3) * 32;      /* 0..96   */

    wmma::fragment<wmma::accumulator, 16, 16, 16, float> acc[4][2];
    #pragma unroll
    for (int mi = 0; mi < 4; mi++)
        #pragma unroll
        for (int ni = 0; ni < 2; ni++)
            wmma::fill_fragment(acc[mi][ni], 0.f);

    const int nk = K / BK;

    auto load_tile = [&](int ck, int s) {
        const __half* Ab = A  + (size_t)m0 * K + ck * BK;
        const __half* Bb = BT + (size_t)n0 * K + ck * BK;
        /* 512 chunks of 16B per tile (128 rows x 4 chunks), 2/thread */
        #pragma unroll
        for (int i = 0; i < 2; i++) {
            int c = tid + i * 256;
            int r = c >> 2, col = (c & 3) * 8;      /* halfs */
            cp_async16(asu + (uint32_t)(s * TILE_B + r * (HSTR*2) + col * 2),
                       Ab + (size_t)r * K + col);
        }
        #pragma unroll
        for (int i = 0; i < 2; i++) {
            int c = tid + i * 256;
            int r = c >> 2, col = (c & 3) * 8;
            cp_async16(bsu + (uint32_t)(s * TILE_B + r * (HSTR*2) + col * 2),
                       Bb + (size_t)r * K + col);
        }
    };

    load_tile(0, 0); cp_commit();
    load_tile(1, 1); cp_commit();

    for (int it = 0; it < nk; it++) {
        int s = it & 1;
        if (it + 1 < nk) cp_wait1(); else cp_wait0();
        __syncthreads();

        const __half* Acur = As + s * TILE_H;
        const __half* Bcur = Bs + s * TILE_H;

        #pragma unroll
        for (int kk = 0; kk < BK; kk += 16) {
            wmma::fragment<wmma::matrix_a, 16, 16, 16, __half, wmma::row_major> af[4];
            wmma::fragment<wmma::matrix_b, 16, 16, 16, __half, wmma::col_major> bf[2];
            #pragma unroll
            for (int mi = 0; mi < 4; mi++)
                wmma::load_matrix_sync(af[mi], Acur + (wm + mi*16) * HSTR + kk, HSTR);
            #pragma unroll
            for (int ni = 0; ni < 2; ni++)
                wmma::load_matrix_sync(bf[ni], Bcur + (wn + ni*16) * HSTR + kk, HSTR);
            #pragma unroll
            for (int mi = 0; mi < 4; mi++)
                #pragma unroll
                for (int ni = 0; ni < 2; ni++)
                    wmma::mma_sync(acc[mi][ni], af[mi], bf[ni], acc[mi][ni]);
        }
        __syncthreads();
        if (it + 2 < nk) { load_tile(it + 2, s); cp_commit(); }
    }

    /* epilogue: stage 16x16 fp32 tiles through smem */
    float* stage = (float*)smem_raw + warp * 272;
    #pragma unroll
    for (int mi = 0; mi < 4; mi++) {
        #pragma unroll
        for (int ni = 0; ni < 2; ni++) {
            wmma::store_matrix_sync(stage, acc[mi][ni], 16, wmma::mem_row_major);
            __syncwarp();
            #pragma unroll
            for (int l = 0; l < 8; l++) {
                int e = lane + l * 32;
                int r = e >> 4, cc = e & 15;
                int gr = m0 + wm + mi*16 + r;
                int gc = n0 + wn + ni*16 + cc;
                float v = stage[r * 16 + cc];
                if (MODE >= 1) v += bias[gc];
                if (MODE == 1) v += resid[(size_t)gr * N + gc];
                if (MODE == 2) v = gelu_tanh(v);
                if (OUTH)
                    outh[(size_t)gr * N + gc] = __float2half(v);
                else
                    outf[(size_t)gr * N + gc] = v;
            }
            __syncwarp();
        }
    }
}

/* ------------------ sliding-window (64) attention ------------------ */
/* reads fused qkv (fp32, stride QKVD), writes half att                */
#define ATT_SMEM ((2*128*65 + 64*64) * (int)sizeof(float))

__global__ __launch_bounds__(256)
void attn_kernel(const float* __restrict__ QKV, __half* __restrict__ O)
{
    extern __shared__ float sm[];
    float* Ks = sm;                 /* 128 x 65 */
    float* Vs = sm + 128 * 65;      /* 128 x 65 */
    float* Sc = sm + 2 * 128 * 65;  /* 64 x 64  */
    float* Qs = Vs;                 /* 64 x 65 overlay, used before V */

    const int tid = threadIdx.x;
    const int b = blockIdx.z, h = blockIdx.y;
    const int t0 = blockIdx.x * 64;
    const int hc = h * HS;

    for (int idx = tid; idx < 128 * 64; idx += 256) {
        int j = idx >> 6, d = idx & 63;
        int s = t0 - 63 + j;
        Ks[j * 65 + d] = (s >= 0 && s < TSEQ)
                       ? QKV[((size_t)(b * TSEQ + s)) * QKVD + N_EMBD + hc + d] : 0.f;
    }
    for (int idx = tid; idx < 64 * 64; idx += 256) {
        int i = idx >> 6, d = idx & 63;
        Qs[i * 65 + d] = QKV[((size_t)(b * TSEQ + t0 + i)) * QKVD + hc + d];
    }
    __syncthreads();

    for (int e = tid; e < 64 * 64; e += 256) {
        int i = e >> 6, cc = e & 63;
        int s = t0 + i - 63 + cc;
        float acc;
        if (s < 0) acc = -1e30f;
        else {
            acc = 0.f;
            int j = i + cc;
            #pragma unroll 8
            for (int d = 0; d < 64; d++)
                acc += Qs[i * 65 + d] * Ks[j * 65 + d];
            acc *= 0.125f;
        }
        Sc[i * 64 + cc] = acc;
    }
    __syncthreads();

    for (int idx = tid; idx < 128 * 64; idx += 256) {
        int j = idx >> 6, d = idx & 63;
        int s = t0 - 63 + j;
        Vs[j * 65 + d] = (s >= 0 && s < TSEQ)
                       ? QKV[((size_t)(b * TSEQ + s)) * QKVD + 2*N_EMBD + hc + d] : 0.f;
    }

    {
        int warp = tid >> 5, lane = tid & 31;
        for (int r = warp * 8; r < warp * 8 + 8; r++) {
            float s0 = Sc[r * 64 + lane];
            float s1 = Sc[r * 64 + lane + 32];
            float mx = fmaxf(s0, s1);
            for (int o = 16; o; o >>= 1) mx = fmaxf(mx, __shfl_xor_sync(0xffffffffu, mx, o));
            float e0 = __expf(s0 - mx), e1 = __expf(s1 - mx);
            float sum = e0 + e1;
            for (int o = 16; o; o >>= 1) sum += __shfl_xor_sync(0xffffffffu, sum, o);
            float inv = 1.f / sum;
            Sc[r * 64 + lane]      = e0 * inv;
            Sc[r * 64 + lane + 32] = e1 * inv;
        }
    }
    __syncthreads();

    for (int e = tid; e < 64 * 64; e += 256) {
        int i = e >> 6, d = e & 63;
        float acc = 0.f;
        #pragma unroll 8
        for (int cc = 0; cc < 64; cc++)
            acc += Sc[i * 64 + cc] * Vs[(i + cc) * 65 + d];
        O[((size_t)(b * TSEQ + t0 + i)) * N_EMBD + hc + d] = __float2half(acc);
    }
}

/* --------------------------- tail zero ----------------------------- */
__global__ void tail_kernel(float* out, int start, int total)
{
    int i = start + blockIdx.x * blockDim.x + threadIdx.x;
    if (i < total) out[i] = 0.f;
}

/* --------------------------- launcher ------------------------------ */
extern "C" void kernel_launch(void* const* d_in, const int* in_sizes, int n_in,
                              void* d_out, int out_size)
{
    const float* x      = (const float*)d_in[0];
    const float* w_q    = (const float*)d_in[1];
    const float* w_k    = (const float*)d_in[2];
    const float* w_v    = (const float*)d_in[3];
    const float* w_proj = (const float*)d_in[4];
    const float* b_proj = (const float*)d_in[5];
    const float* w_ff1  = (const float*)d_in[6];
    const float* b_ff1  = (const float*)d_in[7];
    const float* w_ff2  = (const float*)d_in[8];
    const float* b_ff2  = (const float*)d_in[9];
    const float* g1     = (const float*)d_in[10];
    const float* g2     = (const float*)d_in[11];
    float* out = (float*)d_out;

    float *qkv, *x1;
    __half *h1h, *atth, *h2h, *ffhh, *wqkv, *wtp, *wt1, *wt2;
    { void* p;
      cudaGetSymbolAddress(&p, g_qkv);  qkv  = (float*)p;
      cudaGetSymbolAddress(&p, g_x1);   x1   = (float*)p;
      cudaGetSymbolAddress(&p, g_h1h);  h1h  = (__half*)p;
      cudaGetSymbolAddress(&p, g_atth); atth = (__half*)p;
      cudaGetSymbolAddress(&p, g_h2h);  h2h  = (__half*)p;
      cudaGetSymbolAddress(&p, g_ffhh); ffhh = (__half*)p;
      cudaGetSymbolAddress(&p, g_wqkv); wqkv = (__half*)p;
      cudaGetSymbolAddress(&p, g_wtp);  wtp  = (__half*)p;
      cudaGetSymbolAddress(&p, g_wt1);  wt1  = (__half*)p;
      cudaGetSymbolAddress(&p, g_wt2);  wt2  = (__half*)p;
    }

    cudaFuncSetAttribute(attn_kernel,
                         cudaFuncAttributeMaxDynamicSharedMemorySize, ATT_SMEM);

    /* 0. transpose weights to half [N,K] */
    {
        dim3 blk(32, 8);
        dim3 gsq(N_EMBD/32, N_EMBD/32);
        transpose_h_kernel<<<gsq, blk>>>(w_q,    wqkv,                   N_EMBD, N_EMBD);
        transpose_h_kernel<<<gsq, blk>>>(w_k,    wqkv + N_EMBD*N_EMBD,   N_EMBD, N_EMBD);
        transpose_h_kernel<<<gsq, blk>>>(w_v,    wqkv + 2*N_EMBD*N_EMBD, N_EMBD, N_EMBD);
        transpose_h_kernel<<<gsq, blk>>>(w_proj, wtp,                    N_EMBD, N_EMBD);
        dim3 gf1(FFDIM/32, N_EMBD/32);
        transpose_h_kernel<<<gf1, blk>>>(w_ff1,  wt1, N_EMBD, FFDIM);
        dim3 gf2(N_EMBD/32, FFDIM/32);
        transpose_h_kernel<<<gf2, blk>>>(w_ff2,  wt2, FFDIM, N_EMBD);
    }

    /* 1. rmsnorm(x)*g1 -> half */
    rmsnorm_h_kernel<<<MROWS, 256>>>(x, g1, h1h);

    /* 2. fused QKV GEMM: [8192,768] @ [768,2304] -> fp32 */
    dim3 gqkv(QKVD / BN, MROWS / BM);
    gemm_fp16<0,0><<<gqkv, 256, SMEM_GEMM>>>(h1h, wqkv, nullptr, nullptr,
                                             qkv, nullptr, MROWS, QKVD, N_EMBD);

    /* 3. sliding-window attention -> half */
    dim3 ga(TSEQ / 64, NHEAD, BATCH);
    attn_kernel<<<ga, 256, ATT_SMEM>>>(qkv, atth);

    /* 4. proj: x1 = x + att @ w_proj + b_proj (fp32) */
    dim3 gp(N_EMBD / BN, MROWS / BM);
    gemm_fp16<1,0><<<gp, 256, SMEM_GEMM>>>(atth, wtp, b_proj, x,
                                           x1, nullptr, MROWS, N_EMBD, N_EMBD);

    /* 5. rmsnorm(x1)*g2 -> half */
    rmsnorm_h_kernel<<<MROWS, 256>>>(x1, g2, h2h);

    /* 6. ff1: gelu(h2 @ w_ff1 + b_ff1) -> half */
    dim3 gff1(FFDIM / BN, MROWS / BM);
    gemm_fp16<2,1><<<gff1, 256, SMEM_GEMM>>>(h2h, wt1, b_ff1, nullptr,
                                             nullptr, ffhh, MROWS, FFDIM, N_EMBD);

    /* 7. ff2: out = x1 + ffh @ w_ff2 + b_ff2 (fp32, straight to d_out) */
    gemm_fp16<1,0><<<gp, 256, SMEM_GEMM>>>(ffhh, wt2, b_ff2, x1,
                                           out, nullptr, MROWS, N_EMBD, FFDIM);

    /* 8. aux / tail */
    const int TOT = MROWS * N_EMBD;
    if (out_size > TOT) {
        int rem = out_size - TOT;
        tail_kernel<<<(rem + 255) / 256, 256>>>(out, TOT, out_size);
    }
}

// round 7
// speedup vs baseline: 3.8829x; 1.3070x over previous
#include <cstdint>
#include <cuda_runtime.h>
#include <cuda_fp16.h>
#include <mma.h>

using namespace nvcuda;

#define N_EMBD 768
#define NHEAD  12
#define HS     64
#define TSEQ   1024
#define BATCH  8
#define MROWS  (BATCH*TSEQ)     /* 8192 */
#define FFDIM  (4*N_EMBD)       /* 3072 */
#define QKVD   (3*N_EMBD)       /* 2304 */
#define WINDOW 64

/* -------- scratch (no allocation allowed -> device globals) -------- */
__device__ float  g_x1  [MROWS*N_EMBD];
__device__ __half g_qkvh[MROWS*QKVD];     /* fused q|k|v half */
__device__ __half g_h1h [MROWS*N_EMBD];
__device__ __half g_atth[MROWS*N_EMBD];
__device__ __half g_h2h [MROWS*N_EMBD];
__device__ __half g_ffhh[MROWS*FFDIM];
/* transposed half weights [N,K] K-major */
__device__ __half g_wqkv[QKVD*N_EMBD];
__device__ __half g_wtp [N_EMBD*N_EMBD];
__device__ __half g_wt1 [FFDIM*N_EMBD];
__device__ __half g_wt2 [N_EMBD*FFDIM];

/* --------------------- cp.async helpers ---------------------------- */
__device__ __forceinline__ void cp_async16(uint32_t dst, const void* src)
{
    asm volatile("cp.async.cg.shared.global [%0], [%1], 16;\n" :: "r"(dst), "l"(src));
}
/* zero-fill variant: src_sz = 0 -> full 16B zero fill */
__device__ __forceinline__ void cp_async16z(uint32_t dst, const void* src, int src_sz)
{
    asm volatile("cp.async.cg.shared.global [%0], [%1], 16, %2;\n"
                 :: "r"(dst), "l"(src), "r"(src_sz));
}
__device__ __forceinline__ void cp_commit()
{
    asm volatile("cp.async.commit_group;\n");
}
__device__ __forceinline__ void cp_wait1()
{
    asm volatile("cp.async.wait_group 1;\n");
}
__device__ __forceinline__ void cp_wait0()
{
    asm volatile("cp.async.wait_group 0;\n");
}

/* ----------------------------- RMSNorm (half out) ------------------ */
__global__ void rmsnorm_h_kernel(const float* __restrict__ x,
                                 const float* __restrict__ g,
                                 __half* __restrict__ out)
{
    int row = blockIdx.x;
    const float4* xr = (const float4*)(x + (size_t)row * N_EMBD);
    const float4* gr = (const float4*)g;
    __half2* o2 = (__half2*)(out + (size_t)row * N_EMBD);

    float ss = 0.f;
    for (int i = threadIdx.x; i < N_EMBD/4; i += 256) {
        float4 v = xr[i];
        ss += v.x*v.x + v.y*v.y + v.z*v.z + v.w*v.w;
    }
    __shared__ float red[8];
    for (int o = 16; o; o >>= 1) ss += __shfl_xor_sync(0xffffffffu, ss, o);
    int warp = threadIdx.x >> 5, lane = threadIdx.x & 31;
    if (lane == 0) red[warp] = ss;
    __syncthreads();
    if (threadIdx.x == 0) {
        float t = 0.f;
        for (int i = 0; i < 8; i++) t += red[i];
        red[0] = t;
    }
    __syncthreads();
    float r = rsqrtf(red[0] * (1.0f / N_EMBD) + 1e-6f);

    for (int i = threadIdx.x; i < N_EMBD/4; i += 256) {
        float4 v = xr[i], gv = gr[i];
        o2[i*2]   = __floats2half2_rn(v.x * r * gv.x, v.y * r * gv.y);
        o2[i*2+1] = __floats2half2_rn(v.z * r * gv.z, v.w * r * gv.w);
    }
}

/* ------------------------ weight transpose (f32 -> half) ----------- */
__global__ void transpose_h_kernel(const float* __restrict__ in,
                                   __half* __restrict__ outp, int K, int N)
{
    __shared__ float t[32][33];
    int n0 = blockIdx.x * 32, k0 = blockIdx.y * 32;
    int tx = threadIdx.x, ty = threadIdx.y;
    #pragma unroll
    for (int dy = 0; dy < 32; dy += 8)
        t[ty + dy][tx] = in[(size_t)(k0 + ty + dy) * N + n0 + tx];
    __syncthreads();
    #pragma unroll
    for (int dy = 0; dy < 32; dy += 8)
        outp[(size_t)(n0 + ty + dy) * K + k0 + tx] = __float2half(t[tx][ty + dy]);
}

/* ------------------------- FP16 WMMA GEMM -------------------------- */
#define BM 128
#define BN 128
#define BK 32
#define HSTR 40                       /* halfs per row (BK+8) */
#define TILE_H (128 * HSTR)           /* 5120 halfs */
#define TILE_B (TILE_H * 2)           /* 10240 bytes */
#define SMEM_GEMM (4 * TILE_B)        /* 40960 B */

__device__ __forceinline__ float gelu_tanh(float v)
{
    const float c = 0.7978845608028654f;
    return 0.5f * v * (1.f + tanhf(c * (v + 0.044715f * v * v * v)));
}

template<int MODE, int OUTH>
__global__ __launch_bounds__(256)
void gemm_fp16(const __half* __restrict__ A, const __half* __restrict__ BT,
               const float* __restrict__ bias, const float* __restrict__ resid,
               float* __restrict__ outf, __half* __restrict__ outh,
               int M, int N, int K)
{
    extern __shared__ __align__(16) unsigned char smem_raw[];
    __half* As = (__half*)smem_raw;                       /* [2][128][40] */
    __half* Bs = (__half*)(smem_raw + 2 * TILE_B);        /* [2][128][40] */
    const uint32_t asu = (uint32_t)__cvta_generic_to_shared(As);
    const uint32_t bsu = (uint32_t)__cvta_generic_to_shared(Bs);

    const int tid  = threadIdx.x;
    const int warp = tid >> 5, lane = tid & 31;
    const int m0 = blockIdx.y * BM, n0 = blockIdx.x * BN;
    const int wm = (warp >> 2) * 64;
    const int wn = (warp & 3) * 32;

    wmma::fragment<wmma::accumulator, 16, 16, 16, float> acc[4][2];
    #pragma unroll
    for (int mi = 0; mi < 4; mi++)
        #pragma unroll
        for (int ni = 0; ni < 2; ni++)
            wmma::fill_fragment(acc[mi][ni], 0.f);

    const int nk = K / BK;

    auto load_tile = [&](int ck, int s) {
        const __half* Ab = A  + (size_t)m0 * K + ck * BK;
        const __half* Bb = BT + (size_t)n0 * K + ck * BK;
        #pragma unroll
        for (int i = 0; i < 2; i++) {
            int c = tid + i * 256;
            int r = c >> 2, col = (c & 3) * 8;
            cp_async16(asu + (uint32_t)(s * TILE_B + r * (HSTR*2) + col * 2),
                       Ab + (size_t)r * K + col);
        }
        #pragma unroll
        for (int i = 0; i < 2; i++) {
            int c = tid + i * 256;
            int r = c >> 2, col = (c & 3) * 8;
            cp_async16(bsu + (uint32_t)(s * TILE_B + r * (HSTR*2) + col * 2),
                       Bb + (size_t)r * K + col);
        }
    };

    load_tile(0, 0); cp_commit();
    load_tile(1, 1); cp_commit();

    for (int it = 0; it < nk; it++) {
        int s = it & 1;
        if (it + 1 < nk) cp_wait1(); else cp_wait0();
        __syncthreads();

        const __half* Acur = As + s * TILE_H;
        const __half* Bcur = Bs + s * TILE_H;

        #pragma unroll
        for (int kk = 0; kk < BK; kk += 16) {
            wmma::fragment<wmma::matrix_a, 16, 16, 16, __half, wmma::row_major> af[4];
            wmma::fragment<wmma::matrix_b, 16, 16, 16, __half, wmma::col_major> bf[2];
            #pragma unroll
            for (int mi = 0; mi < 4; mi++)
                wmma::load_matrix_sync(af[mi], Acur + (wm + mi*16) * HSTR + kk, HSTR);
            #pragma unroll
            for (int ni = 0; ni < 2; ni++)
                wmma::load_matrix_sync(bf[ni], Bcur + (wn + ni*16) * HSTR + kk, HSTR);
            #pragma unroll
            for (int mi = 0; mi < 4; mi++)
                #pragma unroll
                for (int ni = 0; ni < 2; ni++)
                    wmma::mma_sync(acc[mi][ni], af[mi], bf[ni], acc[mi][ni]);
        }
        __syncthreads();
        if (it + 2 < nk) { load_tile(it + 2, s); cp_commit(); }
    }

    float* stage = (float*)smem_raw + warp * 272;
    #pragma unroll
    for (int mi = 0; mi < 4; mi++) {
        #pragma unroll
        for (int ni = 0; ni < 2; ni++) {
            wmma::store_matrix_sync(stage, acc[mi][ni], 16, wmma::mem_row_major);
            __syncwarp();
            #pragma unroll
            for (int l = 0; l < 8; l++) {
                int e = lane + l * 32;
                int r = e >> 4, cc = e & 15;
                int gr = m0 + wm + mi*16 + r;
                int gc = n0 + wn + ni*16 + cc;
                float v = stage[r * 16 + cc];
                if (MODE >= 1) v += bias[gc];
                if (MODE == 1) v += resid[(size_t)gr * N + gc];
                if (MODE == 2) v = gelu_tanh(v);
                if (OUTH)
                    outh[(size_t)gr * N + gc] = __float2half(v);
                else
                    outf[(size_t)gr * N + gc] = v;
            }
            __syncwarp();
        }
    }
}

/* ------------- tensor-core sliding-window (64) attention ----------- */
/* per CTA: 64 queries (t0..t0+63) of head h, batch b.
   Kext rows j=0..127 <-> s = t0-63+j (zero-filled OOB).
   S[64][128] = Q @ Kext^T ; masked softmax (j in [i,i+63], s>=0);
   P half in-place over S ; O = P @ V.
   smem: Qs 64x72h | Ks 128x72h | Vs 128x72h | Sf 64x136f           */
#define AQ_OFF 0
#define AK_OFF 9216
#define AV_OFF 27648
#define AS_OFF 46080
#define ATT_SMEM (AS_OFF + 64*136*4)   /* 80896 B */

__global__ __launch_bounds__(256)
void attn_wmma(const __half* __restrict__ QKV, __half* __restrict__ O)
{
    extern __shared__ __align__(16) unsigned char smem[];
    __half* Qs = (__half*)(smem + AQ_OFF);   /* ld 72 */
    __half* Ks = (__half*)(smem + AK_OFF);   /* ld 72 */
    __half* Vs = (__half*)(smem + AV_OFF);   /* ld 72 */
    float*  Sf = (float*)(smem + AS_OFF);    /* ld 136 */
    __half* Ph = (__half*)(smem + AS_OFF);   /* ld 272, overlays Sf */
    const uint32_t squ = (uint32_t)__cvta_generic_to_shared(smem);

    const int tid = threadIdx.x, warp = tid >> 5, lane = tid & 31;
    const int b = blockIdx.z, h = blockIdx.y;
    const int t0 = blockIdx.x * 64;
    const int hc = h * HS;

    /* ---- async loads: Q (512 chunks), K (1024), V (1024) ---- */
    #pragma unroll
    for (int i = 0; i < 2; i++) {
        int c = tid + i * 256;
        int r = c >> 3, col = (c & 7) * 8;
        cp_async16(squ + AQ_OFF + (uint32_t)(r * 144 + col * 2),
                   QKV + ((size_t)(b * TSEQ + t0 + r)) * QKVD + hc + col);
    }
    #pragma unroll
    for (int i = 0; i < 4; i++) {
        int c = tid + i * 256;
        int r = c >> 3, col = (c & 7) * 8;
        int s = t0 - 63 + r;
        int ok = (s >= 0 && s < TSEQ) ? 16 : 0;
        int sc = s < 0 ? 0 : (s >= TSEQ ? TSEQ - 1 : s);
        cp_async16z(squ + AK_OFF + (uint32_t)(r * 144 + col * 2),
                    QKV + ((size_t)(b * TSEQ + sc)) * QKVD + N_EMBD + hc + col, ok);
    }
    #pragma unroll
    for (int i = 0; i < 4; i++) {
        int c = tid + i * 256;
        int r = c >> 3, col = (c & 7) * 8;
        int s = t0 - 63 + r;
        int ok = (s >= 0 && s < TSEQ) ? 16 : 0;
        int sc = s < 0 ? 0 : (s >= TSEQ ? TSEQ - 1 : s);
        cp_async16z(squ + AV_OFF + (uint32_t)(r * 144 + col * 2),
                    QKV + ((size_t)(b * TSEQ + sc)) * QKVD + 2*N_EMBD + hc + col, ok);
    }
    cp_commit();
    cp_wait0();
    __syncthreads();

    /* ---- S = Q @ Kext^T : warp w -> m-block (w&3), n-blocks (w>>2)*4.. ---- */
    {
        const int mb = warp & 3, nb0 = (warp >> 2) * 4;
        wmma::fragment<wmma::accumulator, 16, 16, 16, float> sa[4];
        #pragma unroll
        for (int t = 0; t < 4; t++) wmma::fill_fragment(sa[t], 0.f);
        #pragma unroll
        for (int k = 0; k < 4; k++) {
            wmma::fragment<wmma::matrix_a, 16, 16, 16, __half, wmma::row_major> af;
            wmma::load_matrix_sync(af, Qs + mb * 16 * 72 + k * 16, 72);
            #pragma unroll
            for (int t = 0; t < 4; t++) {
                wmma::fragment<wmma::matrix_b, 16, 16, 16, __half, wmma::col_major> bf;
                wmma::load_matrix_sync(bf, Ks + (nb0 + t) * 16 * 72 + k * 16, 72);
                wmma::mma_sync(sa[t], af, bf, sa[t]);
            }
        }
        #pragma unroll
        for (int t = 0; t < 4; t++)
            wmma::store_matrix_sync(Sf + mb * 16 * 136 + (nb0 + t) * 16, sa[t],
                                    136, wmma::mem_row_major);
    }
    __syncthreads();

    /* ---- masked softmax; P (half) written in place over Sf ---- */
    {
        for (int r = warp * 8; r < warp * 8 + 8; r++) {
            float vals[4];
            #pragma unroll
            for (int q = 0; q < 4; q++) {
                int j = lane + q * 32;
                float v = Sf[r * 136 + j] * 0.125f;
                bool valid = (j >= r) && (j <= r + 63) && (t0 - 63 + j >= 0);
                vals[q] = valid ? v : -1e30f;
            }
            float mx = fmaxf(fmaxf(vals[0], vals[1]), fmaxf(vals[2], vals[3]));
            #pragma unroll
            for (int o = 16; o; o >>= 1) mx = fmaxf(mx, __shfl_xor_sync(0xffffffffu, mx, o));
            float e[4], sum = 0.f;
            #pragma unroll
            for (int q = 0; q < 4; q++) { e[q] = __expf(vals[q] - mx); sum += e[q]; }
            #pragma unroll
            for (int o = 16; o; o >>= 1) sum += __shfl_xor_sync(0xffffffffu, sum, o);
            float inv = 1.f / sum;
            #pragma unroll
            for (int q = 0; q < 4; q++)
                Ph[r * 272 + lane + q * 32] = __float2half(e[q] * inv);
        }
    }
    __syncthreads();

    /* ---- O = P @ V : warp w -> m (w&3), n pair (w>>2)*2..+1 ---- */
    {
        const int mb = warp & 3, nb0 = (warp >> 2) * 2;
        wmma::fragment<wmma::accumulator, 16, 16, 16, float> oa[2];
        #pragma unroll
        for (int t = 0; t < 2; t++) wmma::fill_fragment(oa[t], 0.f);
        #pragma unroll
        for (int k = 0; k < 8; k++) {
            wmma::fragment<wmma::matrix_a, 16, 16, 16, __half, wmma::row_major> af;
            wmma::load_matrix_sync(af, Ph + mb * 16 * 272 + k * 16, 272);
            #pragma unroll
            for (int t = 0; t < 2; t++) {
                wmma::fragment<wmma::matrix_b, 16, 16, 16, __half, wmma::row_major> bf;
                wmma::load_matrix_sync(bf, Vs + k * 16 * 72 + (nb0 + t) * 16, 72);
                wmma::mma_sync(oa[t], af, bf, oa[t]);
            }
        }
        /* stage through Qs area (free now): warp-private 1088B */
        float* stg = (float*)(smem + warp * 1088);
        #pragma unroll
        for (int t = 0; t < 2; t++) {
            wmma::store_matrix_sync(stg, oa[t], 16, wmma::mem_row_major);
            __syncwarp();
            #pragma unroll
            for (int l = 0; l < 8; l++) {
                int e = lane + l * 32;
                int r = e >> 4, cc = e & 15;
                int gr = t0 + mb * 16 + r;
                int gc = hc + (nb0 + t) * 16 + cc;
                O[((size_t)(b * TSEQ + gr)) * N_EMBD + gc] = __float2half(stg[r * 16 + cc]);
            }
            __syncwarp();
        }
    }
}

/* --------------------------- tail zero ----------------------------- */
__global__ void tail_kernel(float* out, int start, int total)
{
    int i = start + blockIdx.x * blockDim.x + threadIdx.x;
    if (i < total) out[i] = 0.f;
}

/* --------------------------- launcher ------------------------------ */
extern "C" void kernel_launch(void* const* d_in, const int* in_sizes, int n_in,
                              void* d_out, int out_size)
{
    const float* x      = (const float*)d_in[0];
    const float* w_q    = (const float*)d_in[1];
    const float* w_k    = (const float*)d_in[2];
    const float* w_v    = (const float*)d_in[3];
    const float* w_proj = (const float*)d_in[4];
    const float* b_proj = (const float*)d_in[5];
    const float* w_ff1  = (const float*)d_in[6];
    const float* b_ff1  = (const float*)d_in[7];
    const float* w_ff2  = (const float*)d_in[8];
    const float* b_ff2  = (const float*)d_in[9];
    const float* g1     = (const float*)d_in[10];
    const float* g2     = (const float*)d_in[11];
    float* out = (float*)d_out;

    float *x1;
    __half *qkvh, *h1h, *atth, *h2h, *ffhh, *wqkv, *wtp, *wt1, *wt2;
    { void* p;
      cudaGetSymbolAddress(&p, g_x1);   x1   = (float*)p;
      cudaGetSymbolAddress(&p, g_qkvh); qkvh = (__half*)p;
      cudaGetSymbolAddress(&p, g_h1h);  h1h  = (__half*)p;
      cudaGetSymbolAddress(&p, g_atth); atth = (__half*)p;
      cudaGetSymbolAddress(&p, g_h2h);  h2h  = (__half*)p;
      cudaGetSymbolAddress(&p, g_ffhh); ffhh = (__half*)p;
      cudaGetSymbolAddress(&p, g_wqkv); wqkv = (__half*)p;
      cudaGetSymbolAddress(&p, g_wtp);  wtp  = (__half*)p;
      cudaGetSymbolAddress(&p, g_wt1);  wt1  = (__half*)p;
      cudaGetSymbolAddress(&p, g_wt2);  wt2  = (__half*)p;
    }

    cudaFuncSetAttribute(attn_wmma,
                         cudaFuncAttributeMaxDynamicSharedMemorySize, ATT_SMEM);

    /* 0. transpose weights to half [N,K] */
    {
        dim3 blk(32, 8);
        dim3 gsq(N_EMBD/32, N_EMBD/32);
        transpose_h_kernel<<<gsq, blk>>>(w_q,    wqkv,                   N_EMBD, N_EMBD);
        transpose_h_kernel<<<gsq, blk>>>(w_k,    wqkv + N_EMBD*N_EMBD,   N_EMBD, N_EMBD);
        transpose_h_kernel<<<gsq, blk>>>(w_v,    wqkv + 2*N_EMBD*N_EMBD, N_EMBD, N_EMBD);
        transpose_h_kernel<<<gsq, blk>>>(w_proj, wtp,                    N_EMBD, N_EMBD);
        dim3 gf1t(FFDIM/32, N_EMBD/32);
        transpose_h_kernel<<<gf1t, blk>>>(w_ff1,  wt1, N_EMBD, FFDIM);
        dim3 gf2t(N_EMBD/32, FFDIM/32);
        transpose_h_kernel<<<gf2t, blk>>>(w_ff2,  wt2, FFDIM, N_EMBD);
    }

    /* 1. rmsnorm(x)*g1 -> half */
    rmsnorm_h_kernel<<<MROWS, 256>>>(x, g1, h1h);

    /* 2. fused QKV GEMM -> half */
    dim3 gqkv(QKVD / BN, MROWS / BM);
    gemm_fp16<0,1><<<gqkv, 256, SMEM_GEMM>>>(h1h, wqkv, nullptr, nullptr,
                                             nullptr, qkvh, MROWS, QKVD, N_EMBD);

    /* 3. tensor-core sliding-window attention -> half */
    dim3 ga(TSEQ / 64, NHEAD, BATCH);
    attn_wmma<<<ga, 256, ATT_SMEM>>>(qkvh, atth);

    /* 4. proj: x1 = x + att @ w_proj + b_proj (fp32) */
    dim3 gp(N_EMBD / BN, MROWS / BM);
    gemm_fp16<1,0><<<gp, 256, SMEM_GEMM>>>(atth, wtp, b_proj, x,
                                           x1, nullptr, MROWS, N_EMBD, N_EMBD);

    /* 5. rmsnorm(x1)*g2 -> half */
    rmsnorm_h_kernel<<<MROWS, 256>>>(x1, g2, h2h);

    /* 6. ff1: gelu(h2 @ w_ff1 + b_ff1) -> half */
    dim3 gff1(FFDIM / BN, MROWS / BM);
    gemm_fp16<2,1><<<gff1, 256, SMEM_GEMM>>>(h2h, wt1, b_ff1, nullptr,
                                             nullptr, ffhh, MROWS, FFDIM, N_EMBD);

    /* 7. ff2: out = x1 + ffh @ w_ff2 + b_ff2 (fp32, straight to d_out) */
    gemm_fp16<1,0><<<gp, 256, SMEM_GEMM>>>(ffhh, wt2, b_ff2, x1,
                                           out, nullptr, MROWS, N_EMBD, FFDIM);

    /* 8. aux / tail */
    const int TOT = MROWS * N_EMBD;
    if (out_size > TOT) {
        int rem = out_size - TOT;
        tail_kernel<<<(rem + 255) / 256, 256>>>(out, TOT, out_size);
    }
}

// round 9
// speedup vs baseline: 4.3077x; 1.1094x over previous
#include <cstdint>
#include <cuda_runtime.h>
#include <cuda_fp16.h>
#include <mma.h>

using namespace nvcuda;

#define N_EMBD 768
#define NHEAD  12
#define HS     64
#define TSEQ   1024
#define BATCH  8
#define MROWS  (BATCH*TSEQ)     /* 8192 */
#define FFDIM  (4*N_EMBD)       /* 3072 */
#define QKVD   (3*N_EMBD)       /* 2304 */
#define WINDOW 64

/* -------- scratch (no allocation allowed -> device globals) -------- */
__device__ float  g_x1  [MROWS*N_EMBD];
__device__ __half g_qkvh[MROWS*QKVD];
__device__ __half g_h1h [MROWS*N_EMBD];
__device__ __half g_atth[MROWS*N_EMBD];
__device__ __half g_h2h [MROWS*N_EMBD];
__device__ __half g_ffhh[MROWS*FFDIM];
__device__ __half g_wqkv[QKVD*N_EMBD];
__device__ __half g_wtp [N_EMBD*N_EMBD];
__device__ __half g_wt1 [FFDIM*N_EMBD];
__device__ __half g_wt2 [N_EMBD*FFDIM];

/* --------------------- cp.async helpers ---------------------------- */
__device__ __forceinline__ void cp_async16(uint32_t dst, const void* src)
{
    asm volatile("cp.async.cg.shared.global [%0], [%1], 16;\n" :: "r"(dst), "l"(src));
}
__device__ __forceinline__ void cp_async16z(uint32_t dst, const void* src, int src_sz)
{
    asm volatile("cp.async.cg.shared.global [%0], [%1], 16, %2;\n"
                 :: "r"(dst), "l"(src), "r"(src_sz));
}
__device__ __forceinline__ void cp_commit()
{
    asm volatile("cp.async.commit_group;\n");
}
__device__ __forceinline__ void cp_wait1()
{
    asm volatile("cp.async.wait_group 1;\n");
}
__device__ __forceinline__ void cp_wait0()
{
    asm volatile("cp.async.wait_group 0;\n");
}

__device__ __forceinline__ float gelu_tanh(float v)
{
    const float c = 0.7978845608028654f;
    return 0.5f * v * (1.f + tanhf(c * (v + 0.044715f * v * v * v)));
}

/* ----------------------------- RMSNorm (half out) ------------------ */
__global__ void rmsnorm_h_kernel(const float* __restrict__ x,
                                 const float* __restrict__ g,
                                 __half* __restrict__ out)
{
    int row = blockIdx.x;
    const float4* xr = (const float4*)(x + (size_t)row * N_EMBD);
    const float4* gr = (const float4*)g;
    __half2* o2 = (__half2*)(out + (size_t)row * N_EMBD);

    float ss = 0.f;
    for (int i = threadIdx.x; i < N_EMBD/4; i += 256) {
        float4 v = xr[i];
        ss += v.x*v.x + v.y*v.y + v.z*v.z + v.w*v.w;
    }
    __shared__ float red[8];
    for (int o = 16; o; o >>= 1) ss += __shfl_xor_sync(0xffffffffu, ss, o);
    int warp = threadIdx.x >> 5, lane = threadIdx.x & 31;
    if (lane == 0) red[warp] = ss;
    __syncthreads();
    if (threadIdx.x == 0) {
        float t = 0.f;
        for (int i = 0; i < 8; i++) t += red[i];
        red[0] = t;
    }
    __syncthreads();
    float r = rsqrtf(red[0] * (1.0f / N_EMBD) + 1e-6f);

    for (int i = threadIdx.x; i < N_EMBD/4; i += 256) {
        float4 v = xr[i], gv = gr[i];
        o2[i*2]   = __floats2half2_rn(v.x * r * gv.x, v.y * r * gv.y);
        o2[i*2+1] = __floats2half2_rn(v.z * r * gv.z, v.w * r * gv.w);
    }
}

/* ---------------- weight transpose (f32 -> half) ------------------- */
__global__ void transpose4_h_kernel(const float* s0, __half* d0,
                                    const float* s1, __half* d1,
                                    const float* s2, __half* d2,
                                    const float* s3, __half* d3)
{
    __shared__ float t[32][33];
    const float* in; __half* outp;
    switch (blockIdx.z) {
        case 0: in = s0; outp = d0; break;
        case 1: in = s1; outp = d1; break;
        case 2: in = s2; outp = d2; break;
        default: in = s3; outp = d3; break;
    }
    int n0 = blockIdx.x * 32, k0 = blockIdx.y * 32;
    int tx = threadIdx.x, ty = threadIdx.y;
    #pragma unroll
    for (int dy = 0; dy < 32; dy += 8)
        t[ty + dy][tx] = in[(size_t)(k0 + ty + dy) * N_EMBD + n0 + tx];
    __syncthreads();
    #pragma unroll
    for (int dy = 0; dy < 32; dy += 8)
        outp[(size_t)(n0 + ty + dy) * N_EMBD + k0 + tx] = __float2half(t[tx][ty + dy]);
}

__global__ void transpose_h_kernel(const float* __restrict__ in,
                                   __half* __restrict__ outp, int K, int N)
{
    __shared__ float t[32][33];
    int n0 = blockIdx.x * 32, k0 = blockIdx.y * 32;
    int tx = threadIdx.x, ty = threadIdx.y;
    #pragma unroll
    for (int dy = 0; dy < 32; dy += 8)
        t[ty + dy][tx] = in[(size_t)(k0 + ty + dy) * N + n0 + tx];
    __syncthreads();
    #pragma unroll
    for (int dy = 0; dy < 32; dy += 8)
        outp[(size_t)(n0 + ty + dy) * K + k0 + tx] = __float2half(t[tx][ty + dy]);
}

/* ------------------------- FP16 WMMA GEMM (BM=128) ----------------- */
#define HSTR 72                        /* halfs per row (64+8) */
#define TILE128_H (128 * HSTR)         /* 9216 halfs */
#define TILE128_B (TILE128_H * 2)      /* 18432 bytes */
#define SMEM_G128 (4 * TILE128_B)      /* 73728 B */

template<int MODE, int OUTH>
__global__ __launch_bounds__(256, 2)
void gemm_fp16(const __half* __restrict__ A, const __half* __restrict__ BT,
               const float* __restrict__ bias, const float* __restrict__ resid,
               float* __restrict__ outf, __half* __restrict__ outh,
               int M, int N, int K)
{
    extern __shared__ __align__(16) unsigned char smem_raw[];
    __half* As = (__half*)smem_raw;                        /* [2][128][72] */
    __half* Bs = (__half*)(smem_raw + 2 * TILE128_B);      /* [2][128][72] */
    const uint32_t asu = (uint32_t)__cvta_generic_to_shared(As);
    const uint32_t bsu = (uint32_t)__cvta_generic_to_shared(Bs);

    const int tid  = threadIdx.x;
    const int warp = tid >> 5, lane = tid & 31;
    const int m0 = blockIdx.y * 128, n0 = blockIdx.x * 128;
    const int wm = (warp >> 2) * 64;
    const int wn = (warp & 3) * 32;

    wmma::fragment<wmma::accumulator, 16, 16, 16, float> acc[4][2];
    #pragma unroll
    for (int mi = 0; mi < 4; mi++)
        #pragma unroll
        for (int ni = 0; ni < 2; ni++)
            wmma::fill_fragment(acc[mi][ni], 0.f);

    const int nk = K >> 6;

    auto load_tile = [&](int ck, int s) {
        const __half* Ab = A  + (size_t)m0 * K + ck * 64;
        const __half* Bb = BT + (size_t)n0 * K + ck * 64;
        #pragma unroll
        for (int i = 0; i < 4; i++) {
            int c = tid + i * 256;
            int r = c >> 3, col = (c & 7) * 8;
            cp_async16(asu + (uint32_t)(s * TILE128_B + (r * HSTR + col) * 2),
                       Ab + (size_t)r * K + col);
        }
        #pragma unroll
        for (int i = 0; i < 4; i++) {
            int c = tid + i * 256;
            int r = c >> 3, col = (c & 7) * 8;
            cp_async16(bsu + (uint32_t)(s * TILE128_B + (r * HSTR + col) * 2),
                       Bb + (size_t)r * K + col);
        }
    };

    load_tile(0, 0); cp_commit();
    if (nk > 1) { load_tile(1, 1); cp_commit(); }

    for (int it = 0; it < nk; it++) {
        int s = it & 1;
        if (it + 1 < nk) cp_wait1(); else cp_wait0();
        __syncthreads();

        const __half* Acur = As + s * TILE128_H;
        const __half* Bcur = Bs + s * TILE128_H;

        #pragma unroll
        for (int kk = 0; kk < 64; kk += 16) {
            wmma::fragment<wmma::matrix_a, 16, 16, 16, __half, wmma::row_major> af[4];
            wmma::fragment<wmma::matrix_b, 16, 16, 16, __half, wmma::col_major> bf[2];
            #pragma unroll
            for (int mi = 0; mi < 4; mi++)
                wmma::load_matrix_sync(af[mi], Acur + (wm + mi*16) * HSTR + kk, HSTR);
            #pragma unroll
            for (int ni = 0; ni < 2; ni++)
                wmma::load_matrix_sync(bf[ni], Bcur + (wn + ni*16) * HSTR + kk, HSTR);
            #pragma unroll
            for (int mi = 0; mi < 4; mi++)
                #pragma unroll
                for (int ni = 0; ni < 2; ni++)
                    wmma::mma_sync(acc[mi][ni], af[mi], bf[ni], acc[mi][ni]);
        }
        __syncthreads();
        if (it + 2 < nk) { load_tile(it + 2, s); cp_commit(); }
    }

    float* stage = (float*)smem_raw + warp * 272;
    #pragma unroll
    for (int mi = 0; mi < 4; mi++) {
        #pragma unroll
        for (int ni = 0; ni < 2; ni++) {
            wmma::store_matrix_sync(stage, acc[mi][ni], 16, wmma::mem_row_major);
            __syncwarp();
            #pragma unroll
            for (int l = 0; l < 8; l++) {
                int e = lane + l * 32;
                int r = e >> 4, cc = e & 15;
                int gr = m0 + wm + mi*16 + r;
                int gc = n0 + wn + ni*16 + cc;
                float v = stage[r * 16 + cc];
                if (MODE >= 1) v += bias[gc];
                if (MODE == 1) v += resid[(size_t)gr * N + gc];
                if (MODE == 2) v = gelu_tanh(v);
                if (OUTH)
                    outh[(size_t)gr * N + gc] = __float2half(v);
                else
                    outf[(size_t)gr * N + gc] = v;
            }
            __syncwarp();
        }
    }
}

/* ------------------------- FP16 WMMA GEMM (BM=64) ------------------ */
#define TILE64A_H (64 * HSTR)          /* 4608 halfs */
#define TILE64A_B (TILE64A_H * 2)      /* 9216 bytes */
#define SMEM_G64  (2 * TILE64A_B + 2 * TILE128_B)  /* 55296 B */

template<int MODE, int OUTH>
__global__ __launch_bounds__(256, 3)
void gemm_fp16_s(const __half* __restrict__ A, const __half* __restrict__ BT,
                 const float* __restrict__ bias, const float* __restrict__ resid,
                 float* __restrict__ outf, __half* __restrict__ outh,
                 int M, int N, int K)
{
    extern __shared__ __align__(16) unsigned char smem_raw[];
    __half* As = (__half*)smem_raw;                        /* [2][64][72]  */
    __half* Bs = (__half*)(smem_raw + 2 * TILE64A_B);      /* [2][128][72] */
    const uint32_t asu = (uint32_t)__cvta_generic_to_shared(As);
    const uint32_t bsu = (uint32_t)__cvta_generic_to_shared(Bs);

    const int tid  = threadIdx.x;
    const int warp = tid >> 5, lane = tid & 31;
    const int m0 = blockIdx.y * 64, n0 = blockIdx.x * 128;
    const int wm = (warp >> 2) * 32;     /* 0 / 32  */
    const int wn = (warp & 3) * 32;      /* 0..96   */

    wmma::fragment<wmma::accumulator, 16, 16, 16, float> acc[2][2];
    #pragma unroll
    for (int mi = 0; mi < 2; mi++)
        #pragma unroll
        for (int ni = 0; ni < 2; ni++)
            wmma::fill_fragment(acc[mi][ni], 0.f);

    const int nk = K >> 6;

    auto load_tile = [&](int ck, int s) {
        const __half* Ab = A  + (size_t)m0 * K + ck * 64;
        const __half* Bb = BT + (size_t)n0 * K + ck * 64;
        #pragma unroll
        for (int i = 0; i < 2; i++) {
            int c = tid + i * 256;
            int r = c >> 3, col = (c & 7) * 8;
            cp_async16(asu + (uint32_t)(s * TILE64A_B + (r * HSTR + col) * 2),
                       Ab + (size_t)r * K + col);
        }
        #pragma unroll
        for (int i = 0; i < 4; i++) {
            int c = tid + i * 256;
            int r = c >> 3, col = (c & 7) * 8;
            cp_async16(bsu + (uint32_t)(s * TILE128_B + (r * HSTR + col) * 2),
                       Bb + (size_t)r * K + col);
        }
    };

    load_tile(0, 0); cp_commit();
    if (nk > 1) { load_tile(1, 1); cp_commit(); }

    for (int it = 0; it < nk; it++) {
        int s = it & 1;
        if (it + 1 < nk) cp_wait1(); else cp_wait0();
        __syncthreads();

        const __half* Acur = As + s * TILE64A_H;
        const __half* Bcur = Bs + s * TILE128_H;

        #pragma unroll
        for (int kk = 0; kk < 64; kk += 16) {
            wmma::fragment<wmma::matrix_a, 16, 16, 16, __half, wmma::row_major> af[2];
            wmma::fragment<wmma::matrix_b, 16, 16, 16, __half, wmma::col_major> bf[2];
            #pragma unroll
            for (int mi = 0; mi < 2; mi++)
                wmma::load_matrix_sync(af[mi], Acur + (wm + mi*16) * HSTR + kk, HSTR);
            #pragma unroll
            for (int ni = 0; ni < 2; ni++)
                wmma::load_matrix_sync(bf[ni], Bcur + (wn + ni*16) * HSTR + kk, HSTR);
            #pragma unroll
            for (int mi = 0; mi < 2; mi++)
                #pragma unroll
                for (int ni = 0; ni < 2; ni++)
                    wmma::mma_sync(acc[mi][ni], af[mi], bf[ni], acc[mi][ni]);
        }
        __syncthreads();
        if (it + 2 < nk) { load_tile(it + 2, s); cp_commit(); }
    }

    float* stage = (float*)smem_raw + warp * 272;
    #pragma unroll
    for (int mi = 0; mi < 2; mi++) {
        #pragma unroll
        for (int ni = 0; ni < 2; ni++) {
            wmma::store_matrix_sync(stage, acc[mi][ni], 16, wmma::mem_row_major);
            __syncwarp();
            #pragma unroll
            for (int l = 0; l < 8; l++) {
                int e = lane + l * 32;
                int r = e >> 4, cc = e & 15;
                int gr = m0 + wm + mi*16 + r;
                int gc = n0 + wn + ni*16 + cc;
                float v = stage[r * 16 + cc];
                if (MODE >= 1) v += bias[gc];
                if (MODE == 1) v += resid[(size_t)gr * N + gc];
                if (MODE == 2) v = gelu_tanh(v);
                if (OUTH)
                    outh[(size_t)gr * N + gc] = __float2half(v);
                else
                    outf[(size_t)gr * N + gc] = v;
            }
            __syncwarp();
        }
    }
}

/* ------------- tensor-core sliding-window (64) attention ----------- */
#define AQ_OFF 0
#define AK_OFF 9216
#define AV_OFF 27648
#define AS_OFF 46080
#define ATT_SMEM (AS_OFF + 64*136*4)   /* 80896 B */

__global__ __launch_bounds__(256)
void attn_wmma(const __half* __restrict__ QKV, __half* __restrict__ O)
{
    extern __shared__ __align__(16) unsigned char smem[];
    __half* Qs = (__half*)(smem + AQ_OFF);   /* ld 72 */
    __half* Ks = (__half*)(smem + AK_OFF);   /* ld 72 */
    __half* Vs = (__half*)(smem + AV_OFF);   /* ld 72 */
    float*  Sf = (float*)(smem + AS_OFF);    /* ld 136 */
    __half* Ph = (__half*)(smem + AS_OFF);   /* ld 272 */
    const uint32_t squ = (uint32_t)__cvta_generic_to_shared(smem);

    const int tid = threadIdx.x, warp = tid >> 5, lane = tid & 31;
    const int b = blockIdx.z, h = blockIdx.y;
    const int t0 = blockIdx.x * 64;
    const int hc = h * HS;

    #pragma unroll
    for (int i = 0; i < 2; i++) {
        int c = tid + i * 256;
        int r = c >> 3, col = (c & 7) * 8;
        cp_async16(squ + AQ_OFF + (uint32_t)(r * 144 + col * 2),
                   QKV + ((size_t)(b * TSEQ + t0 + r)) * QKVD + hc + col);
    }
    #pragma unroll
    for (int i = 0; i < 4; i++) {
        int c = tid + i * 256;
        int r = c >> 3, col = (c & 7) * 8;
        int s = t0 - 63 + r;
        int ok = (s >= 0 && s < TSEQ) ? 16 : 0;
        int sc = s < 0 ? 0 : (s >= TSEQ ? TSEQ - 1 : s);
        cp_async16z(squ + AK_OFF + (uint32_t)(r * 144 + col * 2),
                    QKV + ((size_t)(b * TSEQ + sc)) * QKVD + N_EMBD + hc + col, ok);
    }
    #pragma unroll
    for (int i = 0; i < 4; i++) {
        int c = tid + i * 256;
        int r = c >> 3, col = (c & 7) * 8;
        int s = t0 - 63 + r;
        int ok = (s >= 0 && s < TSEQ) ? 16 : 0;
        int sc = s < 0 ? 0 : (s >= TSEQ ? TSEQ - 1 : s);
        cp_async16z(squ + AV_OFF + (uint32_t)(r * 144 + col * 2),
                    QKV + ((size_t)(b * TSEQ + sc)) * QKVD + 2*N_EMBD + hc + col, ok);
    }
    cp_commit();
    cp_wait0();
    __syncthreads();

    {
        const int mb = warp & 3, nb0 = (warp >> 2) * 4;
        wmma::fragment<wmma::accumulator, 16, 16, 16, float> sa[4];
        #pragma unroll
        for (int t = 0; t < 4; t++) wmma::fill_fragment(sa[t], 0.f);
        #pragma unroll
        for (int k = 0; k < 4; k++) {
            wmma::fragment<wmma::matrix_a, 16, 16, 16, __half, wmma::row_major> af;
            wmma::load_matrix_sync(af, Qs + mb * 16 * 72 + k * 16, 72);
            #pragma unroll
            for (int t = 0; t < 4; t++) {
                wmma::fragment<wmma::matrix_b, 16, 16, 16, __half, wmma::col_major> bf;
                wmma::load_matrix_sync(bf, Ks + (nb0 + t) * 16 * 72 + k * 16, 72);
                wmma::mma_sync(sa[t], af, bf, sa[t]);
            }
        }
        #pragma unroll
        for (int t = 0; t < 4; t++)
            wmma::store_matrix_sync(Sf + mb * 16 * 136 + (nb0 + t) * 16, sa[t],
                                    136, wmma::mem_row_major);
    }
    __syncthreads();

    {
        for (int r = warp * 8; r < warp * 8 + 8; r++) {
            float vals[4];
            #pragma unroll
            for (int q = 0; q < 4; q++) {
                int j = lane + q * 32;
                float v = Sf[r * 136 + j] * 0.125f;
                bool valid = (j >= r) && (j <= r + 63) && (t0 - 63 + j >= 0);
                vals[q] = valid ? v : -1e30f;
            }
            float mx = fmaxf(fmaxf(vals[0], vals[1]), fmaxf(vals[2], vals[3]));
            #pragma unroll
            for (int o = 16; o; o >>= 1) mx = fmaxf(mx, __shfl_xor_sync(0xffffffffu, mx, o));
            float e[4], sum = 0.f;
            #pragma unroll
            for (int q = 0; q < 4; q++) { e[q] = __expf(vals[q] - mx); sum += e[q]; }
            #pragma unroll
            for (int o = 16; o; o >>= 1) sum += __shfl_xor_sync(0xffffffffu, sum, o);
            float inv = 1.f / sum;
            #pragma unroll
            for (int q = 0; q < 4; q++)
                Ph[r * 272 + lane + q * 32] = __float2half(e[q] * inv);
        }
    }
    __syncthreads();

    {
        const int mb = warp & 3, nb0 = (warp >> 2) * 2;
        wmma::fragment<wmma::accumulator, 16, 16, 16, float> oa[2];
        #pragma unroll
        for (int t = 0; t < 2; t++) wmma::fill_fragment(oa[t], 0.f);
        #pragma unroll
        for (int k = 0; k < 8; k++) {
            wmma::fragment<wmma::matrix_a, 16, 16, 16, __half, wmma::row_major> af;
            wmma::load_matrix_sync(af, Ph + mb * 16 * 272 + k * 16, 272);
            #pragma unroll
            for (int t = 0; t < 2; t++) {
                wmma::fragment<wmma::matrix_b, 16, 16, 16, __half, wmma::row_major> bf;
                wmma::load_matrix_sync(bf, Vs + k * 16 * 72 + (nb0 + t) * 16, 72);
                wmma::mma_sync(oa[t], af, bf, oa[t]);
            }
        }
        float* stg = (float*)(smem + warp * 1088);
        #pragma unroll
        for (int t = 0; t < 2; t++) {
            wmma::store_matrix_sync(stg, oa[t], 16, wmma::mem_row_major);
            __syncwarp();
            #pragma unroll
            for (int l = 0; l < 8; l++) {
                int e = lane + l * 32;
                int r = e >> 4, cc = e & 15;
                int gr = t0 + mb * 16 + r;
                int gc = hc + (nb0 + t) * 16 + cc;
                O[((size_t)(b * TSEQ + gr)) * N_EMBD + gc] = __float2half(stg[r * 16 + cc]);
            }
            __syncwarp();
        }
    }
}

/* --------------------------- tail zero ----------------------------- */
__global__ void tail_kernel(float* out, int start, int total)
{
    int i = start + blockIdx.x * blockDim.x + threadIdx.x;
    if (i < total) out[i] = 0.f;
}

/* --------------------------- launcher ------------------------------ */
extern "C" void kernel_launch(void* const* d_in, const int* in_sizes, int n_in,
                              void* d_out, int out_size)
{
    const float* x      = (const float*)d_in[0];
    const float* w_q    = (const float*)d_in[1];
    const float* w_k    = (const float*)d_in[2];
    const float* w_v    = (const float*)d_in[3];
    const float* w_proj = (const float*)d_in[4];
    const float* b_proj = (const float*)d_in[5];
    const float* w_ff1  = (const float*)d_in[6];
    const float* b_ff1  = (const float*)d_in[7];
    const float* w_ff2  = (const float*)d_in[8];
    const float* b_ff2  = (const float*)d_in[9];
    const float* g1     = (const float*)d_in[10];
    const float* g2     = (const float*)d_in[11];
    float* out = (float*)d_out;

    float *x1;
    __half *qkvh, *h1h, *atth, *h2h, *ffhh, *wqkv, *wtp, *wt1, *wt2;
    { void* p;
      cudaGetSymbolAddress(&p, g_x1);   x1   = (float*)p;
      cudaGetSymbolAddress(&p, g_qkvh); qkvh = (__half*)p;
      cudaGetSymbolAddress(&p, g_h1h);  h1h  = (__half*)p;
      cudaGetSymbolAddress(&p, g_atth); atth = (__half*)p;
      cudaGetSymbolAddress(&p, g_h2h);  h2h  = (__half*)p;
      cudaGetSymbolAddress(&p, g_ffhh); ffhh = (__half*)p;
      cudaGetSymbolAddress(&p, g_wqkv); wqkv = (__half*)p;
      cudaGetSymbolAddress(&p, g_wtp);  wtp  = (__half*)p;
      cudaGetSymbolAddress(&p, g_wt1);  wt1  = (__half*)p;
      cudaGetSymbolAddress(&p, g_wt2);  wt2  = (__half*)p;
    }

    /* dynamic smem > 48KB requires explicit opt-in for EVERY kernel */
    cudaFuncSetAttribute(attn_wmma,
                         cudaFuncAttributeMaxDynamicSharedMemorySize, ATT_SMEM);
    cudaFuncSetAttribute(gemm_fp16<0,1>,
                         cudaFuncAttributeMaxDynamicSharedMemorySize, SMEM_G128);
    cudaFuncSetAttribute(gemm_fp16_s<1,0>,
                         cudaFuncAttributeMaxDynamicSharedMemorySize, SMEM_G64);
    cudaFuncSetAttribute(gemm_fp16_s<2,1>,
                         cudaFuncAttributeMaxDynamicSharedMemorySize, SMEM_G64);

    /* 0. transpose weights to half [N,K] (4 square merged + 2 rect) */
    {
        dim3 blk(32, 8);
        dim3 gsq(N_EMBD/32, N_EMBD/32, 4);
        transpose4_h_kernel<<<gsq, blk>>>(w_q, wqkv,
                                          w_k, wqkv + N_EMBD*N_EMBD,
                                          w_v, wqkv + 2*N_EMBD*N_EMBD,
                                          w_proj, wtp);
        dim3 gf1t(FFDIM/32, N_EMBD/32);
        transpose_h_kernel<<<gf1t, blk>>>(w_ff1,  wt1, N_EMBD, FFDIM);
        dim3 gf2t(N_EMBD/32, FFDIM/32);
        transpose_h_kernel<<<gf2t, blk>>>(w_ff2,  wt2, FFDIM, N_EMBD);
    }

    /* 1. rmsnorm(x)*g1 -> half */
    rmsnorm_h_kernel<<<MROWS, 256>>>(x, g1, h1h);

    /* 2. fused QKV GEMM -> half (BM=128) */
    dim3 gqkv(QKVD / 128, MROWS / 128);
    gemm_fp16<0,1><<<gqkv, 256, SMEM_G128>>>(h1h, wqkv, nullptr, nullptr,
                                             nullptr, qkvh, MROWS, QKVD, N_EMBD);

    /* 3. tensor-core sliding-window attention -> half */
    dim3 ga(TSEQ / 64, NHEAD, BATCH);
    attn_wmma<<<ga, 256, ATT_SMEM>>>(qkvh, atth);

    /* 4. proj: x1 = x + att @ w_proj + b_proj (BM=64) */
    dim3 gp(N_EMBD / 128, MROWS / 64);
    gemm_fp16_s<1,0><<<gp, 256, SMEM_G64>>>(atth, wtp, b_proj, x,
                                            x1, nullptr, MROWS, N_EMBD, N_EMBD);

    /* 5. rmsnorm(x1)*g2 -> half */
    rmsnorm_h_kernel<<<MROWS, 256>>>(x1, g2, h2h);

    /* 6. ff1: gelu(h2 @ w_ff1 + b_ff1) -> half (BM=64) */
    dim3 gff1(FFDIM / 128, MROWS / 64);
    gemm_fp16_s<2,1><<<gff1, 256, SMEM_G64>>>(h2h, wt1, b_ff1, nullptr,
                                              nullptr, ffhh, MROWS, FFDIM, N_EMBD);

    /* 7. ff2: out = x1 + ffh @ w_ff2 + b_ff2 (BM=64) */
    gemm_fp16_s<1,0><<<gp, 256, SMEM_G64>>>(ffhh, wt2, b_ff2, x1,
                                            out, nullptr, MROWS, N_EMBD, FFDIM);

    /* 8. aux / tail */
    const int TOT = MROWS * N_EMBD;
    if (out_size > TOT) {
        int rem = out_size - TOT;
        tail_kernel<<<(rem + 255) / 256, 256>>>(out, TOT, out_size);
    }
}

// round 10
// speedup vs baseline: 4.3646x; 1.0132x over previous
#include <cstdint>
#include <cuda_runtime.h>
#include <cuda_fp16.h>
#include <mma.h>

using namespace nvcuda;

#define N_EMBD 768
#define NHEAD  12
#define HS     64
#define TSEQ   1024
#define BATCH  8
#define MROWS  (BATCH*TSEQ)     /* 8192 */
#define FFDIM  (4*N_EMBD)       /* 3072 */
#define QKVD   (3*N_EMBD)       /* 2304 */
#define WINDOW 64

/* -------- scratch (no allocation allowed -> device globals) -------- */
__device__ float  g_x1  [MROWS*N_EMBD];
__device__ __half g_qkvh[MROWS*QKVD];
__device__ __half g_h1h [MROWS*N_EMBD];
__device__ __half g_atth[MROWS*N_EMBD];
__device__ __half g_h2h [MROWS*N_EMBD];
__device__ __half g_ffhh[MROWS*FFDIM];
__device__ __half g_wqkv[QKVD*N_EMBD];
__device__ __half g_wtp [N_EMBD*N_EMBD];
__device__ __half g_wt1 [FFDIM*N_EMBD];
__device__ __half g_wt2 [N_EMBD*FFDIM];

/* --------------------- cp.async helpers ---------------------------- */
__device__ __forceinline__ void cp_async16(uint32_t dst, const void* src)
{
    asm volatile("cp.async.cg.shared.global [%0], [%1], 16;\n" :: "r"(dst), "l"(src));
}
__device__ __forceinline__ void cp_async16z(uint32_t dst, const void* src, int src_sz)
{
    asm volatile("cp.async.cg.shared.global [%0], [%1], 16, %2;\n"
                 :: "r"(dst), "l"(src), "r"(src_sz));
}
__device__ __forceinline__ void cp_commit()
{
    asm volatile("cp.async.commit_group;\n");
}
__device__ __forceinline__ void cp_wait1()
{
    asm volatile("cp.async.wait_group 1;\n");
}
__device__ __forceinline__ void cp_wait0()
{
    asm volatile("cp.async.wait_group 0;\n");
}

__device__ __forceinline__ float gelu_tanh(float v)
{
    const float c = 0.7978845608028654f;
    return 0.5f * v * (1.f + tanhf(c * (v + 0.044715f * v * v * v)));
}

/* pack 4 floats -> 4 halfs (8B) */
__device__ __forceinline__ uint2 pack_h4(float a, float b, float c, float d)
{
    __half2 lo = __floats2half2_rn(a, b);
    __half2 hi = __floats2half2_rn(c, d);
    uint2 r;
    r.x = *(uint32_t*)&lo;
    r.y = *(uint32_t*)&hi;
    return r;
}

/* ----------------------------- RMSNorm (half out) ------------------ */
__global__ void rmsnorm_h_kernel(const float* __restrict__ x,
                                 const float* __restrict__ g,
                                 __half* __restrict__ out)
{
    int row = blockIdx.x;
    const float4* xr = (const float4*)(x + (size_t)row * N_EMBD);
    const float4* gr = (const float4*)g;
    __half2* o2 = (__half2*)(out + (size_t)row * N_EMBD);

    float ss = 0.f;
    for (int i = threadIdx.x; i < N_EMBD/4; i += 256) {
        float4 v = xr[i];
        ss += v.x*v.x + v.y*v.y + v.z*v.z + v.w*v.w;
    }
    __shared__ float red[8];
    for (int o = 16; o; o >>= 1) ss += __shfl_xor_sync(0xffffffffu, ss, o);
    int warp = threadIdx.x >> 5, lane = threadIdx.x & 31;
    if (lane == 0) red[warp] = ss;
    __syncthreads();
    if (threadIdx.x == 0) {
        float t = 0.f;
        for (int i = 0; i < 8; i++) t += red[i];
        red[0] = t;
    }
    __syncthreads();
    float r = rsqrtf(red[0] * (1.0f / N_EMBD) + 1e-6f);

    for (int i = threadIdx.x; i < N_EMBD/4; i += 256) {
        float4 v = xr[i], gv = gr[i];
        o2[i*2]   = __floats2half2_rn(v.x * r * gv.x, v.y * r * gv.y);
        o2[i*2+1] = __floats2half2_rn(v.z * r * gv.z, v.w * r * gv.w);
    }
}

/* ---------------- weight transpose (f32 -> half) ------------------- */
__global__ void transpose4_h_kernel(const float* s0, __half* d0,
                                    const float* s1, __half* d1,
                                    const float* s2, __half* d2,
                                    const float* s3, __half* d3)
{
    __shared__ float t[32][33];
    const float* in; __half* outp;
    switch (blockIdx.z) {
        case 0: in = s0; outp = d0; break;
        case 1: in = s1; outp = d1; break;
        case 2: in = s2; outp = d2; break;
        default: in = s3; outp = d3; break;
    }
    int n0 = blockIdx.x * 32, k0 = blockIdx.y * 32;
    int tx = threadIdx.x, ty = threadIdx.y;
    #pragma unroll
    for (int dy = 0; dy < 32; dy += 8)
        t[ty + dy][tx] = in[(size_t)(k0 + ty + dy) * N_EMBD + n0 + tx];
    __syncthreads();
    #pragma unroll
    for (int dy = 0; dy < 32; dy += 8)
        outp[(size_t)(n0 + ty + dy) * N_EMBD + k0 + tx] = __float2half(t[tx][ty + dy]);
}

__global__ void transpose_h_kernel(const float* __restrict__ in,
                                   __half* __restrict__ outp, int K, int N)
{
    __shared__ float t[32][33];
    int n0 = blockIdx.x * 32, k0 = blockIdx.y * 32;
    int tx = threadIdx.x, ty = threadIdx.y;
    #pragma unroll
    for (int dy = 0; dy < 32; dy += 8)
        t[ty + dy][tx] = in[(size_t)(k0 + ty + dy) * N + n0 + tx];
    __syncthreads();
    #pragma unroll
    for (int dy = 0; dy < 32; dy += 8)
        outp[(size_t)(n0 + ty + dy) * K + k0 + tx] = __float2half(t[tx][ty + dy]);
}

/* ------------------------- FP16 WMMA GEMM (BM=128) ----------------- */
#define HSTR 72                        /* halfs per row (64+8) */
#define TILE128_H (128 * HSTR)         /* 9216 halfs */
#define TILE128_B (TILE128_H * 2)      /* 18432 bytes */
#define SMEM_G128 (4 * TILE128_B)      /* 73728 B */
#define ESTR 136                       /* epilogue stage stride (floats) */

template<int MODE, int OUTH>
__global__ __launch_bounds__(256, 2)
void gemm_fp16(const __half* __restrict__ A, const __half* __restrict__ BT,
               const float* __restrict__ bias, const float* __restrict__ resid,
               float* __restrict__ outf, __half* __restrict__ outh,
               int M, int N, int K)
{
    extern __shared__ __align__(16) unsigned char smem_raw[];
    __half* As = (__half*)smem_raw;                        /* [2][128][72] */
    __half* Bs = (__half*)(smem_raw + 2 * TILE128_B);      /* [2][128][72] */
    const uint32_t asu = (uint32_t)__cvta_generic_to_shared(As);
    const uint32_t bsu = (uint32_t)__cvta_generic_to_shared(Bs);

    const int tid  = threadIdx.x;
    const int warp = tid >> 5;
    const int m0 = blockIdx.y * 128, n0 = blockIdx.x * 128;
    const int wm = (warp >> 2) * 64;
    const int wn = (warp & 3) * 32;

    wmma::fragment<wmma::accumulator, 16, 16, 16, float> acc[4][2];
    #pragma unroll
    for (int mi = 0; mi < 4; mi++)
        #pragma unroll
        for (int ni = 0; ni < 2; ni++)
            wmma::fill_fragment(acc[mi][ni], 0.f);

    const int nk = K >> 6;

    auto load_tile = [&](int ck, int s) {
        const __half* Ab = A  + (size_t)m0 * K + ck * 64;
        const __half* Bb = BT + (size_t)n0 * K + ck * 64;
        #pragma unroll
        for (int i = 0; i < 4; i++) {
            int c = tid + i * 256;
            int r = c >> 3, col = (c & 7) * 8;
            cp_async16(asu + (uint32_t)(s * TILE128_B + (r * HSTR + col) * 2),
                       Ab + (size_t)r * K + col);
        }
        #pragma unroll
        for (int i = 0; i < 4; i++) {
            int c = tid + i * 256;
            int r = c >> 3, col = (c & 7) * 8;
            cp_async16(bsu + (uint32_t)(s * TILE128_B + (r * HSTR + col) * 2),
                       Bb + (size_t)r * K + col);
        }
    };

    load_tile(0, 0); cp_commit();
    if (nk > 1) { load_tile(1, 1); cp_commit(); }

    for (int it = 0; it < nk; it++) {
        int s = it & 1;
        if (it + 1 < nk) cp_wait1(); else cp_wait0();
        __syncthreads();

        const __half* Acur = As + s * TILE128_H;
        const __half* Bcur = Bs + s * TILE128_H;

        #pragma unroll
        for (int kk = 0; kk < 64; kk += 16) {
            wmma::fragment<wmma::matrix_a, 16, 16, 16, __half, wmma::row_major> af[4];
            wmma::fragment<wmma::matrix_b, 16, 16, 16, __half, wmma::col_major> bf[2];
            #pragma unroll
            for (int mi = 0; mi < 4; mi++)
                wmma::load_matrix_sync(af[mi], Acur + (wm + mi*16) * HSTR + kk, HSTR);
            #pragma unroll
            for (int ni = 0; ni < 2; ni++)
                wmma::load_matrix_sync(bf[ni], Bcur + (wn + ni*16) * HSTR + kk, HSTR);
            #pragma unroll
            for (int mi = 0; mi < 4; mi++)
                #pragma unroll
                for (int ni = 0; ni < 2; ni++)
                    wmma::mma_sync(acc[mi][ni], af[mi], bf[ni], acc[mi][ni]);
        }
        __syncthreads();
        if (it + 2 < nk) { load_tile(it + 2, s); cp_commit(); }
    }

    /* epilogue: stage whole 128x128 fp32 tile, then coalesced stores */
    float* stage = (float*)smem_raw;    /* 128 x ESTR = 69632 B */
    #pragma unroll
    for (int mi = 0; mi < 4; mi++)
        #pragma unroll
        for (int ni = 0; ni < 2; ni++)
            wmma::store_matrix_sync(stage + (wm + mi*16) * ESTR + wn + ni*16,
                                    acc[mi][ni], ESTR, wmma::mem_row_major);
    __syncthreads();

    #pragma unroll
    for (int i = 0; i < 16; i++) {
        int idx = tid + i * 256;           /* 4096 float4 slots */
        int r = idx >> 5, c4 = idx & 31;
        int col = c4 * 4;
        float4 v = *(float4*)&stage[r * ESTR + col];
        int gr = m0 + r, gc = n0 + col;
        if (MODE >= 1) {
            float4 b = *(const float4*)&bias[gc];
            v.x += b.x; v.y += b.y; v.z += b.z; v.w += b.w;
        }
        if (MODE == 1) {
            float4 rr = *(const float4*)&resid[(size_t)gr * N + gc];
            v.x += rr.x; v.y += rr.y; v.z += rr.z; v.w += rr.w;
        }
        if (MODE == 2) {
            v.x = gelu_tanh(v.x); v.y = gelu_tanh(v.y);
            v.z = gelu_tanh(v.z); v.w = gelu_tanh(v.w);
        }
        if (OUTH)
            *(uint2*)&outh[(size_t)gr * N + gc] = pack_h4(v.x, v.y, v.z, v.w);
        else
            *(float4*)&outf[(size_t)gr * N + gc] = v;
    }
}

/* ------------------------- FP16 WMMA GEMM (BM=64) ------------------ */
#define TILE64A_H (64 * HSTR)          /* 4608 halfs */
#define TILE64A_B (TILE64A_H * 2)      /* 9216 bytes */
#define SMEM_G64  (2 * TILE64A_B + 2 * TILE128_B)  /* 55296 B */

template<int MODE, int OUTH>
__global__ __launch_bounds__(256, 3)
void gemm_fp16_s(const __half* __restrict__ A, const __half* __restrict__ BT,
                 const float* __restrict__ bias, const float* __restrict__ resid,
                 float* __restrict__ outf, __half* __restrict__ outh,
                 int M, int N, int K)
{
    extern __shared__ __align__(16) unsigned char smem_raw[];
    __half* As = (__half*)smem_raw;                        /* [2][64][72]  */
    __half* Bs = (__half*)(smem_raw + 2 * TILE64A_B);      /* [2][128][72] */
    const uint32_t asu = (uint32_t)__cvta_generic_to_shared(As);
    const uint32_t bsu = (uint32_t)__cvta_generic_to_shared(Bs);

    const int tid  = threadIdx.x;
    const int warp = tid >> 5;
    const int m0 = blockIdx.y * 64, n0 = blockIdx.x * 128;
    const int wm = (warp >> 2) * 32;     /* 0 / 32  */
    const int wn = (warp & 3) * 32;      /* 0..96   */

    wmma::fragment<wmma::accumulator, 16, 16, 16, float> acc[2][2];
    #pragma unroll
    for (int mi = 0; mi < 2; mi++)
        #pragma unroll
        for (int ni = 0; ni < 2; ni++)
            wmma::fill_fragment(acc[mi][ni], 0.f);

    const int nk = K >> 6;

    auto load_tile = [&](int ck, int s) {
        const __half* Ab = A  + (size_t)m0 * K + ck * 64;
        const __half* Bb = BT + (size_t)n0 * K + ck * 64;
        #pragma unroll
        for (int i = 0; i < 2; i++) {
            int c = tid + i * 256;
            int r = c >> 3, col = (c & 7) * 8;
            cp_async16(asu + (uint32_t)(s * TILE64A_B + (r * HSTR + col) * 2),
                       Ab + (size_t)r * K + col);
        }
        #pragma unroll
        for (int i = 0; i < 4; i++) {
            int c = tid + i * 256;
            int r = c >> 3, col = (c & 7) * 8;
            cp_async16(bsu + (uint32_t)(s * TILE128_B + (r * HSTR + col) * 2),
                       Bb + (size_t)r * K + col);
        }
    };

    load_tile(0, 0); cp_commit();
    if (nk > 1) { load_tile(1, 1); cp_commit(); }

    for (int it = 0; it < nk; it++) {
        int s = it & 1;
        if (it + 1 < nk) cp_wait1(); else cp_wait0();
        __syncthreads();

        const __half* Acur = As + s * TILE64A_H;
        const __half* Bcur = Bs + s * TILE128_H;

        #pragma unroll
        for (int kk = 0; kk < 64; kk += 16) {
            wmma::fragment<wmma::matrix_a, 16, 16, 16, __half, wmma::row_major> af[2];
            wmma::fragment<wmma::matrix_b, 16, 16, 16, __half, wmma::col_major> bf[2];
            #pragma unroll
            for (int mi = 0; mi < 2; mi++)
                wmma::load_matrix_sync(af[mi], Acur + (wm + mi*16) * HSTR + kk, HSTR);
            #pragma unroll
            for (int ni = 0; ni < 2; ni++)
                wmma::load_matrix_sync(bf[ni], Bcur + (wn + ni*16) * HSTR + kk, HSTR);
            #pragma unroll
            for (int mi = 0; mi < 2; mi++)
                #pragma unroll
                for (int ni = 0; ni < 2; ni++)
                    wmma::mma_sync(acc[mi][ni], af[mi], bf[ni], acc[mi][ni]);
        }
        __syncthreads();
        if (it + 2 < nk) { load_tile(it + 2, s); cp_commit(); }
    }

    /* epilogue: stage 64x128 fp32 tile, then coalesced stores */
    float* stage = (float*)smem_raw;    /* 64 x ESTR = 34816 B */
    #pragma unroll
    for (int mi = 0; mi < 2; mi++)
        #pragma unroll
        for (int ni = 0; ni < 2; ni++)
            wmma::store_matrix_sync(stage + (wm + mi*16) * ESTR + wn + ni*16,
                                    acc[mi][ni], ESTR, wmma::mem_row_major);
    __syncthreads();

    #pragma unroll
    for (int i = 0; i < 8; i++) {
        int idx = tid + i * 256;           /* 2048 float4 slots */
        int r = idx >> 5, c4 = idx & 31;
        int col = c4 * 4;
        float4 v = *(float4*)&stage[r * ESTR + col];
        int gr = m0 + r, gc = n0 + col;
        if (MODE >= 1) {
            float4 b = *(const float4*)&bias[gc];
            v.x += b.x; v.y += b.y; v.z += b.z; v.w += b.w;
        }
        if (MODE == 1) {
            float4 rr = *(const float4*)&resid[(size_t)gr * N + gc];
            v.x += rr.x; v.y += rr.y; v.z += rr.z; v.w += rr.w;
        }
        if (MODE == 2) {
            v.x = gelu_tanh(v.x); v.y = gelu_tanh(v.y);
            v.z = gelu_tanh(v.z); v.w = gelu_tanh(v.w);
        }
        if (OUTH)
            *(uint2*)&outh[(size_t)gr * N + gc] = pack_h4(v.x, v.y, v.z, v.w);
        else
            *(float4*)&outf[(size_t)gr * N + gc] = v;
    }
}

/* ------------- tensor-core sliding-window (64) attention ----------- */
#define AQ_OFF 0
#define AK_OFF 9216
#define AV_OFF 27648
#define AS_OFF 46080
#define ATT_SMEM (AS_OFF + 64*136*4)   /* 80896 B */

__global__ __launch_bounds__(256)
void attn_wmma(const __half* __restrict__ QKV, __half* __restrict__ O)
{
    extern __shared__ __align__(16) unsigned char smem[];
    __half* Qs = (__half*)(smem + AQ_OFF);   /* ld 72 */
    __half* Ks = (__half*)(smem + AK_OFF);   /* ld 72 */
    __half* Vs = (__half*)(smem + AV_OFF);   /* ld 72 */
    float*  Sf = (float*)(smem + AS_OFF);    /* ld 136 */
    __half* Ph = (__half*)(smem + AS_OFF);   /* ld 272 */
    const uint32_t squ = (uint32_t)__cvta_generic_to_shared(smem);

    const int tid = threadIdx.x, warp = tid >> 5, lane = tid & 31;
    const int b = blockIdx.z, h = blockIdx.y;
    const int t0 = blockIdx.x * 64;
    const int hc = h * HS;

    #pragma unroll
    for (int i = 0; i < 2; i++) {
        int c = tid + i * 256;
        int r = c >> 3, col = (c & 7) * 8;
        cp_async16(squ + AQ_OFF + (uint32_t)(r * 144 + col * 2),
                   QKV + ((size_t)(b * TSEQ + t0 + r)) * QKVD + hc + col);
    }
    #pragma unroll
    for (int i = 0; i < 4; i++) {
        int c = tid + i * 256;
        int r = c >> 3, col = (c & 7) * 8;
        int s = t0 - 63 + r;
        int ok = (s >= 0 && s < TSEQ) ? 16 : 0;
        int sc = s < 0 ? 0 : (s >= TSEQ ? TSEQ - 1 : s);
        cp_async16z(squ + AK_OFF + (uint32_t)(r * 144 + col * 2),
                    QKV + ((size_t)(b * TSEQ + sc)) * QKVD + N_EMBD + hc + col, ok);
    }
    #pragma unroll
    for (int i = 0; i < 4; i++) {
        int c = tid + i * 256;
        int r = c >> 3, col = (c & 7) * 8;
        int s = t0 - 63 + r;
        int ok = (s >= 0 && s < TSEQ) ? 16 : 0;
        int sc = s < 0 ? 0 : (s >= TSEQ ? TSEQ - 1 : s);
        cp_async16z(squ + AV_OFF + (uint32_t)(r * 144 + col * 2),
                    QKV + ((size_t)(b * TSEQ + sc)) * QKVD + 2*N_EMBD + hc + col, ok);
    }
    cp_commit();
    cp_wait0();
    __syncthreads();

    {
        const int mb = warp & 3, nb0 = (warp >> 2) * 4;
        wmma::fragment<wmma::accumulator, 16, 16, 16, float> sa[4];
        #pragma unroll
        for (int t = 0; t < 4; t++) wmma::fill_fragment(sa[t], 0.f);
        #pragma unroll
        for (int k = 0; k < 4; k++) {
            wmma::fragment<wmma::matrix_a, 16, 16, 16, __half, wmma::row_major> af;
            wmma::load_matrix_sync(af, Qs + mb * 16 * 72 + k * 16, 72);
            #pragma unroll
            for (int t = 0; t < 4; t++) {
                wmma::fragment<wmma::matrix_b, 16, 16, 16, __half, wmma::col_major> bf;
                wmma::load_matrix_sync(bf, Ks + (nb0 + t) * 16 * 72 + k * 16, 72);
                wmma::mma_sync(sa[t], af, bf, sa[t]);
            }
        }
        #pragma unroll
        for (int t = 0; t < 4; t++)
            wmma::store_matrix_sync(Sf + mb * 16 * 136 + (nb0 + t) * 16, sa[t],
                                    136, wmma::mem_row_major);
    }
    __syncthreads();

    {
        for (int r = warp * 8; r < warp * 8 + 8; r++) {
            float vals[4];
            #pragma unroll
            for (int q = 0; q < 4; q++) {
                int j = lane + q * 32;
                float v = Sf[r * 136 + j] * 0.125f;
                bool valid = (j >= r) && (j <= r + 63) && (t0 - 63 + j >= 0);
                vals[q] = valid ? v : -1e30f;
            }
            float mx = fmaxf(fmaxf(vals[0], vals[1]), fmaxf(vals[2], vals[3]));
            #pragma unroll
            for (int o = 16; o; o >>= 1) mx = fmaxf(mx, __shfl_xor_sync(0xffffffffu, mx, o));
            float e[4], sum = 0.f;
            #pragma unroll
            for (int q = 0; q < 4; q++) { e[q] = __expf(vals[q] - mx); sum += e[q]; }
            #pragma unroll
            for (int o = 16; o; o >>= 1) sum += __shfl_xor_sync(0xffffffffu, sum, o);
            float inv = 1.f / sum;
            #pragma unroll
            for (int q = 0; q < 4; q++)
                Ph[r * 272 + lane + q * 32] = __float2half(e[q] * inv);
        }
    }
    __syncthreads();

    {
        const int mb = warp & 3, nb0 = (warp >> 2) * 2;
        wmma::fragment<wmma::accumulator, 16, 16, 16, float> oa[2];
        #pragma unroll
        for (int t = 0; t < 2; t++) wmma::fill_fragment(oa[t], 0.f);
        #pragma unroll
        for (int k = 0; k < 8; k++) {
            wmma::fragment<wmma::matrix_a, 16, 16, 16, __half, wmma::row_major> af;
            wmma::load_matrix_sync(af, Ph + mb * 16 * 272 + k * 16, 272);
            #pragma unroll
            for (int t = 0; t < 2; t++) {
                wmma::fragment<wmma::matrix_b, 16, 16, 16, __half, wmma::row_major> bf;
                wmma::load_matrix_sync(bf, Vs + k * 16 * 72 + (nb0 + t) * 16, 72);
                wmma::mma_sync(oa[t], af, bf, oa[t]);
            }
        }
        /* all warps done reading Ph before overwriting with O stage */
        __syncthreads();
        float* OS = (float*)(smem + AS_OFF);   /* 64 x 72 fp32 stage */
        #pragma unroll
        for (int t = 0; t < 2; t++)
            wmma::store_matrix_sync(OS + (mb * 16) * 72 + (nb0 + t) * 16,
                                    oa[t], 72, wmma::mem_row_major);
        __syncthreads();
        #pragma unroll
        for (int i = 0; i < 4; i++) {
            int idx = tid + i * 256;           /* 1024 float4 slots */
            int r = idx >> 4, c4 = idx & 15;
            int col = c4 * 4;
            float4 v = *(float4*)&OS[r * 72 + col];
            *(uint2*)&O[((size_t)(b * TSEQ + t0 + r)) * N_EMBD + hc + col] =
                pack_h4(v.x, v.y, v.z, v.w);
        }
    }
}

/* --------------------------- tail zero ----------------------------- */
__global__ void tail_kernel(float* out, int start, int total)
{
    int i = start + blockIdx.x * blockDim.x + threadIdx.x;
    if (i < total) out[i] = 0.f;
}

/* --------------------------- launcher ------------------------------ */
extern "C" void kernel_launch(void* const* d_in, const int* in_sizes, int n_in,
                              void* d_out, int out_size)
{
    const float* x      = (const float*)d_in[0];
    const float* w_q    = (const float*)d_in[1];
    const float* w_k    = (const float*)d_in[2];
    const float* w_v    = (const float*)d_in[3];
    const float* w_proj = (const float*)d_in[4];
    const float* b_proj = (const float*)d_in[5];
    const float* w_ff1  = (const float*)d_in[6];
    const float* b_ff1  = (const float*)d_in[7];
    const float* w_ff2  = (const float*)d_in[8];
    const float* b_ff2  = (const float*)d_in[9];
    const float* g1     = (const float*)d_in[10];
    const float* g2     = (const float*)d_in[11];
    float* out = (float*)d_out;

    float *x1;
    __half *qkvh, *h1h, *atth, *h2h, *ffhh, *wqkv, *wtp, *wt1, *wt2;
    { void* p;
      cudaGetSymbolAddress(&p, g_x1);   x1   = (float*)p;
      cudaGetSymbolAddress(&p, g_qkvh); qkvh = (__half*)p;
      cudaGetSymbolAddress(&p, g_h1h);  h1h  = (__half*)p;
      cudaGetSymbolAddress(&p, g_atth); atth = (__half*)p;
      cudaGetSymbolAddress(&p, g_h2h);  h2h  = (__half*)p;
      cudaGetSymbolAddress(&p, g_ffhh); ffhh = (__half*)p;
      cudaGetSymbolAddress(&p, g_wqkv); wqkv = (__half*)p;
      cudaGetSymbolAddress(&p, g_wtp);  wtp  = (__half*)p;
      cudaGetSymbolAddress(&p, g_wt1);  wt1  = (__half*)p;
      cudaGetSymbolAddress(&p, g_wt2);  wt2  = (__half*)p;
    }

    cudaFuncSetAttribute(attn_wmma,
                         cudaFuncAttributeMaxDynamicSharedMemorySize, ATT_SMEM);
    cudaFuncSetAttribute(gemm_fp16<0,1>,
                         cudaFuncAttributeMaxDynamicSharedMemorySize, SMEM_G128);
    cudaFuncSetAttribute(gemm_fp16_s<1,0>,
                         cudaFuncAttributeMaxDynamicSharedMemorySize, SMEM_G64);
    cudaFuncSetAttribute(gemm_fp16_s<2,1>,
                         cudaFuncAttributeMaxDynamicSharedMemorySize, SMEM_G64);

    /* 0. transpose weights to half [N,K] */
    {
        dim3 blk(32, 8);
        dim3 gsq(N_EMBD/32, N_EMBD/32, 4);
        transpose4_h_kernel<<<gsq, blk>>>(w_q, wqkv,
                                          w_k, wqkv + N_EMBD*N_EMBD,
                                          w_v, wqkv + 2*N_EMBD*N_EMBD,
                                          w_proj, wtp);
        dim3 gf1t(FFDIM/32, N_EMBD/32);
        transpose_h_kernel<<<gf1t, blk>>>(w_ff1,  wt1, N_EMBD, FFDIM);
        dim3 gf2t(N_EMBD/32, FFDIM/32);
        transpose_h_kernel<<<gf2t, blk>>>(w_ff2,  wt2, FFDIM, N_EMBD);
    }

    /* 1. rmsnorm(x)*g1 -> half */
    rmsnorm_h_kernel<<<MROWS, 256>>>(x, g1, h1h);

    /* 2. fused QKV GEMM -> half (BM=128) */
    dim3 gqkv(QKVD / 128, MROWS / 128);
    gemm_fp16<0,1><<<gqkv, 256, SMEM_G128>>>(h1h, wqkv, nullptr, nullptr,
                                             nullptr, qkvh, MROWS, QKVD, N_EMBD);

    /* 3. tensor-core sliding-window attention -> half */
    dim3 ga(TSEQ / 64, NHEAD, BATCH);
    attn_wmma<<<ga, 256, ATT_SMEM>>>(qkvh, atth);

    /* 4. proj: x1 = x + att @ w_proj + b_proj (BM=64) */
    dim3 gp(N_EMBD / 128, MROWS / 64);
    gemm_fp16_s<1,0><<<gp, 256, SMEM_G64>>>(atth, wtp, b_proj, x,
                                            x1, nullptr, MROWS, N_EMBD, N_EMBD);

    /* 5. rmsnorm(x1)*g2 -> half */
    rmsnorm_h_kernel<<<MROWS, 256>>>(x1, g2, h2h);

    /* 6. ff1: gelu(h2 @ w_ff1 + b_ff1) -> half (BM=64) */
    dim3 gff1(FFDIM / 128, MROWS / 64);
    gemm_fp16_s<2,1><<<gff1, 256, SMEM_G64>>>(h2h, wt1, b_ff1, nullptr,
                                              nullptr, ffhh, MROWS, FFDIM, N_EMBD);

    /* 7. ff2: out = x1 + ffh @ w_ff2 + b_ff2 (BM=64) */
    gemm_fp16_s<1,0><<<gp, 256, SMEM_G64>>>(ffhh, wt2, b_ff2, x1,
                                            out, nullptr, MROWS, N_EMBD, FFDIM);

    /* 8. aux / tail */
    const int TOT = MROWS * N_EMBD;
    if (out_size > TOT) {
        int rem = out_size - TOT;
        tail_kernel<<<(rem + 255) / 256, 256>>>(out, TOT, out_size);
    }
}

// round 11
// speedup vs baseline: 4.4239x; 1.0136x over previous
#include <cstdint>
#include <cuda_runtime.h>
#include <cuda_fp16.h>
#include <mma.h>

using namespace nvcuda;

#define N_EMBD 768
#define NHEAD  12
#define HS     64
#define TSEQ   1024
#define BATCH  8
#define MROWS  (BATCH*TSEQ)     /* 8192 */
#define FFDIM  (4*N_EMBD)       /* 3072 */
#define QKVD   (3*N_EMBD)       /* 2304 */
#define WINDOW 64

/* -------- scratch (no allocation allowed -> device globals) -------- */
__device__ float  g_x1  [MROWS*N_EMBD];
__device__ __half g_qkvh[MROWS*QKVD];
__device__ __half g_h1h [MROWS*N_EMBD];
__device__ __half g_atth[MROWS*N_EMBD];
__device__ __half g_h2h [MROWS*N_EMBD];
__device__ __half g_ffhh[MROWS*FFDIM];
__device__ __half g_wqkv[QKVD*N_EMBD];
__device__ __half g_wtp [N_EMBD*N_EMBD];
__device__ __half g_wt1 [FFDIM*N_EMBD];
__device__ __half g_wt2 [N_EMBD*FFDIM];

/* --------------------- cp.async helpers ---------------------------- */
__device__ __forceinline__ void cp_async16(uint32_t dst, const void* src)
{
    asm volatile("cp.async.cg.shared.global [%0], [%1], 16;\n" :: "r"(dst), "l"(src));
}
__device__ __forceinline__ void cp_async16z(uint32_t dst, const void* src, int src_sz)
{
    asm volatile("cp.async.cg.shared.global [%0], [%1], 16, %2;\n"
                 :: "r"(dst), "l"(src), "r"(src_sz));
}
__device__ __forceinline__ void cp_commit()
{
    asm volatile("cp.async.commit_group;\n");
}
__device__ __forceinline__ void cp_wait1()
{
    asm volatile("cp.async.wait_group 1;\n");
}
__device__ __forceinline__ void cp_wait0()
{
    asm volatile("cp.async.wait_group 0;\n");
}

__device__ __forceinline__ float gelu_tanh(float v)
{
    const float c = 0.7978845608028654f;
    return 0.5f * v * (1.f + tanhf(c * (v + 0.044715f * v * v * v)));
}

/* pack 4 floats -> 4 halfs (8B) */
__device__ __forceinline__ uint2 pack_h4(float a, float b, float c, float d)
{
    __half2 lo = __floats2half2_rn(a, b);
    __half2 hi = __floats2half2_rn(c, d);
    uint2 r;
    r.x = *(uint32_t*)&lo;
    r.y = *(uint32_t*)&hi;
    return r;
}

/* ---------------- RMSNorm: one warp per row, x in registers -------- */
/* grid MROWS/8, block 256 (8 warps = 8 rows)                          */
__global__ __launch_bounds__(256)
void rmsnorm_h_kernel(const float* __restrict__ x,
                      const float* __restrict__ g,
                      __half* __restrict__ out)
{
    const int row  = blockIdx.x * 8 + (threadIdx.x >> 5);
    const int lane = threadIdx.x & 31;
    const float4* xr = (const float4*)(x + (size_t)row * N_EMBD);
    const float4* gr = (const float4*)g;

    float4 v[6];
    float ss = 0.f;
    #pragma unroll
    for (int k = 0; k < 6; k++) {
        v[k] = xr[lane + 32 * k];
        ss += v[k].x*v[k].x + v[k].y*v[k].y + v[k].z*v[k].z + v[k].w*v[k].w;
    }
    #pragma unroll
    for (int o = 16; o; o >>= 1) ss += __shfl_xor_sync(0xffffffffu, ss, o);
    const float r = rsqrtf(ss * (1.0f / N_EMBD) + 1e-6f);

    __half2* o2 = (__half2*)(out + (size_t)row * N_EMBD);
    #pragma unroll
    for (int k = 0; k < 6; k++) {
        float4 gv = gr[lane + 32 * k];
        int i = lane + 32 * k;
        o2[i*2]   = __floats2half2_rn(v[k].x * r * gv.x, v[k].y * r * gv.y);
        o2[i*2+1] = __floats2half2_rn(v[k].z * r * gv.z, v[k].w * r * gv.w);
    }
}

/* ------------- merged weight transpose (f32 -> half), 1 launch ----- */
/* segs 0-3: 768x768 squares (576 blocks each)                         */
/* seg  4: w_ff1 K=768,N=3072 (2304 blocks)                            */
/* seg  5: w_ff2 K=3072,N=768 (2304 blocks)                            */
#define TRANS_BLOCKS (4*576 + 2304 + 2304)   /* 6912 */

__global__ void transpose_all_kernel(const float* s0, __half* d0,
                                     const float* s1, __half* d1,
                                     const float* s2, __half* d2,
                                     const float* s3, __half* d3,
                                     const float* s4, __half* d4,
                                     const float* s5, __half* d5)
{
    __shared__ float t[32][33];
    const float* in; __half* outp;
    int K, N, n0, k0;
    int bid = blockIdx.x;
    if (bid < 2304) {
        int seg = bid / 576, r = bid % 576;
        switch (seg) {
            case 0: in = s0; outp = d0; break;
            case 1: in = s1; outp = d1; break;
            case 2: in = s2; outp = d2; break;
            default: in = s3; outp = d3; break;
        }
        K = N_EMBD; N = N_EMBD;
        n0 = (r % 24) * 32; k0 = (r / 24) * 32;
    } else if (bid < 4608) {
        int r = bid - 2304;
        in = s4; outp = d4; K = N_EMBD; N = FFDIM;
        n0 = (r % 96) * 32; k0 = (r / 96) * 32;
    } else {
        int r = bid - 4608;
        in = s5; outp = d5; K = FFDIM; N = N_EMBD;
        n0 = (r % 24) * 32; k0 = (r / 24) * 32;
    }

    int tx = threadIdx.x, ty = threadIdx.y;
    #pragma unroll
    for (int dy = 0; dy < 32; dy += 8)
        t[ty + dy][tx] = in[(size_t)(k0 + ty + dy) * N + n0 + tx];
    __syncthreads();
    #pragma unroll
    for (int dy = 0; dy < 32; dy += 8)
        outp[(size_t)(n0 + ty + dy) * K + k0 + tx] = __float2half(t[tx][ty + dy]);
}

/* ------------------------- FP16 WMMA GEMM (BM=128) ----------------- */
#define HSTR 72                        /* halfs per row (64+8) */
#define TILE128_H (128 * HSTR)         /* 9216 halfs */
#define TILE128_B (TILE128_H * 2)      /* 18432 bytes */
#define SMEM_G128 (4 * TILE128_B)      /* 73728 B */
#define ESTR 136                       /* epilogue stage stride (floats) */

template<int MODE, int OUTH>
__global__ __launch_bounds__(256, 2)
void gemm_fp16(const __half* __restrict__ A, const __half* __restrict__ BT,
               const float* __restrict__ bias, const float* __restrict__ resid,
               float* __restrict__ outf, __half* __restrict__ outh,
               int M, int N, int K)
{
    extern __shared__ __align__(16) unsigned char smem_raw[];
    __half* As = (__half*)smem_raw;                        /* [2][128][72] */
    __half* Bs = (__half*)(smem_raw + 2 * TILE128_B);      /* [2][128][72] */
    const uint32_t asu = (uint32_t)__cvta_generic_to_shared(As);
    const uint32_t bsu = (uint32_t)__cvta_generic_to_shared(Bs);

    const int tid  = threadIdx.x;
    const int warp = tid >> 5;
    const int m0 = blockIdx.y * 128, n0 = blockIdx.x * 128;
    const int wm = (warp >> 2) * 64;
    const int wn = (warp & 3) * 32;

    wmma::fragment<wmma::accumulator, 16, 16, 16, float> acc[4][2];
    #pragma unroll
    for (int mi = 0; mi < 4; mi++)
        #pragma unroll
        for (int ni = 0; ni < 2; ni++)
            wmma::fill_fragment(acc[mi][ni], 0.f);

    const int nk = K >> 6;

    auto load_tile = [&](int ck, int s) {
        const __half* Ab = A  + (size_t)m0 * K + ck * 64;
        const __half* Bb = BT + (size_t)n0 * K + ck * 64;
        #pragma unroll
        for (int i = 0; i < 4; i++) {
            int c = tid + i * 256;
            int r = c >> 3, col = (c & 7) * 8;
            cp_async16(asu + (uint32_t)(s * TILE128_B + (r * HSTR + col) * 2),
                       Ab + (size_t)r * K + col);
        }
        #pragma unroll
        for (int i = 0; i < 4; i++) {
            int c = tid + i * 256;
            int r = c >> 3, col = (c & 7) * 8;
            cp_async16(bsu + (uint32_t)(s * TILE128_B + (r * HSTR + col) * 2),
                       Bb + (size_t)r * K + col);
        }
    };

    load_tile(0, 0); cp_commit();
    if (nk > 1) { load_tile(1, 1); cp_commit(); }

    for (int it = 0; it < nk; it++) {
        int s = it & 1;
        if (it + 1 < nk) cp_wait1(); else cp_wait0();
        __syncthreads();

        const __half* Acur = As + s * TILE128_H;
        const __half* Bcur = Bs + s * TILE128_H;

        #pragma unroll
        for (int kk = 0; kk < 64; kk += 16) {
            wmma::fragment<wmma::matrix_a, 16, 16, 16, __half, wmma::row_major> af[4];
            wmma::fragment<wmma::matrix_b, 16, 16, 16, __half, wmma::col_major> bf[2];
            #pragma unroll
            for (int mi = 0; mi < 4; mi++)
                wmma::load_matrix_sync(af[mi], Acur + (wm + mi*16) * HSTR + kk, HSTR);
            #pragma unroll
            for (int ni = 0; ni < 2; ni++)
                wmma::load_matrix_sync(bf[ni], Bcur + (wn + ni*16) * HSTR + kk, HSTR);
            #pragma unroll
            for (int mi = 0; mi < 4; mi++)
                #pragma unroll
                for (int ni = 0; ni < 2; ni++)
                    wmma::mma_sync(acc[mi][ni], af[mi], bf[ni], acc[mi][ni]);
        }
        __syncthreads();
        if (it + 2 < nk) { load_tile(it + 2, s); cp_commit(); }
    }

    /* epilogue: stage whole 128x128 fp32 tile, then coalesced stores */
    float* stage = (float*)smem_raw;    /* 128 x ESTR = 69632 B */
    #pragma unroll
    for (int mi = 0; mi < 4; mi++)
        #pragma unroll
        for (int ni = 0; ni < 2; ni++)
            wmma::store_matrix_sync(stage + (wm + mi*16) * ESTR + wn + ni*16,
                                    acc[mi][ni], ESTR, wmma::mem_row_major);
    __syncthreads();

    #pragma unroll
    for (int i = 0; i < 16; i++) {
        int idx = tid + i * 256;           /* 4096 float4 slots */
        int r = idx >> 5, c4 = idx & 31;
        int col = c4 * 4;
        float4 v = *(float4*)&stage[r * ESTR + col];
        int gr = m0 + r, gc = n0 + col;
        if (MODE >= 1) {
            float4 b = *(const float4*)&bias[gc];
            v.x += b.x; v.y += b.y; v.z += b.z; v.w += b.w;
        }
        if (MODE == 1) {
            float4 rr = *(const float4*)&resid[(size_t)gr * N + gc];
            v.x += rr.x; v.y += rr.y; v.z += rr.z; v.w += rr.w;
        }
        if (MODE == 2) {
            v.x = gelu_tanh(v.x); v.y = gelu_tanh(v.y);
            v.z = gelu_tanh(v.z); v.w = gelu_tanh(v.w);
        }
        if (OUTH)
            *(uint2*)&outh[(size_t)gr * N + gc] = pack_h4(v.x, v.y, v.z, v.w);
        else
            *(float4*)&outf[(size_t)gr * N + gc] = v;
    }
}

/* ------------------------- FP16 WMMA GEMM (BM=64) ------------------ */
#define TILE64A_H (64 * HSTR)          /* 4608 halfs */
#define TILE64A_B (TILE64A_H * 2)      /* 9216 bytes */
#define SMEM_G64  (2 * TILE64A_B + 2 * TILE128_B)  /* 55296 B */

template<int MODE, int OUTH>
__global__ __launch_bounds__(256, 3)
void gemm_fp16_s(const __half* __restrict__ A, const __half* __restrict__ BT,
                 const float* __restrict__ bias, const float* __restrict__ resid,
                 float* __restrict__ outf, __half* __restrict__ outh,
                 int M, int N, int K)
{
    extern __shared__ __align__(16) unsigned char smem_raw[];
    __half* As = (__half*)smem_raw;                        /* [2][64][72]  */
    __half* Bs = (__half*)(smem_raw + 2 * TILE64A_B);      /* [2][128][72] */
    const uint32_t asu = (uint32_t)__cvta_generic_to_shared(As);
    const uint32_t bsu = (uint32_t)__cvta_generic_to_shared(Bs);

    const int tid  = threadIdx.x;
    const int warp = tid >> 5;
    const int m0 = blockIdx.y * 64, n0 = blockIdx.x * 128;
    const int wm = (warp >> 2) * 32;     /* 0 / 32  */
    const int wn = (warp & 3) * 32;      /* 0..96   */

    wmma::fragment<wmma::accumulator, 16, 16, 16, float> acc[2][2];
    #pragma unroll
    for (int mi = 0; mi < 2; mi++)
        #pragma unroll
        for (int ni = 0; ni < 2; ni++)
            wmma::fill_fragment(acc[mi][ni], 0.f);

    const int nk = K >> 6;

    auto load_tile = [&](int ck, int s) {
        const __half* Ab = A  + (size_t)m0 * K + ck * 64;
        const __half* Bb = BT + (size_t)n0 * K + ck * 64;
        #pragma unroll
        for (int i = 0; i < 2; i++) {
            int c = tid + i * 256;
            int r = c >> 3, col = (c & 7) * 8;
            cp_async16(asu + (uint32_t)(s * TILE64A_B + (r * HSTR + col) * 2),
                       Ab + (size_t)r * K + col);
        }
        #pragma unroll
        for (int i = 0; i < 4; i++) {
            int c = tid + i * 256;
            int r = c >> 3, col = (c & 7) * 8;
            cp_async16(bsu + (uint32_t)(s * TILE128_B + (r * HSTR + col) * 2),
                       Bb + (size_t)r * K + col);
        }
    };

    load_tile(0, 0); cp_commit();
    if (nk > 1) { load_tile(1, 1); cp_commit(); }

    for (int it = 0; it < nk; it++) {
        int s = it & 1;
        if (it + 1 < nk) cp_wait1(); else cp_wait0();
        __syncthreads();

        const __half* Acur = As + s * TILE64A_H;
        const __half* Bcur = Bs + s * TILE128_H;

        #pragma unroll
        for (int kk = 0; kk < 64; kk += 16) {
            wmma::fragment<wmma::matrix_a, 16, 16, 16, __half, wmma::row_major> af[2];
            wmma::fragment<wmma::matrix_b, 16, 16, 16, __half, wmma::col_major> bf[2];
            #pragma unroll
            for (int mi = 0; mi < 2; mi++)
                wmma::load_matrix_sync(af[mi], Acur + (wm + mi*16) * HSTR + kk, HSTR);
            #pragma unroll
            for (int ni = 0; ni < 2; ni++)
                wmma::load_matrix_sync(bf[ni], Bcur + (wn + ni*16) * HSTR + kk, HSTR);
            #pragma unroll
            for (int mi = 0; mi < 2; mi++)
                #pragma unroll
                for (int ni = 0; ni < 2; ni++)
                    wmma::mma_sync(acc[mi][ni], af[mi], bf[ni], acc[mi][ni]);
        }
        __syncthreads();
        if (it + 2 < nk) { load_tile(it + 2, s); cp_commit(); }
    }

    /* epilogue: stage 64x128 fp32 tile, then coalesced stores */
    float* stage = (float*)smem_raw;    /* 64 x ESTR = 34816 B */
    #pragma unroll
    for (int mi = 0; mi < 2; mi++)
        #pragma unroll
        for (int ni = 0; ni < 2; ni++)
            wmma::store_matrix_sync(stage + (wm + mi*16) * ESTR + wn + ni*16,
                                    acc[mi][ni], ESTR, wmma::mem_row_major);
    __syncthreads();

    #pragma unroll
    for (int i = 0; i < 8; i++) {
        int idx = tid + i * 256;           /* 2048 float4 slots */
        int r = idx >> 5, c4 = idx & 31;
        int col = c4 * 4;
        float4 v = *(float4*)&stage[r * ESTR + col];
        int gr = m0 + r, gc = n0 + col;
        if (MODE >= 1) {
            float4 b = *(const float4*)&bias[gc];
            v.x += b.x; v.y += b.y; v.z += b.z; v.w += b.w;
        }
        if (MODE == 1) {
            float4 rr = *(const float4*)&resid[(size_t)gr * N + gc];
            v.x += rr.x; v.y += rr.y; v.z += rr.z; v.w += rr.w;
        }
        if (MODE == 2) {
            v.x = gelu_tanh(v.x); v.y = gelu_tanh(v.y);
            v.z = gelu_tanh(v.z); v.w = gelu_tanh(v.w);
        }
        if (OUTH)
            *(uint2*)&outh[(size_t)gr * N + gc] = pack_h4(v.x, v.y, v.z, v.w);
        else
            *(float4*)&outf[(size_t)gr * N + gc] = v;
    }
}

/* ------------- tensor-core sliding-window (64) attention ----------- */
#define AQ_OFF 0
#define AK_OFF 9216
#define AV_OFF 27648
#define AS_OFF 46080
#define ATT_SMEM (AS_OFF + 64*136*4)   /* 80896 B */

__global__ __launch_bounds__(256)
void attn_wmma(const __half* __restrict__ QKV, __half* __restrict__ O)
{
    extern __shared__ __align__(16) unsigned char smem[];
    __half* Qs = (__half*)(smem + AQ_OFF);   /* ld 72 */
    __half* Ks = (__half*)(smem + AK_OFF);   /* ld 72 */
    __half* Vs = (__half*)(smem + AV_OFF);   /* ld 72 */
    float*  Sf = (float*)(smem + AS_OFF);    /* ld 136 */
    __half* Ph = (__half*)(smem + AS_OFF);   /* ld 272 */
    const uint32_t squ = (uint32_t)__cvta_generic_to_shared(smem);

    const int tid = threadIdx.x, warp = tid >> 5, lane = tid & 31;
    const int b = blockIdx.z, h = blockIdx.y;
    const int t0 = blockIdx.x * 64;
    const int hc = h * HS;

    #pragma unroll
    for (int i = 0; i < 2; i++) {
        int c = tid + i * 256;
        int r = c >> 3, col = (c & 7) * 8;
        cp_async16(squ + AQ_OFF + (uint32_t)(r * 144 + col * 2),
                   QKV + ((size_t)(b * TSEQ + t0 + r)) * QKVD + hc + col);
    }
    #pragma unroll
    for (int i = 0; i < 4; i++) {
        int c = tid + i * 256;
        int r = c >> 3, col = (c & 7) * 8;
        int s = t0 - 63 + r;
        int ok = (s >= 0 && s < TSEQ) ? 16 : 0;
        int sc = s < 0 ? 0 : (s >= TSEQ ? TSEQ - 1 : s);
        cp_async16z(squ + AK_OFF + (uint32_t)(r * 144 + col * 2),
                    QKV + ((size_t)(b * TSEQ + sc)) * QKVD + N_EMBD + hc + col, ok);
    }
    #pragma unroll
    for (int i = 0; i < 4; i++) {
        int c = tid + i * 256;
        int r = c >> 3, col = (c & 7) * 8;
        int s = t0 - 63 + r;
        int ok = (s >= 0 && s < TSEQ) ? 16 : 0;
        int sc = s < 0 ? 0 : (s >= TSEQ ? TSEQ - 1 : s);
        cp_async16z(squ + AV_OFF + (uint32_t)(r * 144 + col * 2),
                    QKV + ((size_t)(b * TSEQ + sc)) * QKVD + 2*N_EMBD + hc + col, ok);
    }
    cp_commit();
    cp_wait0();
    __syncthreads();

    {
        const int mb = warp & 3, nb0 = (warp >> 2) * 4;
        wmma::fragment<wmma::accumulator, 16, 16, 16, float> sa[4];
        #pragma unroll
        for (int t = 0; t < 4; t++) wmma::fill_fragment(sa[t], 0.f);
        #pragma unroll
        for (int k = 0; k < 4; k++) {
            wmma::fragment<wmma::matrix_a, 16, 16, 16, __half, wmma::row_major> af;
            wmma::load_matrix_sync(af, Qs + mb * 16 * 72 + k * 16, 72);
            #pragma unroll
            for (int t = 0; t < 4; t++) {
                wmma::fragment<wmma::matrix_b, 16, 16, 16, __half, wmma::col_major> bf;
                wmma::load_matrix_sync(bf, Ks + (nb0 + t) * 16 * 72 + k * 16, 72);
                wmma::mma_sync(sa[t], af, bf, sa[t]);
            }
        }
        #pragma unroll
        for (int t = 0; t < 4; t++)
            wmma::store_matrix_sync(Sf + mb * 16 * 136 + (nb0 + t) * 16, sa[t],
                                    136, wmma::mem_row_major);
    }
    __syncthreads();

    {
        for (int r = warp * 8; r < warp * 8 + 8; r++) {
            float vals[4];
            #pragma unroll
            for (int q = 0; q < 4; q++) {
                int j = lane + q * 32;
                float v = Sf[r * 136 + j] * 0.125f;
                bool valid = (j >= r) && (j <= r + 63) && (t0 - 63 + j >= 0);
                vals[q] = valid ? v : -1e30f;
            }
            float mx = fmaxf(fmaxf(vals[0], vals[1]), fmaxf(vals[2], vals[3]));
            #pragma unroll
            for (int o = 16; o; o >>= 1) mx = fmaxf(mx, __shfl_xor_sync(0xffffffffu, mx, o));
            float e[4], sum = 0.f;
            #pragma unroll
            for (int q = 0; q < 4; q++) { e[q] = __expf(vals[q] - mx); sum += e[q]; }
            #pragma unroll
            for (int o = 16; o; o >>= 1) sum += __shfl_xor_sync(0xffffffffu, sum, o);
            float inv = 1.f / sum;
            #pragma unroll
            for (int q = 0; q < 4; q++)
                Ph[r * 272 + lane + q * 32] = __float2half(e[q] * inv);
        }
    }
    __syncthreads();

    {
        const int mb = warp & 3, nb0 = (warp >> 2) * 2;
        wmma::fragment<wmma::accumulator, 16, 16, 16, float> oa[2];
        #pragma unroll
        for (int t = 0; t < 2; t++) wmma::fill_fragment(oa[t], 0.f);
        #pragma unroll
        for (int k = 0; k < 8; k++) {
            wmma::fragment<wmma::matrix_a, 16, 16, 16, __half, wmma::row_major> af;
            wmma::load_matrix_sync(af, Ph + mb * 16 * 272 + k * 16, 272);
            #pragma unroll
            for (int t = 0; t < 2; t++) {
                wmma::fragment<wmma::matrix_b, 16, 16, 16, __half, wmma::row_major> bf;
                wmma::load_matrix_sync(bf, Vs + k * 16 * 72 + (nb0 + t) * 16, 72);
                wmma::mma_sync(oa[t], af, bf, oa[t]);
            }
        }
        __syncthreads();
        float* OS = (float*)(smem + AS_OFF);   /* 64 x 72 fp32 stage */
        #pragma unroll
        for (int t = 0; t < 2; t++)
            wmma::store_matrix_sync(OS + (mb * 16) * 72 + (nb0 + t) * 16,
                                    oa[t], 72, wmma::mem_row_major);
        __syncthreads();
        #pragma unroll
        for (int i = 0; i < 4; i++) {
            int idx = tid + i * 256;           /* 1024 float4 slots */
            int r = idx >> 4, c4 = idx & 15;
            int col = c4 * 4;
            float4 v = *(float4*)&OS[r * 72 + col];
            *(uint2*)&O[((size_t)(b * TSEQ + t0 + r)) * N_EMBD + hc + col] =
                pack_h4(v.x, v.y, v.z, v.w);
        }
    }
}

/* --------------------------- tail zero ----------------------------- */
__global__ void tail_kernel(float* out, int start, int total)
{
    int i = start + blockIdx.x * blockDim.x + threadIdx.x;
    if (i < total) out[i] = 0.f;
}

/* --------------------------- launcher ------------------------------ */
extern "C" void kernel_launch(void* const* d_in, const int* in_sizes, int n_in,
                              void* d_out, int out_size)
{
    const float* x      = (const float*)d_in[0];
    const float* w_q    = (const float*)d_in[1];
    const float* w_k    = (const float*)d_in[2];
    const float* w_v    = (const float*)d_in[3];
    const float* w_proj = (const float*)d_in[4];
    const float* b_proj = (const float*)d_in[5];
    const float* w_ff1  = (const float*)d_in[6];
    const float* b_ff1  = (const float*)d_in[7];
    const float* w_ff2  = (const float*)d_in[8];
    const float* b_ff2  = (const float*)d_in[9];
    const float* g1     = (const float*)d_in[10];
    const float* g2     = (const float*)d_in[11];
    float* out = (float*)d_out;

    float *x1;
    __half *qkvh, *h1h, *atth, *h2h, *ffhh, *wqkv, *wtp, *wt1, *wt2;
    { void* p;
      cudaGetSymbolAddress(&p, g_x1);   x1   = (float*)p;
      cudaGetSymbolAddress(&p, g_qkvh); qkvh = (__half*)p;
      cudaGetSymbolAddress(&p, g_h1h);  h1h  = (__half*)p;
      cudaGetSymbolAddress(&p, g_atth); atth = (__half*)p;
      cudaGetSymbolAddress(&p, g_h2h);  h2h  = (__half*)p;
      cudaGetSymbolAddress(&p, g_ffhh); ffhh = (__half*)p;
      cudaGetSymbolAddress(&p, g_wqkv); wqkv = (__half*)p;
      cudaGetSymbolAddress(&p, g_wtp);  wtp  = (__half*)p;
      cudaGetSymbolAddress(&p, g_wt1);  wt1  = (__half*)p;
      cudaGetSymbolAddress(&p, g_wt2);  wt2  = (__half*)p;
    }

    cudaFuncSetAttribute(attn_wmma,
                         cudaFuncAttributeMaxDynamicSharedMemorySize, ATT_SMEM);
    cudaFuncSetAttribute(gemm_fp16<0,1>,
                         cudaFuncAttributeMaxDynamicSharedMemorySize, SMEM_G128);
    cudaFuncSetAttribute(gemm_fp16_s<1,0>,
                         cudaFuncAttributeMaxDynamicSharedMemorySize, SMEM_G64);
    cudaFuncSetAttribute(gemm_fp16_s<2,1>,
                         cudaFuncAttributeMaxDynamicSharedMemorySize, SMEM_G64);

    /* 0. transpose all weights to half [N,K] in ONE launch */
    {
        dim3 blk(32, 8);
        transpose_all_kernel<<<TRANS_BLOCKS, blk>>>(
            w_q, wqkv,
            w_k, wqkv + N_EMBD*N_EMBD,
            w_v, wqkv + 2*N_EMBD*N_EMBD,
            w_proj, wtp,
            w_ff1, wt1,
            w_ff2, wt2);
    }

    /* 1. rmsnorm(x)*g1 -> half (warp per row) */
    rmsnorm_h_kernel<<<MROWS/8, 256>>>(x, g1, h1h);

    /* 2. fused QKV GEMM -> half (BM=128) */
    dim3 gqkv(QKVD / 128, MROWS / 128);
    gemm_fp16<0,1><<<gqkv, 256, SMEM_G128>>>(h1h, wqkv, nullptr, nullptr,
                                             nullptr, qkvh, MROWS, QKVD, N_EMBD);

    /* 3. tensor-core sliding-window attention -> half */
    dim3 ga(TSEQ / 64, NHEAD, BATCH);
    attn_wmma<<<ga, 256, ATT_SMEM>>>(qkvh, atth);

    /* 4. proj: x1 = x + att @ w_proj + b_proj (BM=64) */
    dim3 gp(N_EMBD / 128, MROWS / 64);
    gemm_fp16_s<1,0><<<gp, 256, SMEM_G64>>>(atth, wtp, b_proj, x,
                                            x1, nullptr, MROWS, N_EMBD, N_EMBD);

    /* 5. rmsnorm(x1)*g2 -> half (warp per row) */
    rmsnorm_h_kernel<<<MROWS/8, 256>>>(x1, g2, h2h);

    /* 6. ff1: gelu(h2 @ w_ff1 + b_ff1) -> half (BM=64) */
    dim3 gff1(FFDIM / 128, MROWS / 64);
    gemm_fp16_s<2,1><<<gff1, 256, SMEM_G64>>>(h2h, wt1, b_ff1, nullptr,
                                              nullptr, ffhh, MROWS, FFDIM, N_EMBD);

    /* 7. ff2: out = x1 + ffh @ w_ff2 + b_ff2 (BM=64) */
    gemm_fp16_s<1,0><<<gp, 256, SMEM_G64>>>(ffhh, wt2, b_ff2, x1,
                                            out, nullptr, MROWS, N_EMBD, FFDIM);

    /* 8. aux / tail */
    const int TOT = MROWS * N_EMBD;
    if (out_size > TOT) {
        int rem = out_size - TOT;
        tail_kernel<<<(rem + 255) / 256, 256>>>(out, TOT, out_size);
    }
}

// round 12
// speedup vs baseline: 4.4823x; 1.0132x over previous
#include <cstdint>
#include <cuda_runtime.h>
#include <cuda_fp16.h>
#include <mma.h>

using namespace nvcuda;

#define N_EMBD 768
#define NHEAD  12
#define HS     64
#define TSEQ   1024
#define BATCH  8
#define MROWS  (BATCH*TSEQ)     /* 8192 */
#define FFDIM  (4*N_EMBD)       /* 3072 */
#define QKVD   (3*N_EMBD)       /* 2304 */
#define WINDOW 64

/* -------- scratch (no allocation allowed -> device globals) -------- */
__device__ float  g_x1  [MROWS*N_EMBD];
__device__ __half g_qkvh[MROWS*QKVD];
__device__ __half g_h1h [MROWS*N_EMBD];
__device__ __half g_atth[MROWS*N_EMBD];
__device__ __half g_h2h [MROWS*N_EMBD];
__device__ __half g_ffhh[MROWS*FFDIM];
__device__ __half g_wqkv[QKVD*N_EMBD];
__device__ __half g_wtp [N_EMBD*N_EMBD];
__device__ __half g_wt1 [FFDIM*N_EMBD];
__device__ __half g_wt2 [N_EMBD*FFDIM];

/* --------------------- cp.async helpers ---------------------------- */
__device__ __forceinline__ void cp_async16(uint32_t dst, const void* src)
{
    asm volatile("cp.async.cg.shared.global [%0], [%1], 16;\n" :: "r"(dst), "l"(src));
}
__device__ __forceinline__ void cp_async16z(uint32_t dst, const void* src, int src_sz)
{
    asm volatile("cp.async.cg.shared.global [%0], [%1], 16, %2;\n"
                 :: "r"(dst), "l"(src), "r"(src_sz));
}
__device__ __forceinline__ void cp_commit()
{
    asm volatile("cp.async.commit_group;\n");
}
__device__ __forceinline__ void cp_wait1()
{
    asm volatile("cp.async.wait_group 1;\n");
}
__device__ __forceinline__ void cp_wait0()
{
    asm volatile("cp.async.wait_group 0;\n");
}

__device__ __forceinline__ float gelu_tanh(float v)
{
    const float c = 0.7978845608028654f;
    return 0.5f * v * (1.f + tanhf(c * (v + 0.044715f * v * v * v)));
}

/* pack 4 floats -> 4 halfs (8B) */
__device__ __forceinline__ uint2 pack_h4(float a, float b, float c, float d)
{
    __half2 lo = __floats2half2_rn(a, b);
    __half2 hi = __floats2half2_rn(c, d);
    uint2 r;
    r.x = *(uint32_t*)&lo;
    r.y = *(uint32_t*)&hi;
    return r;
}

/* ---------------- RMSNorm: one warp per row, x in registers -------- */
__global__ __launch_bounds__(256)
void rmsnorm_h_kernel(const float* __restrict__ x,
                      const float* __restrict__ g,
                      __half* __restrict__ out)
{
    const int row  = blockIdx.x * 8 + (threadIdx.x >> 5);
    const int lane = threadIdx.x & 31;
    const float4* xr = (const float4*)(x + (size_t)row * N_EMBD);
    const float4* gr = (const float4*)g;

    float4 v[6];
    float ss = 0.f;
    #pragma unroll
    for (int k = 0; k < 6; k++) {
        v[k] = xr[lane + 32 * k];
        ss += v[k].x*v[k].x + v[k].y*v[k].y + v[k].z*v[k].z + v[k].w*v[k].w;
    }
    #pragma unroll
    for (int o = 16; o; o >>= 1) ss += __shfl_xor_sync(0xffffffffu, ss, o);
    const float r = rsqrtf(ss * (1.0f / N_EMBD) + 1e-6f);

    __half2* o2 = (__half2*)(out + (size_t)row * N_EMBD);
    #pragma unroll
    for (int k = 0; k < 6; k++) {
        float4 gv = gr[lane + 32 * k];
        int i = lane + 32 * k;
        o2[i*2]   = __floats2half2_rn(v[k].x * r * gv.x, v[k].y * r * gv.y);
        o2[i*2+1] = __floats2half2_rn(v[k].z * r * gv.z, v[k].w * r * gv.w);
    }
}

/* ------------- merged weight transpose (f32 -> half), 1 launch ----- */
#define TRANS_BLOCKS (4*576 + 2304 + 2304)   /* 6912 */

__global__ void transpose_all_kernel(const float* s0, __half* d0,
                                     const float* s1, __half* d1,
                                     const float* s2, __half* d2,
                                     const float* s3, __half* d3,
                                     const float* s4, __half* d4,
                                     const float* s5, __half* d5)
{
    __shared__ float t[32][33];
    const float* in; __half* outp;
    int K, N, n0, k0;
    int bid = blockIdx.x;
    if (bid < 2304) {
        int seg = bid / 576, r = bid % 576;
        switch (seg) {
            case 0: in = s0; outp = d0; break;
            case 1: in = s1; outp = d1; break;
            case 2: in = s2; outp = d2; break;
            default: in = s3; outp = d3; break;
        }
        K = N_EMBD; N = N_EMBD;
        n0 = (r % 24) * 32; k0 = (r / 24) * 32;
    } else if (bid < 4608) {
        int r = bid - 2304;
        in = s4; outp = d4; K = N_EMBD; N = FFDIM;
        n0 = (r % 96) * 32; k0 = (r / 96) * 32;
    } else {
        int r = bid - 4608;
        in = s5; outp = d5; K = FFDIM; N = N_EMBD;
        n0 = (r % 24) * 32; k0 = (r / 24) * 32;
    }

    int tx = threadIdx.x, ty = threadIdx.y;
    #pragma unroll
    for (int dy = 0; dy < 32; dy += 8)
        t[ty + dy][tx] = in[(size_t)(k0 + ty + dy) * N + n0 + tx];
    __syncthreads();
    #pragma unroll
    for (int dy = 0; dy < 32; dy += 8)
        outp[(size_t)(n0 + ty + dy) * K + k0 + tx] = __float2half(t[tx][ty + dy]);
}

/* ------------------------- FP16 WMMA GEMM (BM=128) ----------------- */
#define HSTR 72                        /* halfs per row (64+8) */
#define TILE128_H (128 * HSTR)         /* 9216 halfs */
#define TILE128_B (TILE128_H * 2)      /* 18432 bytes */
#define SMEM_G128 (4 * TILE128_B)      /* 73728 B */
#define ESTR 136                       /* epilogue stage stride (floats) */

template<int MODE, int OUTH>
__global__ __launch_bounds__(256, 2)
void gemm_fp16(const __half* __restrict__ A, const __half* __restrict__ BT,
               const float* __restrict__ bias, const float* __restrict__ resid,
               float* __restrict__ outf, __half* __restrict__ outh,
               int M, int N, int K)
{
    extern __shared__ __align__(16) unsigned char smem_raw[];
    __half* As = (__half*)smem_raw;                        /* [2][128][72] */
    __half* Bs = (__half*)(smem_raw + 2 * TILE128_B);      /* [2][128][72] */
    const uint32_t asu = (uint32_t)__cvta_generic_to_shared(As);
    const uint32_t bsu = (uint32_t)__cvta_generic_to_shared(Bs);

    const int tid  = threadIdx.x;
    const int warp = tid >> 5;
    const int m0 = blockIdx.y * 128, n0 = blockIdx.x * 128;
    const int wm = (warp >> 2) * 64;
    const int wn = (warp & 3) * 32;

    wmma::fragment<wmma::accumulator, 16, 16, 16, float> acc[4][2];
    #pragma unroll
    for (int mi = 0; mi < 4; mi++)
        #pragma unroll
        for (int ni = 0; ni < 2; ni++)
            wmma::fill_fragment(acc[mi][ni], 0.f);

    const int nk = K >> 6;

    auto load_tile = [&](int ck, int s) {
        const __half* Ab = A  + (size_t)m0 * K + ck * 64;
        const __half* Bb = BT + (size_t)n0 * K + ck * 64;
        #pragma unroll
        for (int i = 0; i < 4; i++) {
            int c = tid + i * 256;
            int r = c >> 3, col = (c & 7) * 8;
            cp_async16(asu + (uint32_t)(s * TILE128_B + (r * HSTR + col) * 2),
                       Ab + (size_t)r * K + col);
        }
        #pragma unroll
        for (int i = 0; i < 4; i++) {
            int c = tid + i * 256;
            int r = c >> 3, col = (c & 7) * 8;
            cp_async16(bsu + (uint32_t)(s * TILE128_B + (r * HSTR + col) * 2),
                       Bb + (size_t)r * K + col);
        }
    };

    load_tile(0, 0); cp_commit();
    if (nk > 1) { load_tile(1, 1); cp_commit(); }

    for (int it = 0; it < nk; it++) {
        int s = it & 1;
        if (it + 1 < nk) cp_wait1(); else cp_wait0();
        __syncthreads();

        const __half* Acur = As + s * TILE128_H;
        const __half* Bcur = Bs + s * TILE128_H;

        #pragma unroll
        for (int kk = 0; kk < 64; kk += 16) {
            wmma::fragment<wmma::matrix_a, 16, 16, 16, __half, wmma::row_major> af[4];
            wmma::fragment<wmma::matrix_b, 16, 16, 16, __half, wmma::col_major> bf[2];
            #pragma unroll
            for (int mi = 0; mi < 4; mi++)
                wmma::load_matrix_sync(af[mi], Acur + (wm + mi*16) * HSTR + kk, HSTR);
            #pragma unroll
            for (int ni = 0; ni < 2; ni++)
                wmma::load_matrix_sync(bf[ni], Bcur + (wn + ni*16) * HSTR + kk, HSTR);
            #pragma unroll
            for (int mi = 0; mi < 4; mi++)
                #pragma unroll
                for (int ni = 0; ni < 2; ni++)
                    wmma::mma_sync(acc[mi][ni], af[mi], bf[ni], acc[mi][ni]);
        }
        __syncthreads();
        if (it + 2 < nk) { load_tile(it + 2, s); cp_commit(); }
    }

    /* epilogue: stage whole 128x128 fp32 tile, then coalesced stores */
    float* stage = (float*)smem_raw;    /* 128 x ESTR = 69632 B */
    #pragma unroll
    for (int mi = 0; mi < 4; mi++)
        #pragma unroll
        for (int ni = 0; ni < 2; ni++)
            wmma::store_matrix_sync(stage + (wm + mi*16) * ESTR + wn + ni*16,
                                    acc[mi][ni], ESTR, wmma::mem_row_major);
    __syncthreads();

    #pragma unroll
    for (int i = 0; i < 16; i++) {
        int idx = tid + i * 256;           /* 4096 float4 slots */
        int r = idx >> 5, c4 = idx & 31;
        int col = c4 * 4;
        float4 v = *(float4*)&stage[r * ESTR + col];
        int gr = m0 + r, gc = n0 + col;
        if (MODE >= 1) {
            float4 b = *(const float4*)&bias[gc];
            v.x += b.x; v.y += b.y; v.z += b.z; v.w += b.w;
        }
        if (MODE == 1) {
            float4 rr = *(const float4*)&resid[(size_t)gr * N + gc];
            v.x += rr.x; v.y += rr.y; v.z += rr.z; v.w += rr.w;
        }
        if (MODE == 2) {
            v.x = gelu_tanh(v.x); v.y = gelu_tanh(v.y);
            v.z = gelu_tanh(v.z); v.w = gelu_tanh(v.w);
        }
        if (OUTH)
            *(uint2*)&outh[(size_t)gr * N + gc] = pack_h4(v.x, v.y, v.z, v.w);
        else
            *(float4*)&outf[(size_t)gr * N + gc] = v;
    }
}

/* ------------------------- FP16 WMMA GEMM (BM=64) ------------------ */
#define TILE64A_H (64 * HSTR)          /* 4608 halfs */
#define TILE64A_B (TILE64A_H * 2)      /* 9216 bytes */
#define SMEM_G64  (2 * TILE64A_B + 2 * TILE128_B)  /* 55296 B */

template<int MODE, int OUTH>
__global__ __launch_bounds__(256, 3)
void gemm_fp16_s(const __half* __restrict__ A, const __half* __restrict__ BT,
                 const float* __restrict__ bias, const float* __restrict__ resid,
                 float* __restrict__ outf, __half* __restrict__ outh,
                 int M, int N, int K)
{
    extern __shared__ __align__(16) unsigned char smem_raw[];
    __half* As = (__half*)smem_raw;                        /* [2][64][72]  */
    __half* Bs = (__half*)(smem_raw + 2 * TILE64A_B);      /* [2][128][72] */
    const uint32_t asu = (uint32_t)__cvta_generic_to_shared(As);
    const uint32_t bsu = (uint32_t)__cvta_generic_to_shared(Bs);

    const int tid  = threadIdx.x;
    const int warp = tid >> 5;
    const int m0 = blockIdx.y * 64, n0 = blockIdx.x * 128;
    const int wm = (warp >> 2) * 32;     /* 0 / 32  */
    const int wn = (warp & 3) * 32;      /* 0..96   */

    wmma::fragment<wmma::accumulator, 16, 16, 16, float> acc[2][2];
    #pragma unroll
    for (int mi = 0; mi < 2; mi++)
        #pragma unroll
        for (int ni = 0; ni < 2; ni++)
            wmma::fill_fragment(acc[mi][ni], 0.f);

    const int nk = K >> 6;

    auto load_tile = [&](int ck, int s) {
        const __half* Ab = A  + (size_t)m0 * K + ck * 64;
        const __half* Bb = BT + (size_t)n0 * K + ck * 64;
        #pragma unroll
        for (int i = 0; i < 2; i++) {
            int c = tid + i * 256;
            int r = c >> 3, col = (c & 7) * 8;
            cp_async16(asu + (uint32_t)(s * TILE64A_B + (r * HSTR + col) * 2),
                       Ab + (size_t)r * K + col);
        }
        #pragma unroll
        for (int i = 0; i < 4; i++) {
            int c = tid + i * 256;
            int r = c >> 3, col = (c & 7) * 8;
            cp_async16(bsu + (uint32_t)(s * TILE128_B + (r * HSTR + col) * 2),
                       Bb + (size_t)r * K + col);
        }
    };

    load_tile(0, 0); cp_commit();
    if (nk > 1) { load_tile(1, 1); cp_commit(); }

    for (int it = 0; it < nk; it++) {
        int s = it & 1;
        if (it + 1 < nk) cp_wait1(); else cp_wait0();
        __syncthreads();

        const __half* Acur = As + s * TILE64A_H;
        const __half* Bcur = Bs + s * TILE128_H;

        #pragma unroll
        for (int kk = 0; kk < 64; kk += 16) {
            wmma::fragment<wmma::matrix_a, 16, 16, 16, __half, wmma::row_major> af[2];
            wmma::fragment<wmma::matrix_b, 16, 16, 16, __half, wmma::col_major> bf[2];
            #pragma unroll
            for (int mi = 0; mi < 2; mi++)
                wmma::load_matrix_sync(af[mi], Acur + (wm + mi*16) * HSTR + kk, HSTR);
            #pragma unroll
            for (int ni = 0; ni < 2; ni++)
                wmma::load_matrix_sync(bf[ni], Bcur + (wn + ni*16) * HSTR + kk, HSTR);
            #pragma unroll
            for (int mi = 0; mi < 2; mi++)
                #pragma unroll
                for (int ni = 0; ni < 2; ni++)
                    wmma::mma_sync(acc[mi][ni], af[mi], bf[ni], acc[mi][ni]);
        }
        __syncthreads();
        if (it + 2 < nk) { load_tile(it + 2, s); cp_commit(); }
    }

    /* epilogue: stage 64x128 fp32 tile, then coalesced stores */
    float* stage = (float*)smem_raw;    /* 64 x ESTR = 34816 B */
    #pragma unroll
    for (int mi = 0; mi < 2; mi++)
        #pragma unroll
        for (int ni = 0; ni < 2; ni++)
            wmma::store_matrix_sync(stage + (wm + mi*16) * ESTR + wn + ni*16,
                                    acc[mi][ni], ESTR, wmma::mem_row_major);
    __syncthreads();

    #pragma unroll
    for (int i = 0; i < 8; i++) {
        int idx = tid + i * 256;           /* 2048 float4 slots */
        int r = idx >> 5, c4 = idx & 31;
        int col = c4 * 4;
        float4 v = *(float4*)&stage[r * ESTR + col];
        int gr = m0 + r, gc = n0 + col;
        if (MODE >= 1) {
            float4 b = *(const float4*)&bias[gc];
            v.x += b.x; v.y += b.y; v.z += b.z; v.w += b.w;
        }
        if (MODE == 1) {
            float4 rr = *(const float4*)&resid[(size_t)gr * N + gc];
            v.x += rr.x; v.y += rr.y; v.z += rr.z; v.w += rr.w;
        }
        if (MODE == 2) {
            v.x = gelu_tanh(v.x); v.y = gelu_tanh(v.y);
            v.z = gelu_tanh(v.z); v.w = gelu_tanh(v.w);
        }
        if (OUTH)
            *(uint2*)&outh[(size_t)gr * N + gc] = pack_h4(v.x, v.y, v.z, v.w);
        else
            *(float4*)&outf[(size_t)gr * N + gc] = v;
    }
}

/* ------------- tensor-core sliding-window (64) attention ----------- */
/* smem plan (62464 B, 3 CTA/SM):
   phase 1: Qs @ 0 (64x72h, 9216B) | Ks @ 9216 (128x72h, 18432B)
   phase 2: Vs @ 0 (128x72h, 18432B) — overwrites Q/K after S-MMA
   Sf @ 27648 (64x136 f32, 34816B); Ph overlays Sf; O stage overlays Sf */
#define AQ_OFF 0
#define AK_OFF 9216
#define AV_OFF 0
#define AS_OFF 27648
#define ATT_SMEM (AS_OFF + 64*136*4)   /* 62464 B */

__global__ __launch_bounds__(256)
void attn_wmma(const __half* __restrict__ QKV, __half* __restrict__ O)
{
    extern __shared__ __align__(16) unsigned char smem[];
    __half* Qs = (__half*)(smem + AQ_OFF);   /* ld 72 */
    __half* Ks = (__half*)(smem + AK_OFF);   /* ld 72 */
    __half* Vs = (__half*)(smem + AV_OFF);   /* ld 72 (phase 2) */
    float*  Sf = (float*)(smem + AS_OFF);    /* ld 136 */
    __half* Ph = (__half*)(smem + AS_OFF);   /* ld 272 */
    const uint32_t squ = (uint32_t)__cvta_generic_to_shared(smem);

    const int tid = threadIdx.x, warp = tid >> 5, lane = tid & 31;
    const int b = blockIdx.z, h = blockIdx.y;
    const int t0 = blockIdx.x * 64;
    const int hc = h * HS;

    /* ---- phase 1 loads: Q + K ---- */
    #pragma unroll
    for (int i = 0; i < 2; i++) {
        int c = tid + i * 256;
        int r = c >> 3, col = (c & 7) * 8;
        cp_async16(squ + AQ_OFF + (uint32_t)(r * 144 + col * 2),
                   QKV + ((size_t)(b * TSEQ + t0 + r)) * QKVD + hc + col);
    }
    #pragma unroll
    for (int i = 0; i < 4; i++) {
        int c = tid + i * 256;
        int r = c >> 3, col = (c & 7) * 8;
        int s = t0 - 63 + r;
        int ok = (s >= 0 && s < TSEQ) ? 16 : 0;
        int sc = s < 0 ? 0 : (s >= TSEQ ? TSEQ - 1 : s);
        cp_async16z(squ + AK_OFF + (uint32_t)(r * 144 + col * 2),
                    QKV + ((size_t)(b * TSEQ + sc)) * QKVD + N_EMBD + hc + col, ok);
    }
    cp_commit();
    cp_wait0();
    __syncthreads();

    /* ---- S = Q @ Kext^T ---- */
    {
        const int mb = warp & 3, nb0 = (warp >> 2) * 4;
        wmma::fragment<wmma::accumulator, 16, 16, 16, float> sa[4];
        #pragma unroll
        for (int t = 0; t < 4; t++) wmma::fill_fragment(sa[t], 0.f);
        #pragma unroll
        for (int k = 0; k < 4; k++) {
            wmma::fragment<wmma::matrix_a, 16, 16, 16, __half, wmma::row_major> af;
            wmma::load_matrix_sync(af, Qs + mb * 16 * 72 + k * 16, 72);
            #pragma unroll
            for (int t = 0; t < 4; t++) {
                wmma::fragment<wmma::matrix_b, 16, 16, 16, __half, wmma::col_major> bf;
                wmma::load_matrix_sync(bf, Ks + (nb0 + t) * 16 * 72 + k * 16, 72);
                wmma::mma_sync(sa[t], af, bf, sa[t]);
            }
        }
        #pragma unroll
        for (int t = 0; t < 4; t++)
            wmma::store_matrix_sync(Sf + mb * 16 * 136 + (nb0 + t) * 16, sa[t],
                                    136, wmma::mem_row_major);
    }
    __syncthreads();   /* Q/K dead; Sf live */

    /* ---- issue V loads into the (free) Q/K region ---- */
    #pragma unroll
    for (int i = 0; i < 4; i++) {
        int c = tid + i * 256;
        int r = c >> 3, col = (c & 7) * 8;
        int s = t0 - 63 + r;
        int ok = (s >= 0 && s < TSEQ) ? 16 : 0;
        int sc = s < 0 ? 0 : (s >= TSEQ ? TSEQ - 1 : s);
        cp_async16z(squ + AV_OFF + (uint32_t)(r * 144 + col * 2),
                    QKV + ((size_t)(b * TSEQ + sc)) * QKVD + 2*N_EMBD + hc + col, ok);
    }
    cp_commit();

    /* ---- masked softmax while V streams in; P (half) in place ---- */
    {
        for (int r = warp * 8; r < warp * 8 + 8; r++) {
            float vals[4];
            #pragma unroll
            for (int q = 0; q < 4; q++) {
                int j = lane + q * 32;
                float v = Sf[r * 136 + j] * 0.125f;
                bool valid = (j >= r) && (j <= r + 63) && (t0 - 63 + j >= 0);
                vals[q] = valid ? v : -1e30f;
            }
            float mx = fmaxf(fmaxf(vals[0], vals[1]), fmaxf(vals[2], vals[3]));
            #pragma unroll
            for (int o = 16; o; o >>= 1) mx = fmaxf(mx, __shfl_xor_sync(0xffffffffu, mx, o));
            float e[4], sum = 0.f;
            #pragma unroll
            for (int q = 0; q < 4; q++) { e[q] = __expf(vals[q] - mx); sum += e[q]; }
            #pragma unroll
            for (int o = 16; o; o >>= 1) sum += __shfl_xor_sync(0xffffffffu, sum, o);
            float inv = 1.f / sum;
            #pragma unroll
            for (int q = 0; q < 4; q++)
                Ph[r * 272 + lane + q * 32] = __float2half(e[q] * inv);
        }
    }
    cp_wait0();        /* V resident */
    __syncthreads();   /* Ph visible to all warps */

    /* ---- O = P @ V ---- */
    {
        const int mb = warp & 3, nb0 = (warp >> 2) * 2;
        wmma::fragment<wmma::accumulator, 16, 16, 16, float> oa[2];
        #pragma unroll
        for (int t = 0; t < 2; t++) wmma::fill_fragment(oa[t], 0.f);
        #pragma unroll
        for (int k = 0; k < 8; k++) {
            wmma::fragment<wmma::matrix_a, 16, 16, 16, __half, wmma::row_major> af;
            wmma::load_matrix_sync(af, Ph + mb * 16 * 272 + k * 16, 272);
            #pragma unroll
            for (int t = 0; t < 2; t++) {
                wmma::fragment<wmma::matrix_b, 16, 16, 16, __half, wmma::row_major> bf;
                wmma::load_matrix_sync(bf, Vs + k * 16 * 72 + (nb0 + t) * 16, 72);
                wmma::mma_sync(oa[t], af, bf, oa[t]);
            }
        }
        __syncthreads();   /* everyone done reading Ph */
        float* OS = (float*)(smem + AS_OFF);   /* 64 x 72 fp32 stage */
        #pragma unroll
        for (int t = 0; t < 2; t++)
            wmma::store_matrix_sync(OS + (mb * 16) * 72 + (nb0 + t) * 16,
                                    oa[t], 72, wmma::mem_row_major);
        __syncthreads();
        #pragma unroll
        for (int i = 0; i < 4; i++) {
            int idx = tid + i * 256;           /* 1024 float4 slots */
            int r = idx >> 4, c4 = idx & 15;
            int col = c4 * 4;
            float4 v = *(float4*)&OS[r * 72 + col];
            *(uint2*)&O[((size_t)(b * TSEQ + t0 + r)) * N_EMBD + hc + col] =
                pack_h4(v.x, v.y, v.z, v.w);
        }
    }
}

/* --------------------------- tail zero ----------------------------- */
__global__ void tail_kernel(float* out, int start, int total)
{
    int i = start + blockIdx.x * blockDim.x + threadIdx.x;
    if (i < total) out[i] = 0.f;
}

/* --------------------------- launcher ------------------------------ */
extern "C" void kernel_launch(void* const* d_in, const int* in_sizes, int n_in,
                              void* d_out, int out_size)
{
    const float* x      = (const float*)d_in[0];
    const float* w_q    = (const float*)d_in[1];
    const float* w_k    = (const float*)d_in[2];
    const float* w_v    = (const float*)d_in[3];
    const float* w_proj = (const float*)d_in[4];
    const float* b_proj = (const float*)d_in[5];
    const float* w_ff1  = (const float*)d_in[6];
    const float* b_ff1  = (const float*)d_in[7];
    const float* w_ff2  = (const float*)d_in[8];
    const float* b_ff2  = (const float*)d_in[9];
    const float* g1     = (const float*)d_in[10];
    const float* g2     = (const float*)d_in[11];
    float* out = (float*)d_out;

    float *x1;
    __half *qkvh, *h1h, *atth, *h2h, *ffhh, *wqkv, *wtp, *wt1, *wt2;
    { void* p;
      cudaGetSymbolAddress(&p, g_x1);   x1   = (float*)p;
      cudaGetSymbolAddress(&p, g_qkvh); qkvh = (__half*)p;
      cudaGetSymbolAddress(&p, g_h1h);  h1h  = (__half*)p;
      cudaGetSymbolAddress(&p, g_atth); atth = (__half*)p;
      cudaGetSymbolAddress(&p, g_h2h);  h2h  = (__half*)p;
      cudaGetSymbolAddress(&p, g_ffhh); ffhh = (__half*)p;
      cudaGetSymbolAddress(&p, g_wqkv); wqkv = (__half*)p;
      cudaGetSymbolAddress(&p, g_wtp);  wtp  = (__half*)p;
      cudaGetSymbolAddress(&p, g_wt1);  wt1  = (__half*)p;
      cudaGetSymbolAddress(&p, g_wt2);  wt2  = (__half*)p;
    }

    cudaFuncSetAttribute(attn_wmma,
                         cudaFuncAttributeMaxDynamicSharedMemorySize, ATT_SMEM);
    cudaFuncSetAttribute(gemm_fp16<0,1>,
                         cudaFuncAttributeMaxDynamicSharedMemorySize, SMEM_G128);
    cudaFuncSetAttribute(gemm_fp16_s<1,0>,
                         cudaFuncAttributeMaxDynamicSharedMemorySize, SMEM_G64);
    cudaFuncSetAttribute(gemm_fp16_s<2,1>,
                         cudaFuncAttributeMaxDynamicSharedMemorySize, SMEM_G64);

    /* 0. transpose all weights to half [N,K] in ONE launch */
    {
        dim3 blk(32, 8);
        transpose_all_kernel<<<TRANS_BLOCKS, blk>>>(
            w_q, wqkv,
            w_k, wqkv + N_EMBD*N_EMBD,
            w_v, wqkv + 2*N_EMBD*N_EMBD,
            w_proj, wtp,
            w_ff1, wt1,
            w_ff2, wt2);
    }

    /* 1. rmsnorm(x)*g1 -> half (warp per row) */
    rmsnorm_h_kernel<<<MROWS/8, 256>>>(x, g1, h1h);

    /* 2. fused QKV GEMM -> half (BM=128) */
    dim3 gqkv(QKVD / 128, MROWS / 128);
    gemm_fp16<0,1><<<gqkv, 256, SMEM_G128>>>(h1h, wqkv, nullptr, nullptr,
                                             nullptr, qkvh, MROWS, QKVD, N_EMBD);

    /* 3. tensor-core sliding-window attention -> half */
    dim3 ga(TSEQ / 64, NHEAD, BATCH);
    attn_wmma<<<ga, 256, ATT_SMEM>>>(qkvh, atth);

    /* 4. proj: x1 = x + att @ w_proj + b_proj (BM=64) */
    dim3 gp(N_EMBD / 128, MROWS / 64);
    gemm_fp16_s<1,0><<<gp, 256, SMEM_G64>>>(atth, wtp, b_proj, x,
                                            x1, nullptr, MROWS, N_EMBD, N_EMBD);

    /* 5. rmsnorm(x1)*g2 -> half (warp per row) */
    rmsnorm_h_kernel<<<MROWS/8, 256>>>(x1, g2, h2h);

    /* 6. ff1: gelu(h2 @ w_ff1 + b_ff1) -> half (BM=64) */
    dim3 gff1(FFDIM / 128, MROWS / 64);
    gemm_fp16_s<2,1><<<gff1, 256, SMEM_G64>>>(h2h, wt1, b_ff1, nullptr,
                                              nullptr, ffhh, MROWS, FFDIM, N_EMBD);

    /* 7. ff2: out = x1 + ffh @ w_ff2 + b_ff2 (BM=64) */
    gemm_fp16_s<1,0><<<gp, 256, SMEM_G64>>>(ffhh, wt2, b_ff2, x1,
                                            out, nullptr, MROWS, N_EMBD, FFDIM);

    /* 8. aux / tail */
    const int TOT = MROWS * N_EMBD;
    if (out_size > TOT) {
        int rem = out_size - TOT;
        tail_kernel<<<(rem + 255) / 256, 256>>>(out, TOT, out_size);
    }
}

// round 13
// speedup vs baseline: 4.4997x; 1.0039x over previous
#include <cstdint>
#include <cuda_runtime.h>
#include <cuda_fp16.h>
#include <mma.h>

using namespace nvcuda;

#define N_EMBD 768
#define NHEAD  12
#define HS     64
#define TSEQ   1024
#define BATCH  8
#define MROWS  (BATCH*TSEQ)     /* 8192 */
#define FFDIM  (4*N_EMBD)       /* 3072 */
#define QKVD   (3*N_EMBD)       /* 2304 */
#define WINDOW 64

/* -------- scratch (no allocation allowed -> device globals) -------- */
__device__ float  g_x1  [MROWS*N_EMBD];
__device__ __half g_qkvh[MROWS*QKVD];
__device__ __half g_h1h [MROWS*N_EMBD];
__device__ __half g_atth[MROWS*N_EMBD];
__device__ __half g_h2h [MROWS*N_EMBD];
__device__ __half g_ffhh[MROWS*FFDIM];
__device__ __half g_wqkv[QKVD*N_EMBD];
__device__ __half g_wtp [N_EMBD*N_EMBD];
__device__ __half g_wt1 [FFDIM*N_EMBD];
__device__ __half g_wt2 [N_EMBD*FFDIM];

/* --------------------- cp.async helpers ---------------------------- */
__device__ __forceinline__ void cp_async16(uint32_t dst, const void* src)
{
    asm volatile("cp.async.cg.shared.global [%0], [%1], 16;\n" :: "r"(dst), "l"(src));
}
__device__ __forceinline__ void cp_async16z(uint32_t dst, const void* src, int src_sz)
{
    asm volatile("cp.async.cg.shared.global [%0], [%1], 16, %2;\n"
                 :: "r"(dst), "l"(src), "r"(src_sz));
}
__device__ __forceinline__ void cp_commit()
{
    asm volatile("cp.async.commit_group;\n");
}
__device__ __forceinline__ void cp_wait1()
{
    asm volatile("cp.async.wait_group 1;\n");
}
__device__ __forceinline__ void cp_wait0()
{
    asm volatile("cp.async.wait_group 0;\n");
}

__device__ __forceinline__ float gelu_tanh(float v)
{
    const float c = 0.7978845608028654f;
    return 0.5f * v * (1.f + tanhf(c * (v + 0.044715f * v * v * v)));
}

/* pack 4 floats -> 4 halfs (8B) */
__device__ __forceinline__ uint2 pack_h4(float a, float b, float c, float d)
{
    __half2 lo = __floats2half2_rn(a, b);
    __half2 hi = __floats2half2_rn(c, d);
    uint2 r;
    r.x = *(uint32_t*)&lo;
    r.y = *(uint32_t*)&hi;
    return r;
}

/* ---------------- RMSNorm: one warp per row, x in registers -------- */
__global__ __launch_bounds__(256)
void rmsnorm_h_kernel(const float* __restrict__ x,
                      const float* __restrict__ g,
                      __half* __restrict__ out)
{
    const int row  = blockIdx.x * 8 + (threadIdx.x >> 5);
    const int lane = threadIdx.x & 31;
    const float4* xr = (const float4*)(x + (size_t)row * N_EMBD);
    const float4* gr = (const float4*)g;

    float4 v[6];
    float ss = 0.f;
    #pragma unroll
    for (int k = 0; k < 6; k++) {
        v[k] = xr[lane + 32 * k];
        ss += v[k].x*v[k].x + v[k].y*v[k].y + v[k].z*v[k].z + v[k].w*v[k].w;
    }
    #pragma unroll
    for (int o = 16; o; o >>= 1) ss += __shfl_xor_sync(0xffffffffu, ss, o);
    const float r = rsqrtf(ss * (1.0f / N_EMBD) + 1e-6f);

    __half2* o2 = (__half2*)(out + (size_t)row * N_EMBD);
    #pragma unroll
    for (int k = 0; k < 6; k++) {
        float4 gv = gr[lane + 32 * k];
        int i = lane + 32 * k;
        o2[i*2]   = __floats2half2_rn(v[k].x * r * gv.x, v[k].y * r * gv.y);
        o2[i*2+1] = __floats2half2_rn(v[k].z * r * gv.z, v[k].w * r * gv.w);
    }
}

/* ------------- merged weight transpose (f32 -> half), 1 launch ----- */
#define TRANS_BLOCKS (4*576 + 2304 + 2304)   /* 6912 */

__global__ void transpose_all_kernel(const float* s0, __half* d0,
                                     const float* s1, __half* d1,
                                     const float* s2, __half* d2,
                                     const float* s3, __half* d3,
                                     const float* s4, __half* d4,
                                     const float* s5, __half* d5)
{
    __shared__ float t[32][33];
    const float* in; __half* outp;
    int K, N, n0, k0;
    int bid = blockIdx.x;
    if (bid < 2304) {
        int seg = bid / 576, r = bid % 576;
        switch (seg) {
            case 0: in = s0; outp = d0; break;
            case 1: in = s1; outp = d1; break;
            case 2: in = s2; outp = d2; break;
            default: in = s3; outp = d3; break;
        }
        K = N_EMBD; N = N_EMBD;
        n0 = (r % 24) * 32; k0 = (r / 24) * 32;
    } else if (bid < 4608) {
        int r = bid - 2304;
        in = s4; outp = d4; K = N_EMBD; N = FFDIM;
        n0 = (r % 96) * 32; k0 = (r / 96) * 32;
    } else {
        int r = bid - 4608;
        in = s5; outp = d5; K = FFDIM; N = N_EMBD;
        n0 = (r % 24) * 32; k0 = (r / 24) * 32;
    }

    int tx = threadIdx.x, ty = threadIdx.y;
    #pragma unroll
    for (int dy = 0; dy < 32; dy += 8)
        t[ty + dy][tx] = in[(size_t)(k0 + ty + dy) * N + n0 + tx];
    __syncthreads();
    #pragma unroll
    for (int dy = 0; dy < 32; dy += 8)
        outp[(size_t)(n0 + ty + dy) * K + k0 + tx] = __float2half(t[tx][ty + dy]);
}

/* ------------------------- FP16 WMMA GEMM (BM=128) ----------------- */
#define HSTR 72                        /* halfs per row (64+8) */
#define TILE128_H (128 * HSTR)         /* 9216 halfs */
#define TILE128_B (TILE128_H * 2)      /* 18432 bytes */
#define SMEM_G128 (4 * TILE128_B)      /* 73728 B */
#define ESTR 136                       /* epilogue stage stride (floats) */

template<int MODE, int OUTH>
__global__ __launch_bounds__(256, 2)
void gemm_fp16(const __half* __restrict__ A, const __half* __restrict__ BT,
               const float* __restrict__ bias, const float* __restrict__ resid,
               float* __restrict__ outf, __half* __restrict__ outh,
               int M, int N, int K)
{
    extern __shared__ __align__(16) unsigned char smem_raw[];
    __half* As = (__half*)smem_raw;                        /* [2][128][72] */
    __half* Bs = (__half*)(smem_raw + 2 * TILE128_B);      /* [2][128][72] */
    const uint32_t asu = (uint32_t)__cvta_generic_to_shared(As);
    const uint32_t bsu = (uint32_t)__cvta_generic_to_shared(Bs);

    const int tid  = threadIdx.x;
    const int warp = tid >> 5;
    const int m0 = blockIdx.y * 128, n0 = blockIdx.x * 128;
    const int wm = (warp >> 2) * 64;
    const int wn = (warp & 3) * 32;

    wmma::fragment<wmma::accumulator, 16, 16, 16, float> acc[4][2];
    #pragma unroll
    for (int mi = 0; mi < 4; mi++)
        #pragma unroll
        for (int ni = 0; ni < 2; ni++)
            wmma::fill_fragment(acc[mi][ni], 0.f);

    const int nk = K >> 6;

    auto load_tile = [&](int ck, int s) {
        const __half* Ab = A  + (size_t)m0 * K + ck * 64;
        const __half* Bb = BT + (size_t)n0 * K + ck * 64;
        #pragma unroll
        for (int i = 0; i < 4; i++) {
            int c = tid + i * 256;
            int r = c >> 3, col = (c & 7) * 8;
            cp_async16(asu + (uint32_t)(s * TILE128_B + (r * HSTR + col) * 2),
                       Ab + (size_t)r * K + col);
        }
        #pragma unroll
        for (int i = 0; i < 4; i++) {
            int c = tid + i * 256;
            int r = c >> 3, col = (c & 7) * 8;
            cp_async16(bsu + (uint32_t)(s * TILE128_B + (r * HSTR + col) * 2),
                       Bb + (size_t)r * K + col);
        }
    };

    load_tile(0, 0); cp_commit();
    if (nk > 1) { load_tile(1, 1); cp_commit(); }

    for (int it = 0; it < nk; it++) {
        int s = it & 1;
        if (it + 1 < nk) cp_wait1(); else cp_wait0();
        __syncthreads();

        const __half* Acur = As + s * TILE128_H;
        const __half* Bcur = Bs + s * TILE128_H;

        #pragma unroll
        for (int kk = 0; kk < 64; kk += 16) {
            wmma::fragment<wmma::matrix_a, 16, 16, 16, __half, wmma::row_major> af[4];
            wmma::fragment<wmma::matrix_b, 16, 16, 16, __half, wmma::col_major> bf[2];
            #pragma unroll
            for (int mi = 0; mi < 4; mi++)
                wmma::load_matrix_sync(af[mi], Acur + (wm + mi*16) * HSTR + kk, HSTR);
            #pragma unroll
            for (int ni = 0; ni < 2; ni++)
                wmma::load_matrix_sync(bf[ni], Bcur + (wn + ni*16) * HSTR + kk, HSTR);
            #pragma unroll
            for (int mi = 0; mi < 4; mi++)
                #pragma unroll
                for (int ni = 0; ni < 2; ni++)
                    wmma::mma_sync(acc[mi][ni], af[mi], bf[ni], acc[mi][ni]);
        }
        __syncthreads();
        if (it + 2 < nk) { load_tile(it + 2, s); cp_commit(); }
    }

    /* epilogue: stage whole 128x128 fp32 tile, then coalesced stores */
    float* stage = (float*)smem_raw;    /* 128 x ESTR = 69632 B */
    #pragma unroll
    for (int mi = 0; mi < 4; mi++)
        #pragma unroll
        for (int ni = 0; ni < 2; ni++)
            wmma::store_matrix_sync(stage + (wm + mi*16) * ESTR + wn + ni*16,
                                    acc[mi][ni], ESTR, wmma::mem_row_major);
    __syncthreads();

    #pragma unroll
    for (int i = 0; i < 16; i++) {
        int idx = tid + i * 256;           /* 4096 float4 slots */
        int r = idx >> 5, c4 = idx & 31;
        int col = c4 * 4;
        float4 v = *(float4*)&stage[r * ESTR + col];
        int gr = m0 + r, gc = n0 + col;
        if (MODE >= 1) {
            float4 b = *(const float4*)&bias[gc];
            v.x += b.x; v.y += b.y; v.z += b.z; v.w += b.w;
        }
        if (MODE == 1) {
            float4 rr = *(const float4*)&resid[(size_t)gr * N + gc];
            v.x += rr.x; v.y += rr.y; v.z += rr.z; v.w += rr.w;
        }
        if (MODE == 2) {
            v.x = gelu_tanh(v.x); v.y = gelu_tanh(v.y);
            v.z = gelu_tanh(v.z); v.w = gelu_tanh(v.w);
        }
        if (OUTH)
            *(uint2*)&outh[(size_t)gr * N + gc] = pack_h4(v.x, v.y, v.z, v.w);
        else
            *(float4*)&outf[(size_t)gr * N + gc] = v;
    }
}

/* ------------------------- FP16 WMMA GEMM (BM=64) ------------------ */
#define TILE64A_H (64 * HSTR)          /* 4608 halfs */
#define TILE64A_B (TILE64A_H * 2)      /* 9216 bytes */
#define SMEM_G64  (2 * TILE64A_B + 2 * TILE128_B)  /* 55296 B */

template<int MODE, int OUTH>
__global__ __launch_bounds__(256, 3)
void gemm_fp16_s(const __half* __restrict__ A, const __half* __restrict__ BT,
                 const float* __restrict__ bias, const float* __restrict__ resid,
                 float* __restrict__ outf, __half* __restrict__ outh,
                 int M, int N, int K)
{
    extern __shared__ __align__(16) unsigned char smem_raw[];
    __half* As = (__half*)smem_raw;                        /* [2][64][72]  */
    __half* Bs = (__half*)(smem_raw + 2 * TILE64A_B);      /* [2][128][72] */
    const uint32_t asu = (uint32_t)__cvta_generic_to_shared(As);
    const uint32_t bsu = (uint32_t)__cvta_generic_to_shared(Bs);

    const int tid  = threadIdx.x;
    const int warp = tid >> 5;
    const int m0 = blockIdx.y * 64, n0 = blockIdx.x * 128;
    const int wm = (warp >> 2) * 32;     /* 0 / 32  */
    const int wn = (warp & 3) * 32;      /* 0..96   */

    wmma::fragment<wmma::accumulator, 16, 16, 16, float> acc[2][2];
    #pragma unroll
    for (int mi = 0; mi < 2; mi++)
        #pragma unroll
        for (int ni = 0; ni < 2; ni++)
            wmma::fill_fragment(acc[mi][ni], 0.f);

    const int nk = K >> 6;

    auto load_tile = [&](int ck, int s) {
        const __half* Ab = A  + (size_t)m0 * K + ck * 64;
        const __half* Bb = BT + (size_t)n0 * K + ck * 64;
        #pragma unroll
        for (int i = 0; i < 2; i++) {
            int c = tid + i * 256;
            int r = c >> 3, col = (c & 7) * 8;
            cp_async16(asu + (uint32_t)(s * TILE64A_B + (r * HSTR + col) * 2),
                       Ab + (size_t)r * K + col);
        }
        #pragma unroll
        for (int i = 0; i < 4; i++) {
            int c = tid + i * 256;
            int r = c >> 3, col = (c & 7) * 8;
            cp_async16(bsu + (uint32_t)(s * TILE128_B + (r * HSTR + col) * 2),
                       Bb + (size_t)r * K + col);
        }
    };

    load_tile(0, 0); cp_commit();
    if (nk > 1) { load_tile(1, 1); cp_commit(); }

    for (int it = 0; it < nk; it++) {
        int s = it & 1;
        if (it + 1 < nk) cp_wait1(); else cp_wait0();
        __syncthreads();

        const __half* Acur = As + s * TILE64A_H;
        const __half* Bcur = Bs + s * TILE128_H;

        #pragma unroll
        for (int kk = 0; kk < 64; kk += 16) {
            wmma::fragment<wmma::matrix_a, 16, 16, 16, __half, wmma::row_major> af[2];
            wmma::fragment<wmma::matrix_b, 16, 16, 16, __half, wmma::col_major> bf[2];
            #pragma unroll
            for (int mi = 0; mi < 2; mi++)
                wmma::load_matrix_sync(af[mi], Acur + (wm + mi*16) * HSTR + kk, HSTR);
            #pragma unroll
            for (int ni = 0; ni < 2; ni++)
                wmma::load_matrix_sync(bf[ni], Bcur + (wn + ni*16) * HSTR + kk, HSTR);
            #pragma unroll
            for (int mi = 0; mi < 2; mi++)
                #pragma unroll
                for (int ni = 0; ni < 2; ni++)
                    wmma::mma_sync(acc[mi][ni], af[mi], bf[ni], acc[mi][ni]);
        }
        __syncthreads();
        if (it + 2 < nk) { load_tile(it + 2, s); cp_commit(); }
    }

    /* epilogue: stage 64x128 fp32 tile, then coalesced stores */
    float* stage = (float*)smem_raw;    /* 64 x ESTR = 34816 B */
    #pragma unroll
    for (int mi = 0; mi < 2; mi++)
        #pragma unroll
        for (int ni = 0; ni < 2; ni++)
            wmma::store_matrix_sync(stage + (wm + mi*16) * ESTR + wn + ni*16,
                                    acc[mi][ni], ESTR, wmma::mem_row_major);
    __syncthreads();

    #pragma unroll
    for (int i = 0; i < 8; i++) {
        int idx = tid + i * 256;           /* 2048 float4 slots */
        int r = idx >> 5, c4 = idx & 31;
        int col = c4 * 4;
        float4 v = *(float4*)&stage[r * ESTR + col];
        int gr = m0 + r, gc = n0 + col;
        if (MODE >= 1) {
            float4 b = *(const float4*)&bias[gc];
            v.x += b.x; v.y += b.y; v.z += b.z; v.w += b.w;
        }
        if (MODE == 1) {
            float4 rr = *(const float4*)&resid[(size_t)gr * N + gc];
            v.x += rr.x; v.y += rr.y; v.z += rr.z; v.w += rr.w;
        }
        if (MODE == 2) {
            v.x = gelu_tanh(v.x); v.y = gelu_tanh(v.y);
            v.z = gelu_tanh(v.z); v.w = gelu_tanh(v.w);
        }
        if (OUTH)
            *(uint2*)&outh[(size_t)gr * N + gc] = pack_h4(v.x, v.y, v.z, v.w);
        else
            *(float4*)&outf[(size_t)gr * N + gc] = v;
    }
}

/* ------------- tensor-core sliding-window (64) attention ----------- */
/* smem plan (53248 B, 4 CTA/SM):
   phase 1: Qs @ 0 (9216B) | Ks @ 9216 (18432B)          [0, 27648)
   S held in accumulator fragments across the phase sync.
   phase 2: Vs @ 0 (18432B) | Sf @ 18432 (64x136f, 34816B) [0, 53248)
   Ph overlays Sf; O stage overlays Sf.                              */
#define AQ_OFF 0
#define AK_OFF 9216
#define AV_OFF 0
#define AS_OFF 18432
#define ATT_SMEM (AS_OFF + 64*136*4)   /* 53248 B */

__global__ __launch_bounds__(256, 4)
void attn_wmma(const __half* __restrict__ QKV, __half* __restrict__ O)
{
    extern __shared__ __align__(16) unsigned char smem[];
    __half* Qs = (__half*)(smem + AQ_OFF);   /* ld 72 */
    __half* Ks = (__half*)(smem + AK_OFF);   /* ld 72 */
    __half* Vs = (__half*)(smem + AV_OFF);   /* ld 72 (phase 2) */
    float*  Sf = (float*)(smem + AS_OFF);    /* ld 136 */
    __half* Ph = (__half*)(smem + AS_OFF);   /* ld 272 */
    const uint32_t squ = (uint32_t)__cvta_generic_to_shared(smem);

    const int tid = threadIdx.x, warp = tid >> 5, lane = tid & 31;
    const int b = blockIdx.z, h = blockIdx.y;
    const int t0 = blockIdx.x * 64;
    const int hc = h * HS;

    /* ---- phase 1 loads: Q + K ---- */
    #pragma unroll
    for (int i = 0; i < 2; i++) {
        int c = tid + i * 256;
        int r = c >> 3, col = (c & 7) * 8;
        cp_async16(squ + AQ_OFF + (uint32_t)(r * 144 + col * 2),
                   QKV + ((size_t)(b * TSEQ + t0 + r)) * QKVD + hc + col);
    }
    #pragma unroll
    for (int i = 0; i < 4; i++) {
        int c = tid + i * 256;
        int r = c >> 3, col = (c & 7) * 8;
        int s = t0 - 63 + r;
        int ok = (s >= 0 && s < TSEQ) ? 16 : 0;
        int sc = s < 0 ? 0 : (s >= TSEQ ? TSEQ - 1 : s);
        cp_async16z(squ + AK_OFF + (uint32_t)(r * 144 + col * 2),
                    QKV + ((size_t)(b * TSEQ + sc)) * QKVD + N_EMBD + hc + col, ok);
    }
    cp_commit();
    cp_wait0();
    __syncthreads();

    /* ---- S = Q @ Kext^T, held in fragments ---- */
    const int mb = warp & 3;
    const int nb0s = (warp >> 2) * 4;     /* S tile columns */
    wmma::fragment<wmma::accumulator, 16, 16, 16, float> sa[4];
    #pragma unroll
    for (int t = 0; t < 4; t++) wmma::fill_fragment(sa[t], 0.f);
    #pragma unroll
    for (int k = 0; k < 4; k++) {
        wmma::fragment<wmma::matrix_a, 16, 16, 16, __half, wmma::row_major> af;
        wmma::load_matrix_sync(af, Qs + mb * 16 * 72 + k * 16, 72);
        #pragma unroll
        for (int t = 0; t < 4; t++) {
            wmma::fragment<wmma::matrix_b, 16, 16, 16, __half, wmma::col_major> bf;
            wmma::load_matrix_sync(bf, Ks + (nb0s + t) * 16 * 72 + k * 16, 72);
            wmma::mma_sync(sa[t], af, bf, sa[t]);
        }
    }
    __syncthreads();   /* all warps done reading Q/K -> region reusable */

    /* ---- issue V loads into [0, 18432) ---- */
    #pragma unroll
    for (int i = 0; i < 4; i++) {
        int c = tid + i * 256;
        int r = c >> 3, col = (c & 7) * 8;
        int s = t0 - 63 + r;
        int ok = (s >= 0 && s < TSEQ) ? 16 : 0;
        int sc = s < 0 ? 0 : (s >= TSEQ ? TSEQ - 1 : s);
        cp_async16z(squ + AV_OFF + (uint32_t)(r * 144 + col * 2),
                    QKV + ((size_t)(b * TSEQ + sc)) * QKVD + 2*N_EMBD + hc + col, ok);
    }
    cp_commit();

    /* ---- store S fragments to Sf (over dead K region) ---- */
    #pragma unroll
    for (int t = 0; t < 4; t++)
        wmma::store_matrix_sync(Sf + mb * 16 * 136 + (nb0s + t) * 16, sa[t],
                                136, wmma::mem_row_major);
    __syncthreads();

    /* ---- masked softmax while V streams in; P (half) in place ---- */
    {
        for (int r = warp * 8; r < warp * 8 + 8; r++) {
            float vals[4];
            #pragma unroll
            for (int q = 0; q < 4; q++) {
                int j = lane + q * 32;
                float v = Sf[r * 136 + j] * 0.125f;
                bool valid = (j >= r) && (j <= r + 63) && (t0 - 63 + j >= 0);
                vals[q] = valid ? v : -1e30f;
            }
            float mx = fmaxf(fmaxf(vals[0], vals[1]), fmaxf(vals[2], vals[3]));
            #pragma unroll
            for (int o = 16; o; o >>= 1) mx = fmaxf(mx, __shfl_xor_sync(0xffffffffu, mx, o));
            float e[4], sum = 0.f;
            #pragma unroll
            for (int q = 0; q < 4; q++) { e[q] = __expf(vals[q] - mx); sum += e[q]; }
            #pragma unroll
            for (int o = 16; o; o >>= 1) sum += __shfl_xor_sync(0xffffffffu, sum, o);
            float inv = 1.f / sum;
            #pragma unroll
            for (int q = 0; q < 4; q++)
                Ph[r * 272 + lane + q * 32] = __float2half(e[q] * inv);
        }
    }
    cp_wait0();        /* V resident */
    __syncthreads();   /* Ph visible to all warps */

    /* ---- O = P @ V ---- */
    {
        const int nb0 = (warp >> 2) * 2;
        wmma::fragment<wmma::accumulator, 16, 16, 16, float> oa[2];
        #pragma unroll
        for (int t = 0; t < 2; t++) wmma::fill_fragment(oa[t], 0.f);
        #pragma unroll
        for (int k = 0; k < 8; k++) {
            wmma::fragment<wmma::matrix_a, 16, 16, 16, __half, wmma::row_major> af;
            wmma::load_matrix_sync(af, Ph + mb * 16 * 272 + k * 16, 272);
            #pragma unroll
            for (int t = 0; t < 2; t++) {
                wmma::fragment<wmma::matrix_b, 16, 16, 16, __half, wmma::row_major> bf;
                wmma::load_matrix_sync(bf, Vs + k * 16 * 72 + (nb0 + t) * 16, 72);
                wmma::mma_sync(oa[t], af, bf, oa[t]);
            }
        }
        __syncthreads();   /* everyone done reading Ph */
        float* OS = (float*)(smem + AS_OFF);   /* 64 x 72 fp32 stage */
        #pragma unroll
        for (int t = 0; t < 2; t++)
            wmma::store_matrix_sync(OS + (mb * 16) * 72 + (nb0 + t) * 16,
                                    oa[t], 72, wmma::mem_row_major);
        __syncthreads();
        #pragma unroll
        for (int i = 0; i < 4; i++) {
            int idx = tid + i * 256;           /* 1024 float4 slots */
            int r = idx >> 4, c4 = idx & 15;
            int col = c4 * 4;
            float4 v = *(float4*)&OS[r * 72 + col];
            *(uint2*)&O[((size_t)(b * TSEQ + t0 + r)) * N_EMBD + hc + col] =
                pack_h4(v.x, v.y, v.z, v.w);
        }
    }
}

/* --------------------------- tail zero ----------------------------- */
__global__ void tail_kernel(float* out, int start, int total)
{
    int i = start + blockIdx.x * blockDim.x + threadIdx.x;
    if (i < total) out[i] = 0.f;
}

/* --------------------------- launcher ------------------------------ */
extern "C" void kernel_launch(void* const* d_in, const int* in_sizes, int n_in,
                              void* d_out, int out_size)
{
    const float* x      = (const float*)d_in[0];
    const float* w_q    = (const float*)d_in[1];
    const float* w_k    = (const float*)d_in[2];
    const float* w_v    = (const float*)d_in[3];
    const float* w_proj = (const float*)d_in[4];
    const float* b_proj = (const float*)d_in[5];
    const float* w_ff1  = (const float*)d_in[6];
    const float* b_ff1  = (const float*)d_in[7];
    const float* w_ff2  = (const float*)d_in[8];
    const float* b_ff2  = (const float*)d_in[9];
    const float* g1     = (const float*)d_in[10];
    const float* g2     = (const float*)d_in[11];
    float* out = (float*)d_out;

    float *x1;
    __half *qkvh, *h1h, *atth, *h2h, *ffhh, *wqkv, *wtp, *wt1, *wt2;
    { void* p;
      cudaGetSymbolAddress(&p, g_x1);   x1   = (float*)p;
      cudaGetSymbolAddress(&p, g_qkvh); qkvh = (__half*)p;
      cudaGetSymbolAddress(&p, g_h1h);  h1h  = (__half*)p;
      cudaGetSymbolAddress(&p, g_atth); atth = (__half*)p;
      cudaGetSymbolAddress(&p, g_h2h);  h2h  = (__half*)p;
      cudaGetSymbolAddress(&p, g_ffhh); ffhh = (__half*)p;
      cudaGetSymbolAddress(&p, g_wqkv); wqkv = (__half*)p;
      cudaGetSymbolAddress(&p, g_wtp);  wtp  = (__half*)p;
      cudaGetSymbolAddress(&p, g_wt1);  wt1  = (__half*)p;
      cudaGetSymbolAddress(&p, g_wt2);  wt2  = (__half*)p;
    }

    cudaFuncSetAttribute(attn_wmma,
                         cudaFuncAttributeMaxDynamicSharedMemorySize, ATT_SMEM);
    cudaFuncSetAttribute(gemm_fp16<0,1>,
                         cudaFuncAttributeMaxDynamicSharedMemorySize, SMEM_G128);
    cudaFuncSetAttribute(gemm_fp16_s<1,0>,
                         cudaFuncAttributeMaxDynamicSharedMemorySize, SMEM_G64);
    cudaFuncSetAttribute(gemm_fp16_s<2,1>,
                         cudaFuncAttributeMaxDynamicSharedMemorySize, SMEM_G64);

    /* 0. transpose all weights to half [N,K] in ONE launch */
    {
        dim3 blk(32, 8);
        transpose_all_kernel<<<TRANS_BLOCKS, blk>>>(
            w_q, wqkv,
            w_k, wqkv + N_EMBD*N_EMBD,
            w_v, wqkv + 2*N_EMBD*N_EMBD,
            w_proj, wtp,
            w_ff1, wt1,
            w_ff2, wt2);
    }

    /* 1. rmsnorm(x)*g1 -> half (warp per row) */
    rmsnorm_h_kernel<<<MROWS/8, 256>>>(x, g1, h1h);

    /* 2. fused QKV GEMM -> half (BM=128) */
    dim3 gqkv(QKVD / 128, MROWS / 128);
    gemm_fp16<0,1><<<gqkv, 256, SMEM_G128>>>(h1h, wqkv, nullptr, nullptr,
                                             nullptr, qkvh, MROWS, QKVD, N_EMBD);

    /* 3. tensor-core sliding-window attention -> half */
    dim3 ga(TSEQ / 64, NHEAD, BATCH);
    attn_wmma<<<ga, 256, ATT_SMEM>>>(qkvh, atth);

    /* 4. proj: x1 = x + att @ w_proj + b_proj (BM=64) */
    dim3 gp(N_EMBD / 128, MROWS / 64);
    gemm_fp16_s<1,0><<<gp, 256, SMEM_G64>>>(atth, wtp, b_proj, x,
                                            x1, nullptr, MROWS, N_EMBD, N_EMBD);

    /* 5. rmsnorm(x1)*g2 -> half (warp per row) */
    rmsnorm_h_kernel<<<MROWS/8, 256>>>(x1, g2, h2h);

    /* 6. ff1: gelu(h2 @ w_ff1 + b_ff1) -> half (BM=64) */
    dim3 gff1(FFDIM / 128, MROWS / 64);
    gemm_fp16_s<2,1><<<gff1, 256, SMEM_G64>>>(h2h, wt1, b_ff1, nullptr,
                                              nullptr, ffhh, MROWS, FFDIM, N_EMBD);

    /* 7. ff2: out = x1 + ffh @ w_ff2 + b_ff2 (BM=64) */
    gemm_fp16_s<1,0><<<gp, 256, SMEM_G64>>>(ffhh, wt2, b_ff2, x1,
                                            out, nullptr, MROWS, N_EMBD, FFDIM);

    /* 8. aux / tail */
    const int TOT = MROWS * N_EMBD;
    if (out_size > TOT) {
        int rem = out_size - TOT;
        tail_kernel<<<(rem + 255) / 256, 256>>>(out, TOT, out_size);
    }
}

// round 14
// speedup vs baseline: 4.5290x; 1.0065x over previous
#include <cstdint>
#include <cuda_runtime.h>
#include <cuda_fp16.h>
#include <mma.h>

using namespace nvcuda;

#define N_EMBD 768
#define NHEAD  12
#define HS     64
#define TSEQ   1024
#define BATCH  8
#define MROWS  (BATCH*TSEQ)     /* 8192 */
#define FFDIM  (4*N_EMBD)       /* 3072 */
#define QKVD   (3*N_EMBD)       /* 2304 */
#define WINDOW 64

/* -------- scratch (no allocation allowed -> device globals) -------- */
__device__ float  g_x1  [MROWS*N_EMBD];
__device__ __half g_qkvh[MROWS*QKVD];
__device__ __half g_h1h [MROWS*N_EMBD];
__device__ __half g_atth[MROWS*N_EMBD];
__device__ __half g_h2h [MROWS*N_EMBD];
__device__ __half g_ffhh[MROWS*FFDIM];
/* converted half weights, ORIGINAL [K,N] layout */
__device__ __half g_wqkv[N_EMBD*QKVD];    /* fused q|k|v: [768][2304] */
__device__ __half g_wtp [N_EMBD*N_EMBD];
__device__ __half g_wt1 [N_EMBD*FFDIM];
__device__ __half g_wt2 [FFDIM*N_EMBD];

/* --------------------- cp.async helpers ---------------------------- */
__device__ __forceinline__ void cp_async16(uint32_t dst, const void* src)
{
    asm volatile("cp.async.cg.shared.global [%0], [%1], 16;\n" :: "r"(dst), "l"(src));
}
__device__ __forceinline__ void cp_async16z(uint32_t dst, const void* src, int src_sz)
{
    asm volatile("cp.async.cg.shared.global [%0], [%1], 16, %2;\n"
                 :: "r"(dst), "l"(src), "r"(src_sz));
}
__device__ __forceinline__ void cp_commit()
{
    asm volatile("cp.async.commit_group;\n");
}
__device__ __forceinline__ void cp_wait1()
{
    asm volatile("cp.async.wait_group 1;\n");
}
__device__ __forceinline__ void cp_wait0()
{
    asm volatile("cp.async.wait_group 0;\n");
}

__device__ __forceinline__ float gelu_tanh(float v)
{
    const float c = 0.7978845608028654f;
    return 0.5f * v * (1.f + tanhf(c * (v + 0.044715f * v * v * v)));
}

/* pack 4 floats -> 4 halfs (8B) */
__device__ __forceinline__ uint2 pack_h4(float a, float b, float c, float d)
{
    __half2 lo = __floats2half2_rn(a, b);
    __half2 hi = __floats2half2_rn(c, d);
    uint2 r;
    r.x = *(uint32_t*)&lo;
    r.y = *(uint32_t*)&hi;
    return r;
}

/* ------------- fused prep: convert weights + rmsnorm1 + tail ------- */
/* blocks [0,6912): weight f32->f16 convert (1024 elems/block)
     segs 0-2: w_q/w_k/w_v [768,768] -> g_wqkv strided (dstStride 2304)
     seg  3:   w_proj -> g_wtp
     seg  4:   w_ff1 [768,3072] -> g_wt1
     seg  5:   w_ff2 [3072,768] -> g_wt2
   blocks [6912, 6912+1024): rmsnorm rows (8 rows/block)
   block 6912+1024: zero tail of out                                   */
#define CONV_BLOCKS 6912
#define PREP_BLOCKS (CONV_BLOCKS + MROWS/8 + 1)

__global__ __launch_bounds__(256)
void prep_kernel(const float* wq, const float* wk, const float* wv,
                 const float* wp, const float* w1, const float* w2,
                 __half* whqkv, __half* whp, __half* wh1, __half* wh2,
                 const float* x, const float* g1, __half* h1h,
                 float* out, int tail_start, int out_size)
{
    const int bid = blockIdx.x;
    const int tid = threadIdx.x;

    if (bid < CONV_BLOCKS) {
        const float* src; __half* dst;
        int N, dstStride, dstOff, f4base;
        if (bid < 1728) {            /* 3 squares -> fused qkv buffer */
            int seg = bid / 576, r = bid % 576;
            src = (seg == 0) ? wq : (seg == 1) ? wk : wv;
            dst = whqkv; N = N_EMBD; dstStride = QKVD; dstOff = seg * N_EMBD;
            f4base = r * 256;
        } else if (bid < 2304) {
            src = wp; dst = whp; N = N_EMBD; dstStride = N_EMBD; dstOff = 0;
            f4base = (bid - 1728) * 256;
        } else if (bid < 4608) {
            src = w1; dst = wh1; N = FFDIM; dstStride = FFDIM; dstOff = 0;
            f4base = (bid - 2304) * 256;
        } else {
            src = w2; dst = wh2; N = N_EMBD; dstStride = N_EMBD; dstOff = 0;
            f4base = (bid - 4608) * 256;
        }
        int f4 = f4base + tid;
        int n4r = N >> 2;                    /* float4 per row */
        int k = f4 / n4r, n4 = f4 % n4r;
        float4 v = ((const float4*)src)[f4];
        *(uint2*)&dst[(size_t)k * dstStride + dstOff + n4 * 4] =
            pack_h4(v.x, v.y, v.z, v.w);
        return;
    }

    if (bid < CONV_BLOCKS + MROWS/8) {
        const int row  = (bid - CONV_BLOCKS) * 8 + (tid >> 5);
        const int lane = tid & 31;
        const float4* xr = (const float4*)(x + (size_t)row * N_EMBD);
        const float4* gr = (const float4*)g1;

        float4 v[6];
        float ss = 0.f;
        #pragma unroll
        for (int kk = 0; kk < 6; kk++) {
            v[kk] = xr[lane + 32 * kk];
            ss += v[kk].x*v[kk].x + v[kk].y*v[kk].y + v[kk].z*v[kk].z + v[kk].w*v[kk].w;
        }
        #pragma unroll
        for (int o = 16; o; o >>= 1) ss += __shfl_xor_sync(0xffffffffu, ss, o);
        const float r = rsqrtf(ss * (1.0f / N_EMBD) + 1e-6f);

        __half2* o2 = (__half2*)(h1h + (size_t)row * N_EMBD);
        #pragma unroll
        for (int kk = 0; kk < 6; kk++) {
            float4 gv = gr[lane + 32 * kk];
            int i = lane + 32 * kk;
            o2[i*2]   = __floats2half2_rn(v[kk].x * r * gv.x, v[kk].y * r * gv.y);
            o2[i*2+1] = __floats2half2_rn(v[kk].z * r * gv.z, v[kk].w * r * gv.w);
        }
        return;
    }

    /* tail zero (aux) */
    for (int i = tail_start + tid; i < out_size; i += 256)
        out[i] = 0.f;
}

/* ---------------- RMSNorm (standalone, for x1 -> h2) ---------------- */
__global__ __launch_bounds__(256)
void rmsnorm_h_kernel(const float* __restrict__ x,
                      const float* __restrict__ g,
                      __half* __restrict__ out)
{
    const int row  = blockIdx.x * 8 + (threadIdx.x >> 5);
    const int lane = threadIdx.x & 31;
    const float4* xr = (const float4*)(x + (size_t)row * N_EMBD);
    const float4* gr = (const float4*)g;

    float4 v[6];
    float ss = 0.f;
    #pragma unroll
    for (int k = 0; k < 6; k++) {
        v[k] = xr[lane + 32 * k];
        ss += v[k].x*v[k].x + v[k].y*v[k].y + v[k].z*v[k].z + v[k].w*v[k].w;
    }
    #pragma unroll
    for (int o = 16; o; o >>= 1) ss += __shfl_xor_sync(0xffffffffu, ss, o);
    const float r = rsqrtf(ss * (1.0f / N_EMBD) + 1e-6f);

    __half2* o2 = (__half2*)(out + (size_t)row * N_EMBD);
    #pragma unroll
    for (int k = 0; k < 6; k++) {
        float4 gv = gr[lane + 32 * k];
        int i = lane + 32 * k;
        o2[i*2]   = __floats2half2_rn(v[k].x * r * gv.x, v[k].y * r * gv.y);
        o2[i*2+1] = __floats2half2_rn(v[k].z * r * gv.z, v[k].w * r * gv.w);
    }
}

/* ------------------------- FP16 WMMA GEMM (BM=128) ----------------- */
/* C = A[M,K](row) @ W[K,N](row) ; A,W half, accum fp32                */
#define HSTR 72                        /* A-tile stride (64+8 halfs) */
#define BSTR 136                       /* B-tile stride (128+8 halfs) */
#define ATILE128_H (128 * HSTR)        /* 9216 halfs */
#define ATILE128_B (ATILE128_H * 2)    /* 18432 B */
#define BTILE_H (64 * BSTR)            /* 8704 halfs */
#define BTILE_B (BTILE_H * 2)          /* 17408 B */
#define SMEM_G128 (2*ATILE128_B + 2*BTILE_B)   /* 71680 B */
#define ESTR 136                       /* epilogue stage stride (floats) */

template<int MODE, int OUTH>
__global__ __launch_bounds__(256, 2)
void gemm_fp16(const __half* __restrict__ A, const __half* __restrict__ W,
               const float* __restrict__ bias, const float* __restrict__ resid,
               float* __restrict__ outf, __half* __restrict__ outh,
               int M, int N, int K)
{
    extern __shared__ __align__(16) unsigned char smem_raw[];
    __half* As = (__half*)smem_raw;                         /* [2][128][72] */
    __half* Bs = (__half*)(smem_raw + 2 * ATILE128_B);      /* [2][64][136] */
    const uint32_t asu = (uint32_t)__cvta_generic_to_shared(As);
    const uint32_t bsu = (uint32_t)__cvta_generic_to_shared(Bs);

    const int tid  = threadIdx.x;
    const int warp = tid >> 5;
    const int m0 = blockIdx.y * 128, n0 = blockIdx.x * 128;
    const int wm = (warp >> 2) * 64;
    const int wn = (warp & 3) * 32;

    wmma::fragment<wmma::accumulator, 16, 16, 16, float> acc[4][2];
    #pragma unroll
    for (int mi = 0; mi < 4; mi++)
        #pragma unroll
        for (int ni = 0; ni < 2; ni++)
            wmma::fill_fragment(acc[mi][ni], 0.f);

    const int nk = K >> 6;

    auto load_tile = [&](int ck, int s) {
        const __half* Ab = A + (size_t)m0 * K + ck * 64;
        const __half* Wb = W + (size_t)(ck * 64) * N + n0;
        #pragma unroll
        for (int i = 0; i < 4; i++) {
            int c = tid + i * 256;
            int r = c >> 3, col = (c & 7) * 8;
            cp_async16(asu + (uint32_t)(s * ATILE128_B + (r * HSTR + col) * 2),
                       Ab + (size_t)r * K + col);
        }
        #pragma unroll
        for (int i = 0; i < 4; i++) {
            int c = tid + i * 256;
            int r = c >> 4, col = (c & 15) * 8;
            cp_async16(bsu + (uint32_t)(s * BTILE_B + (r * BSTR + col) * 2),
                       Wb + (size_t)r * N + col);
        }
    };

    load_tile(0, 0); cp_commit();
    if (nk > 1) { load_tile(1, 1); cp_commit(); }

    for (int it = 0; it < nk; it++) {
        int s = it & 1;
        if (it + 1 < nk) cp_wait1(); else cp_wait0();
        __syncthreads();

        const __half* Acur = As + s * ATILE128_H;
        const __half* Bcur = Bs + s * BTILE_H;

        #pragma unroll
        for (int kk = 0; kk < 64; kk += 16) {
            wmma::fragment<wmma::matrix_a, 16, 16, 16, __half, wmma::row_major> af[4];
            wmma::fragment<wmma::matrix_b, 16, 16, 16, __half, wmma::row_major> bf[2];
            #pragma unroll
            for (int mi = 0; mi < 4; mi++)
                wmma::load_matrix_sync(af[mi], Acur + (wm + mi*16) * HSTR + kk, HSTR);
            #pragma unroll
            for (int ni = 0; ni < 2; ni++)
                wmma::load_matrix_sync(bf[ni], Bcur + kk * BSTR + wn + ni*16, BSTR);
            #pragma unroll
            for (int mi = 0; mi < 4; mi++)
                #pragma unroll
                for (int ni = 0; ni < 2; ni++)
                    wmma::mma_sync(acc[mi][ni], af[mi], bf[ni], acc[mi][ni]);
        }
        __syncthreads();
        if (it + 2 < nk) { load_tile(it + 2, s); cp_commit(); }
    }

    /* epilogue: stage whole 128x128 fp32 tile, then coalesced stores */
    float* stage = (float*)smem_raw;    /* 128 x ESTR = 69632 B */
    #pragma unroll
    for (int mi = 0; mi < 4; mi++)
        #pragma unroll
        for (int ni = 0; ni < 2; ni++)
            wmma::store_matrix_sync(stage + (wm + mi*16) * ESTR + wn + ni*16,
                                    acc[mi][ni], ESTR, wmma::mem_row_major);
    __syncthreads();

    #pragma unroll
    for (int i = 0; i < 16; i++) {
        int idx = tid + i * 256;
        int r = idx >> 5, c4 = idx & 31;
        int col = c4 * 4;
        float4 v = *(float4*)&stage[r * ESTR + col];
        int gr = m0 + r, gc = n0 + col;
        if (MODE >= 1) {
            float4 b = *(const float4*)&bias[gc];
            v.x += b.x; v.y += b.y; v.z += b.z; v.w += b.w;
        }
        if (MODE == 1) {
            float4 rr = *(const float4*)&resid[(size_t)gr * N + gc];
            v.x += rr.x; v.y += rr.y; v.z += rr.z; v.w += rr.w;
        }
        if (MODE == 2) {
            v.x = gelu_tanh(v.x); v.y = gelu_tanh(v.y);
            v.z = gelu_tanh(v.z); v.w = gelu_tanh(v.w);
        }
        if (OUTH)
            *(uint2*)&outh[(size_t)gr * N + gc] = pack_h4(v.x, v.y, v.z, v.w);
        else
            *(float4*)&outf[(size_t)gr * N + gc] = v;
    }
}

/* ------------------------- FP16 WMMA GEMM (BM=64) ------------------ */
#define ATILE64_H (64 * HSTR)          /* 4608 halfs */
#define ATILE64_B (ATILE64_H * 2)      /* 9216 B */
#define SMEM_G64  (2*ATILE64_B + 2*BTILE_B)  /* 53248 B */

template<int MODE, int OUTH>
__global__ __launch_bounds__(256, 3)
void gemm_fp16_s(const __half* __restrict__ A, const __half* __restrict__ W,
                 const float* __restrict__ bias, const float* __restrict__ resid,
                 float* __restrict__ outf, __half* __restrict__ outh,
                 int M, int N, int K)
{
    extern __shared__ __align__(16) unsigned char smem_raw[];
    __half* As = (__half*)smem_raw;                        /* [2][64][72]  */
    __half* Bs = (__half*)(smem_raw + 2 * ATILE64_B);      /* [2][64][136] */
    const uint32_t asu = (uint32_t)__cvta_generic_to_shared(As);
    const uint32_t bsu = (uint32_t)__cvta_generic_to_shared(Bs);

    const int tid  = threadIdx.x;
    const int warp = tid >> 5;
    const int m0 = blockIdx.y * 64, n0 = blockIdx.x * 128;
    const int wm = (warp >> 2) * 32;     /* 0 / 32  */
    const int wn = (warp & 3) * 32;      /* 0..96   */

    wmma::fragment<wmma::accumulator, 16, 16, 16, float> acc[2][2];
    #pragma unroll
    for (int mi = 0; mi < 2; mi++)
        #pragma unroll
        for (int ni = 0; ni < 2; ni++)
            wmma::fill_fragment(acc[mi][ni], 0.f);

    const int nk = K >> 6;

    auto load_tile = [&](int ck, int s) {
        const __half* Ab = A + (size_t)m0 * K + ck * 64;
        const __half* Wb = W + (size_t)(ck * 64) * N + n0;
        #pragma unroll
        for (int i = 0; i < 2; i++) {
            int c = tid + i * 256;
            int r = c >> 3, col = (c & 7) * 8;
            cp_async16(asu + (uint32_t)(s * ATILE64_B + (r * HSTR + col) * 2),
                       Ab + (size_t)r * K + col);
        }
        #pragma unroll
        for (int i = 0; i < 4; i++) {
            int c = tid + i * 256;
            int r = c >> 4, col = (c & 15) * 8;
            cp_async16(bsu + (uint32_t)(s * BTILE_B + (r * BSTR + col) * 2),
                       Wb + (size_t)r * N + col);
        }
    };

    load_tile(0, 0); cp_commit();
    if (nk > 1) { load_tile(1, 1); cp_commit(); }

    for (int it = 0; it < nk; it++) {
        int s = it & 1;
        if (it + 1 < nk) cp_wait1(); else cp_wait0();
        __syncthreads();

        const __half* Acur = As + s * ATILE64_H;
        const __half* Bcur = Bs + s * BTILE_H;

        #pragma unroll
        for (int kk = 0; kk < 64; kk += 16) {
            wmma::fragment<wmma::matrix_a, 16, 16, 16, __half, wmma::row_major> af[2];
            wmma::fragment<wmma::matrix_b, 16, 16, 16, __half, wmma::row_major> bf[2];
            #pragma unroll
            for (int mi = 0; mi < 2; mi++)
                wmma::load_matrix_sync(af[mi], Acur + (wm + mi*16) * HSTR + kk, HSTR);
            #pragma unroll
            for (int ni = 0; ni < 2; ni++)
                wmma::load_matrix_sync(bf[ni], Bcur + kk * BSTR + wn + ni*16, BSTR);
            #pragma unroll
            for (int mi = 0; mi < 2; mi++)
                #pragma unroll
                for (int ni = 0; ni < 2; ni++)
                    wmma::mma_sync(acc[mi][ni], af[mi], bf[ni], acc[mi][ni]);
        }
        __syncthreads();
        if (it + 2 < nk) { load_tile(it + 2, s); cp_commit(); }
    }

    /* epilogue: stage 64x128 fp32 tile, then coalesced stores */
    float* stage = (float*)smem_raw;    /* 64 x ESTR = 34816 B */
    #pragma unroll
    for (int mi = 0; mi < 2; mi++)
        #pragma unroll
        for (int ni = 0; ni < 2; ni++)
            wmma::store_matrix_sync(stage + (wm + mi*16) * ESTR + wn + ni*16,
                                    acc[mi][ni], ESTR, wmma::mem_row_major);
    __syncthreads();

    #pragma unroll
    for (int i = 0; i < 8; i++) {
        int idx = tid + i * 256;
        int r = idx >> 5, c4 = idx & 31;
        int col = c4 * 4;
        float4 v = *(float4*)&stage[r * ESTR + col];
        int gr = m0 + r, gc = n0 + col;
        if (MODE >= 1) {
            float4 b = *(const float4*)&bias[gc];
            v.x += b.x; v.y += b.y; v.z += b.z; v.w += b.w;
        }
        if (MODE == 1) {
            float4 rr = *(const float4*)&resid[(size_t)gr * N + gc];
            v.x += rr.x; v.y += rr.y; v.z += rr.z; v.w += rr.w;
        }
        if (MODE == 2) {
            v.x = gelu_tanh(v.x); v.y = gelu_tanh(v.y);
            v.z = gelu_tanh(v.z); v.w = gelu_tanh(v.w);
        }
        if (OUTH)
            *(uint2*)&outh[(size_t)gr * N + gc] = pack_h4(v.x, v.y, v.z, v.w);
        else
            *(float4*)&outf[(size_t)gr * N + gc] = v;
    }
}

/* ------------- tensor-core sliding-window (64) attention ----------- */
/* smem plan (53248 B, 4 CTA/SM):
   phase 1: Qs @ 0 (9216B) | Ks @ 9216 (18432B)
   S held in accumulator fragments across the phase sync.
   phase 2: Vs @ 0 (18432B) | Sf @ 18432 (64x136f, 34816B)
   Ph overlays Sf; O stage overlays Sf.                              */
#define AQ_OFF 0
#define AK_OFF 9216
#define AV_OFF 0
#define AS_OFF 18432
#define ATT_SMEM (AS_OFF + 64*136*4)   /* 53248 B */

__global__ __launch_bounds__(256, 4)
void attn_wmma(const __half* __restrict__ QKV, __half* __restrict__ O)
{
    extern __shared__ __align__(16) unsigned char smem[];
    __half* Qs = (__half*)(smem + AQ_OFF);   /* ld 72 */
    __half* Ks = (__half*)(smem + AK_OFF);   /* ld 72 */
    __half* Vs = (__half*)(smem + AV_OFF);   /* ld 72 (phase 2) */
    float*  Sf = (float*)(smem + AS_OFF);    /* ld 136 */
    __half* Ph = (__half*)(smem + AS_OFF);   /* ld 272 */
    const uint32_t squ = (uint32_t)__cvta_generic_to_shared(smem);

    const int tid = threadIdx.x, warp = tid >> 5, lane = tid & 31;
    const int b = blockIdx.z, h = blockIdx.y;
    const int t0 = blockIdx.x * 64;
    const int hc = h * HS;

    /* ---- phase 1 loads: Q + K ---- */
    #pragma unroll
    for (int i = 0; i < 2; i++) {
        int c = tid + i * 256;
        int r = c >> 3, col = (c & 7) * 8;
        cp_async16(squ + AQ_OFF + (uint32_t)(r * 144 + col * 2),
                   QKV + ((size_t)(b * TSEQ + t0 + r)) * QKVD + hc + col);
    }
    #pragma unroll
    for (int i = 0; i < 4; i++) {
        int c = tid + i * 256;
        int r = c >> 3, col = (c & 7) * 8;
        int s = t0 - 63 + r;
        int ok = (s >= 0 && s < TSEQ) ? 16 : 0;
        int sc = s < 0 ? 0 : (s >= TSEQ ? TSEQ - 1 : s);
        cp_async16z(squ + AK_OFF + (uint32_t)(r * 144 + col * 2),
                    QKV + ((size_t)(b * TSEQ + sc)) * QKVD + N_EMBD + hc + col, ok);
    }
    cp_commit();
    cp_wait0();
    __syncthreads();

    /* ---- S = Q @ Kext^T, held in fragments ---- */
    const int mb = warp & 3;
    const int nb0s = (warp >> 2) * 4;
    wmma::fragment<wmma::accumulator, 16, 16, 16, float> sa[4];
    #pragma unroll
    for (int t = 0; t < 4; t++) wmma::fill_fragment(sa[t], 0.f);
    #pragma unroll
    for (int k = 0; k < 4; k++) {
        wmma::fragment<wmma::matrix_a, 16, 16, 16, __half, wmma::row_major> af;
        wmma::load_matrix_sync(af, Qs + mb * 16 * 72 + k * 16, 72);
        #pragma unroll
        for (int t = 0; t < 4; t++) {
            wmma::fragment<wmma::matrix_b, 16, 16, 16, __half, wmma::col_major> bf;
            wmma::load_matrix_sync(bf, Ks + (nb0s + t) * 16 * 72 + k * 16, 72);
            wmma::mma_sync(sa[t], af, bf, sa[t]);
        }
    }
    __syncthreads();   /* Q/K dead -> region reusable */

    /* ---- issue V loads into [0, 18432) ---- */
    #pragma unroll
    for (int i = 0; i < 4; i++) {
        int c = tid + i * 256;
        int r = c >> 3, col = (c & 7) * 8;
        int s = t0 - 63 + r;
        int ok = (s >= 0 && s < TSEQ) ? 16 : 0;
        int sc = s < 0 ? 0 : (s >= TSEQ ? TSEQ - 1 : s);
        cp_async16z(squ + AV_OFF + (uint32_t)(r * 144 + col * 2),
                    QKV + ((size_t)(b * TSEQ + sc)) * QKVD + 2*N_EMBD + hc + col, ok);
    }
    cp_commit();

    /* ---- store S fragments to Sf ---- */
    #pragma unroll
    for (int t = 0; t < 4; t++)
        wmma::store_matrix_sync(Sf + mb * 16 * 136 + (nb0s + t) * 16, sa[t],
                                136, wmma::mem_row_major);
    __syncthreads();

    /* ---- masked softmax while V streams in; P (half) in place ---- */
    {
        for (int r = warp * 8; r < warp * 8 + 8; r++) {
            float vals[4];
            #pragma unroll
            for (int q = 0; q < 4; q++) {
                int j = lane + q * 32;
                float v = Sf[r * 136 + j] * 0.125f;
                bool valid = (j >= r) && (j <= r + 63) && (t0 - 63 + j >= 0);
                vals[q] = valid ? v : -1e30f;
            }
            float mx = fmaxf(fmaxf(vals[0], vals[1]), fmaxf(vals[2], vals[3]));
            #pragma unroll
            for (int o = 16; o; o >>= 1) mx = fmaxf(mx, __shfl_xor_sync(0xffffffffu, mx, o));
            float e[4], sum = 0.f;
            #pragma unroll
            for (int q = 0; q < 4; q++) { e[q] = __expf(vals[q] - mx); sum += e[q]; }
            #pragma unroll
            for (int o = 16; o; o >>= 1) sum += __shfl_xor_sync(0xffffffffu, sum, o);
            float inv = 1.f / sum;
            #pragma unroll
            for (int q = 0; q < 4; q++)
                Ph[r * 272 + lane + q * 32] = __float2half(e[q] * inv);
        }
    }
    cp_wait0();        /* V resident */
    __syncthreads();   /* Ph visible */

    /* ---- O = P @ V ---- */
    {
        const int nb0 = (warp >> 2) * 2;
        wmma::fragment<wmma::accumulator, 16, 16, 16, float> oa[2];
        #pragma unroll
        for (int t = 0; t < 2; t++) wmma::fill_fragment(oa[t], 0.f);
        #pragma unroll
        for (int k = 0; k < 8; k++) {
            wmma::fragment<wmma::matrix_a, 16, 16, 16, __half, wmma::row_major> af;
            wmma::load_matrix_sync(af, Ph + mb * 16 * 272 + k * 16, 272);
            #pragma unroll
            for (int t = 0; t < 2; t++) {
                wmma::fragment<wmma::matrix_b, 16, 16, 16, __half, wmma::row_major> bf;
                wmma::load_matrix_sync(bf, Vs + k * 16 * 72 + (nb0 + t) * 16, 72);
                wmma::mma_sync(oa[t], af, bf, oa[t]);
            }
        }
        __syncthreads();
        float* OS = (float*)(smem + AS_OFF);   /* 64 x 72 fp32 stage */
        #pragma unroll
        for (int t = 0; t < 2; t++)
            wmma::store_matrix_sync(OS + (mb * 16) * 72 + (nb0 + t) * 16,
                                    oa[t], 72, wmma::mem_row_major);
        __syncthreads();
        #pragma unroll
        for (int i = 0; i < 4; i++) {
            int idx = tid + i * 256;
            int r = idx >> 4, c4 = idx & 15;
            int col = c4 * 4;
            float4 v = *(float4*)&OS[r * 72 + col];
            *(uint2*)&O[((size_t)(b * TSEQ + t0 + r)) * N_EMBD + hc + col] =
                pack_h4(v.x, v.y, v.z, v.w);
        }
    }
}

/* --------------------------- launcher ------------------------------ */
extern "C" void kernel_launch(void* const* d_in, const int* in_sizes, int n_in,
                              void* d_out, int out_size)
{
    const float* x      = (const float*)d_in[0];
    const float* w_q    = (const float*)d_in[1];
    const float* w_k    = (const float*)d_in[2];
    const float* w_v    = (const float*)d_in[3];
    const float* w_proj = (const float*)d_in[4];
    const float* b_proj = (const float*)d_in[5];
    const float* w_ff1  = (const float*)d_in[6];
    const float* b_ff1  = (const float*)d_in[7];
    const float* w_ff2  = (const float*)d_in[8];
    const float* b_ff2  = (const float*)d_in[9];
    const float* g1     = (const float*)d_in[10];
    const float* g2     = (const float*)d_in[11];
    float* out = (float*)d_out;

    float *x1;
    __half *qkvh, *h1h, *atth, *h2h, *ffhh, *wqkv, *wtp, *wt1, *wt2;
    { void* p;
      cudaGetSymbolAddress(&p, g_x1);   x1   = (float*)p;
      cudaGetSymbolAddress(&p, g_qkvh); qkvh = (__half*)p;
      cudaGetSymbolAddress(&p, g_h1h);  h1h  = (__half*)p;
      cudaGetSymbolAddress(&p, g_atth); atth = (__half*)p;
      cudaGetSymbolAddress(&p, g_h2h);  h2h  = (__half*)p;
      cudaGetSymbolAddress(&p, g_ffhh); ffhh = (__half*)p;
      cudaGetSymbolAddress(&p, g_wqkv); wqkv = (__half*)p;
      cudaGetSymbolAddress(&p, g_wtp);  wtp  = (__half*)p;
      cudaGetSymbolAddress(&p, g_wt1);  wt1  = (__half*)p;
      cudaGetSymbolAddress(&p, g_wt2);  wt2  = (__half*)p;
    }

    cudaFuncSetAttribute(attn_wmma,
                         cudaFuncAttributeMaxDynamicSharedMemorySize, ATT_SMEM);
    cudaFuncSetAttribute(gemm_fp16<0,1>,
                         cudaFuncAttributeMaxDynamicSharedMemorySize, SMEM_G128);
    cudaFuncSetAttribute(gemm_fp16_s<1,0>,
                         cudaFuncAttributeMaxDynamicSharedMemorySize, SMEM_G64);
    cudaFuncSetAttribute(gemm_fp16_s<2,1>,
                         cudaFuncAttributeMaxDynamicSharedMemorySize, SMEM_G64);

    /* 0. fused prep: weight convert + rmsnorm1 + tail zero */
    const int TOT = MROWS * N_EMBD;
    prep_kernel<<<PREP_BLOCKS, 256>>>(w_q, w_k, w_v, w_proj, w_ff1, w_ff2,
                                      wqkv, wtp, wt1, wt2,
                                      x, g1, h1h,
                                      out, TOT, out_size);

    /* 1. fused QKV GEMM -> half (BM=128) */
    dim3 gqkv(QKVD / 128, MROWS / 128);
    gemm_fp16<0,1><<<gqkv, 256, SMEM_G128>>>(h1h, wqkv, nullptr, nullptr,
                                             nullptr, qkvh, MROWS, QKVD, N_EMBD);

    /* 2. tensor-core sliding-window attention -> half */
    dim3 ga(TSEQ / 64, NHEAD, BATCH);
    attn_wmma<<<ga, 256, ATT_SMEM>>>(qkvh, atth);

    /* 3. proj: x1 = x + att @ w_proj + b_proj (BM=64) */
    dim3 gp(N_EMBD / 128, MROWS / 64);
    gemm_fp16_s<1,0><<<gp, 256, SMEM_G64>>>(atth, wtp, b_proj, x,
                                            x1, nullptr, MROWS, N_EMBD, N_EMBD);

    /* 4. rmsnorm(x1)*g2 -> half */
    rmsnorm_h_kernel<<<MROWS/8, 256>>>(x1, g2, h2h);

    /* 5. ff1: gelu(h2 @ w_ff1 + b_ff1) -> half (BM=64) */
    dim3 gff1(FFDIM / 128, MROWS / 64);
    gemm_fp16_s<2,1><<<gff1, 256, SMEM_G64>>>(h2h, wt1, b_ff1, nullptr,
                                              nullptr, ffhh, MROWS, FFDIM, N_EMBD);

    /* 6. ff2: out = x1 + ffh @ w_ff2 + b_ff2 (BM=64) */
    gemm_fp16_s<1,0><<<gp, 256, SMEM_G64>>>(ffhh, wt2, b_ff2, x1,
                                            out, nullptr, MROWS, N_EMBD, FFDIM);
}